// round 3
// baseline (speedup 1.0000x reference)
#include <cuda_runtime.h>
#include <math.h>

// ---------------- problem constants ----------------
#define NB 8
#define NC 32
#define NH 256
#define NW 256
#define NM 16            // modes M1 = M2 = 16
#define NKX 32           // 16 top rows + 16 bottom rows
#define WSZ (32*32*16*16*2)   // per-layer w1/w2 float count

// ---------------- device scratch (no allocations allowed) ----------------
__device__ float  g_bufA[NB*NC*NH*NW];
__device__ float  g_bufB[NB*NC*NH*NW];
__device__ float  g_bufC[NB*NC*NH*NW];
__device__ float2 g_Y[NB*NC*NH*NM];      // [b][c][h][ky]
__device__ float2 g_Zb[NB*NC*NKX*NM];    // [b][i][kx][ky]
__device__ float2 g_Tb[NB*NC*NKX*NM];    // [b][o][kx][ky]
__device__ float2 g_G[NB*NC*NH*NM];      // [b][o][h][ky]
__device__ float2 g_cs[NM*NW];           // [ky][w]  (cos, sin) of 2*pi*ky*w/256
__device__ float2 g_E1[NH*NKX];          // [h][kx]  e^{-i phi}
__device__ float2 g_E2[NKX*NH];          // [kx][h]  e^{+i phi}

// ---------------- helpers ----------------
__device__ __forceinline__ float2 ffma2(float2 a, float2 b, float2 c) {
    float2 d;
    asm("fma.rn.f32x2 %0, %1, %2, %3;"
        : "=l"(reinterpret_cast<unsigned long long&>(d))
        : "l"(reinterpret_cast<unsigned long long&>(a)),
          "l"(reinterpret_cast<unsigned long long&>(b)),
          "l"(reinterpret_cast<unsigned long long&>(c)));
    return d;
}

__device__ __forceinline__ float gelu_f(float v) {
    return 0.5f * v * (1.0f + erff(v * 0.7071067811865476f));
}

// forward partial DFT of one (b,h) row held in smem (stride 257), all 32 channels,
// 16 ky modes.  256 threads: tid -> (c0 = tid>>4 and c0+16, ky = tid&15).
__device__ __forceinline__ void fwd_dft_row(const float* orow, const float2* cs,
                                            float2* Y, int b, int h, int tid) {
    int ky = tid & 15;
    int c0 = tid >> 4;
    float2 yr = make_float2(0.f, 0.f);
    float2 yi = make_float2(0.f, 0.f);
#pragma unroll 8
    for (int w = 0; w < NW; w++) {
        float2 e = cs[ky*257 + w];
        float2 xv = make_float2(orow[c0*257 + w], orow[(c0+16)*257 + w]);
        yr = ffma2(xv, make_float2(e.x, e.x), yr);
        yi = ffma2(xv, make_float2(-e.y, -e.y), yi);
    }
    Y[((b*NC + c0     )*NH + h)*NM + ky] = make_float2(yr.x, yi.x);
    Y[((b*NC + c0 + 16)*NH + h)*NM + ky] = make_float2(yr.y, yi.y);
}

// ---------------- table init (runs every launch, deterministic) ----------------
__global__ void init_tables() {
    int tid = threadIdx.x;
    const double TWO_PI = 6.283185307179586476925286766559;
    for (int k = tid; k < NM*NW; k += 256) {
        int ky = k >> 8, w = k & 255;
        double th = TWO_PI * (double)(ky * w) / 256.0;
        g_cs[k] = make_float2((float)cos(th), (float)sin(th));
    }
    for (int k = tid; k < NH*NKX; k += 256) {
        int h = k >> 5, kx = k & 31;
        int fr = (kx < 16) ? kx : (kx - 32);   // freq 0..15, then -16..-1 (rows 240..255)
        double ph = TWO_PI * (double)(fr * h) / 256.0;
        float cp = (float)cos(ph), sp = (float)sin(ph);
        g_E1[k] = make_float2(cp, -sp);        // e^{-i phi}
        g_E2[kx*NH + h] = make_float2(cp, sp); // e^{+i phi}
    }
}

// ---------------- lift: grid concat + fc0 + transpose + forward W-DFT ----------------
// block = (b,h), 256 threads (w).
__global__ void __launch_bounds__(256) lift_kernel(
        const float* __restrict__ x, const float* __restrict__ w0,
        const float* __restrict__ b0, float* __restrict__ out, float2* __restrict__ Y) {
    extern __shared__ unsigned char sm[];
    float2* cs   = (float2*)sm;                 // 16*257
    float*  w0s  = (float*)(cs + 16*257);       // 384
    float*  b0s  = w0s + 384;                   // 32
    float*  orow = b0s + 32;                    // 32*257

    int b = blockIdx.x >> 8, h = blockIdx.x & 255, tid = threadIdx.x;

    for (int k = tid; k < NM*NW; k += 256) { int ky=k>>8, w=k&255; cs[ky*257+w] = g_cs[k]; }
    for (int k = tid; k < 384; k += 256) w0s[k] = w0[k];
    if (tid < 32) b0s[tid] = b0[tid];
    __syncthreads();

    int w = tid;
    const float* xp = x + (((b*NH) + h)*NW + w) * 10;
    float xv[10];
#pragma unroll
    for (int t = 0; t < 10; t++) xv[t] = xp[t];
    float gx = (float)h * (1.0f/255.0f);
    float gy = (float)w * (1.0f/255.0f);

    for (int c = 0; c < NC; c++) {
        float acc = b0s[c];
#pragma unroll
        for (int t = 0; t < 10; t++) acc = fmaf(xv[t], w0s[t*32 + c], acc);
        acc = fmaf(gx, w0s[10*32 + c], acc);
        acc = fmaf(gy, w0s[11*32 + c], acc);
        out[((b*NC + c)*NH + h)*NW + w] = acc;
        orow[c*257 + w] = acc;
    }
    __syncthreads();
    fwd_dft_row(orow, cs, Y, b, h, tid);
}

// ---------------- K2a: H-DFT  Y -> Z ----------------
// block = (b,i): 256 blocks.
__global__ void __launch_bounds__(256) k2a_kernel(
        const float2* __restrict__ Y, float2* __restrict__ Z) {
    extern __shared__ unsigned char sm[];
    float2* Ys  = (float2*)sm;          // 256*16
    float2* E1s = Ys + NH*NM;           // 256*32

    int b = blockIdx.x >> 5, i = blockIdx.x & 31, tid = threadIdx.x;
    for (int k = tid; k < NH*NM;  k += 256) Ys[k]  = Y[(b*NC + i)*NH*NM + k];
    for (int k = tid; k < NH*NKX; k += 256) E1s[k] = g_E1[k];
    __syncthreads();

    int kx = tid & 31, ky0 = tid >> 5;            // ky0 in 0..7, also do ky0+8
    float2 z0 = make_float2(0.f,0.f), z1 = make_float2(0.f,0.f);
#pragma unroll 4
    for (int h = 0; h < NH; h++) {
        float2 e  = E1s[h*NKX + kx];
        float2 en = make_float2(-e.y, e.x);
        float2 y0 = Ys[h*NM + ky0];
        float2 y1 = Ys[h*NM + ky0 + 8];
        z0 = ffma2(make_float2(y0.x, y0.x), e,  z0);
        z0 = ffma2(make_float2(y0.y, y0.y), en, z0);
        z1 = ffma2(make_float2(y1.x, y1.x), e,  z1);
        z1 = ffma2(make_float2(y1.y, y1.y), en, z1);
    }
    Z[((b*NC + i)*NKX + kx)*NM + ky0    ] = z0;
    Z[((b*NC + i)*NKX + kx)*NM + ky0 + 8] = z1;
}

// ---------------- K2b: complex channel mixing  Z,w -> T ----------------
// block = (b,kx): 256 blocks.
__global__ void __launch_bounds__(256) k2b_kernel(
        const float2* __restrict__ Z, const float* __restrict__ w1,
        const float* __restrict__ w2, float2* __restrict__ T) {
    __shared__ float2 Zs[NC*NM];
    int b = blockIdx.x >> 5, kx = blockIdx.x & 31, tid = threadIdx.x;
    for (int k = tid; k < NC*NM; k += 256) {
        int i = k >> 4, ky = k & 15;
        Zs[k] = Z[((b*NC + i)*NKX + kx)*NM + ky];
    }
    __syncthreads();

    int kxm = kx & 15;
    const float2* wb = (const float2*)((kx < 16) ? w1 : w2);
    int ky = tid & 15, o0 = tid >> 4, o1 = o0 + 16;
    float2 t0 = make_float2(0.f,0.f), t1 = make_float2(0.f,0.f);
#pragma unroll 4
    for (int i = 0; i < NC; i++) {
        float2 z = Zs[i*NM + ky];
        float2 zr = make_float2(z.x, z.x), zi = make_float2(z.y, z.y);
        float2 wv0 = wb[((i*32 + o0)*16 + kxm)*16 + ky];
        float2 wv1 = wb[((i*32 + o1)*16 + kxm)*16 + ky];
        t0 = ffma2(zr, wv0, t0);
        t0 = ffma2(zi, make_float2(-wv0.y, wv0.x), t0);
        t1 = ffma2(zr, wv1, t1);
        t1 = ffma2(zi, make_float2(-wv1.y, wv1.x), t1);
    }
    T[((b*NC + o0)*NKX + kx)*NM + ky] = t0;
    T[((b*NC + o1)*NKX + kx)*NM + ky] = t1;
}

// ---------------- K2c: inverse H-DFT  T -> G (scaled) ----------------
// block = (b,o): 256 blocks, thread = h.
__global__ void __launch_bounds__(256) k2c_kernel(
        const float2* __restrict__ T, float2* __restrict__ G) {
    extern __shared__ unsigned char sm[];
    float2* Ts  = (float2*)sm;          // 32*16
    float2* E2s = Ts + NKX*NM;          // 32*256

    int b = blockIdx.x >> 5, o = blockIdx.x & 31, tid = threadIdx.x;
    for (int k = tid; k < NKX*NM; k += 256) Ts[k]  = T[(b*NC + o)*NKX*NM + k];
    for (int k = tid; k < NKX*NH; k += 256) E2s[k] = g_E2[k];
    __syncthreads();

    int h = tid;
    float2 acc[NM];
#pragma unroll
    for (int ky = 0; ky < NM; ky++) acc[ky] = make_float2(0.f, 0.f);

    for (int kx = 0; kx < NKX; kx++) {
        float2 e  = E2s[kx*NH + h];
        float2 en = make_float2(-e.y, e.x);
#pragma unroll
        for (int ky = 0; ky < NM; ky++) {
            float2 t = Ts[kx*NM + ky];
            acc[ky] = ffma2(make_float2(t.x, t.x), e,  acc[ky]);
            acc[ky] = ffma2(make_float2(t.y, t.y), en, acc[ky]);
        }
    }
#pragma unroll
    for (int ky = 0; ky < NM; ky++) {
        float sc = ((ky == 0) ? 1.0f : 2.0f) * (1.0f / 65536.0f);
        G[((b*NC + o)*NH + h)*NM + ky] = make_float2(acc[ky].x * sc, acc[ky].y * sc);
    }
}

// ---------------- fused layer row kernel ----------------
// spectral synthesis + 1x1 conv + bias + GELU (+skip) + optional forward W-DFT.
// block = (b,h), 256 threads (w).
template<bool HAS_SKIP, bool WRITE_Y>
__global__ void __launch_bounds__(256) layer_kernel(
        const float* __restrict__ xin, const float2* __restrict__ G,
        const float* __restrict__ cw, const float* __restrict__ cb,
        const float* __restrict__ skip, float* __restrict__ xout,
        float2* __restrict__ Ynext) {
    extern __shared__ unsigned char sm[];
    float2* cs   = (float2*)sm;              // 16*257
    float2* gr2  = cs + 16*257;              // 256  (o-pairs x ky, real)
    float2* gi2  = gr2 + 256;                // 256  (imag)
    float2* cws2 = gi2 + 256;                // 16*32 (o-pairs x c)
    float2* cb2  = cws2 + 512;               // 16
    float*  xrow = (float*)(cb2 + 16);       // 32*257
    float*  orow = xrow + 32*257;            // 32*257

    int b = blockIdx.x >> 8, h = blockIdx.x & 255, tid = threadIdx.x;

    for (int k = tid; k < NM*NW; k += 256) { int ky=k>>8, w=k&255; cs[ky*257+w] = g_cs[k]; }
    for (int c = 0; c < NC; c++) xrow[c*257 + tid] = xin[((b*NC + c)*NH + h)*NW + tid];
    for (int k = tid; k < 512; k += 256) {
        int p = k >> 5, c = k & 31;
        cws2[p*32 + c] = make_float2(cw[(2*p)*32 + c], cw[(2*p+1)*32 + c]);
    }
    if (tid < 16) cb2[tid] = make_float2(cb[2*tid], cb[2*tid+1]);
    {
        int p = tid >> 4, ky = tid & 15;
        float2 ga = G[((b*NC + 2*p    )*NH + h)*NM + ky];
        float2 gb = G[((b*NC + 2*p + 1)*NH + h)*NM + ky];
        gr2[p*16 + ky] = make_float2(ga.x, gb.x);
        gi2[p*16 + ky] = make_float2(ga.y, gb.y);
    }
    __syncthreads();

    int w = tid;
    for (int p = 0; p < 16; p++) {
        float2 acc = cb2[p];
#pragma unroll
        for (int c = 0; c < NC; c++) {
            float xv = xrow[c*257 + w];
            acc = ffma2(make_float2(xv, xv), cws2[p*32 + c], acc);
        }
#pragma unroll
        for (int ky = 0; ky < NM; ky++) {
            float2 e = cs[ky*257 + w];
            acc = ffma2(gr2[p*16 + ky], make_float2(e.x, e.x), acc);
            acc = ffma2(gi2[p*16 + ky], make_float2(-e.y, -e.y), acc);
        }
        float v0 = gelu_f(acc.x);
        float v1 = gelu_f(acc.y);
        int i0 = ((b*NC + 2*p)*NH + h)*NW + w;
        int i1 = i0 + NH*NW;
        if (HAS_SKIP) { v0 += skip[i0]; v1 += skip[i1]; }
        xout[i0] = v0; xout[i1] = v1;
        if (WRITE_Y) {
            orow[(2*p    )*257 + w] = v0;
            orow[(2*p + 1)*257 + w] = v1;
        }
    }
    if (WRITE_Y) {
        __syncthreads();
        fwd_dft_row(orow, cs, Ynext, b, h, tid);
    }
}

// ---------------- head: fc1 + GELU + fc2 ----------------
// block = (b,h), 256 threads (w).
__global__ void __launch_bounds__(256) head_kernel(
        const float* __restrict__ xin, const float* __restrict__ w1,
        const float* __restrict__ b1, const float* __restrict__ w2,
        const float* __restrict__ b2, float* __restrict__ out) {
    extern __shared__ unsigned char sm[];
    float* xrow = (float*)sm;        // 32*257
    float* w1s  = xrow + 32*257;     // 32*128
    float* b1s  = w1s + 4096;        // 128
    float* w2s  = b1s + 128;         // 640
    float* b2s  = w2s + 640;         // 8

    int b = blockIdx.x >> 8, h = blockIdx.x & 255, tid = threadIdx.x;
    for (int c = 0; c < NC; c++) xrow[c*257 + tid] = xin[((b*NC + c)*NH + h)*NW + tid];
    for (int k = tid; k < 4096; k += 256) w1s[k] = w1[k];
    if (tid < 128) b1s[tid] = b1[tid];
    for (int k = tid; k < 640; k += 256) w2s[k] = w2[k];
    if (tid < 5) b2s[tid] = b2[tid];
    __syncthreads();

    int w = tid;
    float o0 = b2s[0], o1 = b2s[1], o2 = b2s[2], o3 = b2s[3], o4 = b2s[4];
    const float2* w1p = (const float2*)w1s;   // [c][64] pairs of hidden units
    const float2* b1p = (const float2*)b1s;
    for (int j2 = 0; j2 < 64; j2++) {
        float2 acc = b1p[j2];
#pragma unroll
        for (int c = 0; c < NC; c++) {
            float xv = xrow[c*257 + w];
            acc = ffma2(make_float2(xv, xv), w1p[c*64 + j2], acc);
        }
        float h0 = gelu_f(acc.x);
        float h1 = gelu_f(acc.y);
        int j = 2*j2;
        o0 = fmaf(h0, w2s[j*5 + 0], o0); o0 = fmaf(h1, w2s[(j+1)*5 + 0], o0);
        o1 = fmaf(h0, w2s[j*5 + 1], o1); o1 = fmaf(h1, w2s[(j+1)*5 + 1], o1);
        o2 = fmaf(h0, w2s[j*5 + 2], o2); o2 = fmaf(h1, w2s[(j+1)*5 + 2], o2);
        o3 = fmaf(h0, w2s[j*5 + 3], o3); o3 = fmaf(h1, w2s[(j+1)*5 + 3], o3);
        o4 = fmaf(h0, w2s[j*5 + 4], o4); o4 = fmaf(h1, w2s[(j+1)*5 + 4], o4);
    }
    float* op = out + (((b*NH) + h)*NW + w) * 5;
    op[0] = o0; op[1] = o1; op[2] = o2; op[3] = o3; op[4] = o4;
}

// ---------------- host launcher ----------------
static const int LIFT_SM = (16*257)*8 + (384 + 32 + 32*257)*4;                 // 67456
static const int ROW_SM  = (16*257 + 256 + 256 + 512 + 16)*8 + (2*32*257)*4;   // 107008
static const int HEAD_SM = (32*257 + 4096 + 128 + 640 + 8)*4;                  // 52384
static const int K2A_SM  = (NH*NM + NH*NKX)*8;                                 // 98304
static const int K2C_SM  = (NKX*NM + NKX*NH)*8;                                // 69632

extern "C" void kernel_launch(void* const* d_in, const int* in_sizes, int n_in,
                              void* d_out, int out_size) {
    const float* x     = (const float*)d_in[0];
    const float* fc0w  = (const float*)d_in[1];
    const float* fc0b  = (const float*)d_in[2];
    const float* w1    = (const float*)d_in[3];
    const float* w2    = (const float*)d_in[4];
    const float* convw = (const float*)d_in[5];
    const float* convb = (const float*)d_in[6];
    const float* fc1w  = (const float*)d_in[7];
    const float* fc1b  = (const float*)d_in[8];
    const float* fc2w  = (const float*)d_in[9];
    const float* fc2b  = (const float*)d_in[10];
    float* out = (float*)d_out;

    float  *bufA, *bufB, *bufC;
    float2 *Y, *Z, *T, *G;
    cudaGetSymbolAddress((void**)&bufA, g_bufA);
    cudaGetSymbolAddress((void**)&bufB, g_bufB);
    cudaGetSymbolAddress((void**)&bufC, g_bufC);
    cudaGetSymbolAddress((void**)&Y, g_Y);
    cudaGetSymbolAddress((void**)&Z, g_Zb);
    cudaGetSymbolAddress((void**)&T, g_Tb);
    cudaGetSymbolAddress((void**)&G, g_G);

    cudaFuncSetAttribute(lift_kernel, cudaFuncAttributeMaxDynamicSharedMemorySize, LIFT_SM);
    cudaFuncSetAttribute(k2a_kernel,  cudaFuncAttributeMaxDynamicSharedMemorySize, K2A_SM);
    cudaFuncSetAttribute(k2c_kernel,  cudaFuncAttributeMaxDynamicSharedMemorySize, K2C_SM);
    cudaFuncSetAttribute(head_kernel, cudaFuncAttributeMaxDynamicSharedMemorySize, HEAD_SM);
    cudaFuncSetAttribute(layer_kernel<false, false>, cudaFuncAttributeMaxDynamicSharedMemorySize, ROW_SM);
    cudaFuncSetAttribute(layer_kernel<false, true >, cudaFuncAttributeMaxDynamicSharedMemorySize, ROW_SM);
    cudaFuncSetAttribute(layer_kernel<true,  true >, cudaFuncAttributeMaxDynamicSharedMemorySize, ROW_SM);
    cudaFuncSetAttribute(layer_kernel<true,  false>, cudaFuncAttributeMaxDynamicSharedMemorySize, ROW_SM);

    init_tables<<<1, 256>>>();
    lift_kernel<<<NB*NH, 256, LIFT_SM>>>(x, fc0w, fc0b, bufA, Y);   // A = lift, Y = Y_lift

    // Reference DAG:
    //   h0 = L0(lift);  t1 = L1(lift);  t2 = L2(t1) + h0;
    //   h1 = L3(t2);    t4 = L4(t2);    out = L5(t4) + h1;
    //
    // Y usage: L0,L1 share Y_lift; L2 uses Y_t1; L3,L4 share Y_t2; L5 uses Y_t4.
    // Buffers: A=lift/t2/final, B=h0/h1, C=t1/t4.
    struct Step { int in, out, skip; bool hasSkip, writeY; };
    // in/out/skip: 0=A 1=B 2=C, skip=-1 none
    const Step steps[6] = {
        {0, 1, -1, false, false},  // L0: A -> B (h0)
        {0, 2, -1, false, true },  // L1: A -> C (t1), write Y_t1
        {2, 0,  1, true,  true },  // L2: C -> A (t2) + skip B, write Y_t2
        {0, 1, -1, false, false},  // L3: A -> B (h1)
        {0, 2, -1, false, true },  // L4: A -> C (t4), write Y_t4
        {2, 0,  1, true,  false},  // L5: C -> A (final) + skip B
    };
    float* bufs[3] = { bufA, bufB, bufC };

    for (int l = 0; l < 6; l++) {
        const float* w1l = w1 + (size_t)l * WSZ;
        const float* w2l = w2 + (size_t)l * WSZ;
        const float* cwl = convw + l * 32 * 32;
        const float* cbl = convb + l * 32;

        k2a_kernel<<<NB*NC, 256, K2A_SM>>>(Y, Z);
        k2b_kernel<<<NB*NKX, 256>>>(Z, w1l, w2l, T);
        k2c_kernel<<<NB*NC, 256, K2C_SM>>>(T, G);

        const Step& s = steps[l];
        const float* in  = bufs[s.in];
        float*       outb = bufs[s.out];
        const float* sk  = (s.skip >= 0) ? bufs[s.skip] : nullptr;
        if (s.hasSkip) {
            if (s.writeY)
                layer_kernel<true,  true ><<<NB*NH, 256, ROW_SM>>>(in, G, cwl, cbl, sk, outb, Y);
            else
                layer_kernel<true,  false><<<NB*NH, 256, ROW_SM>>>(in, G, cwl, cbl, sk, outb, Y);
        } else {
            if (s.writeY)
                layer_kernel<false, true ><<<NB*NH, 256, ROW_SM>>>(in, G, cwl, cbl, nullptr, outb, Y);
            else
                layer_kernel<false, false><<<NB*NH, 256, ROW_SM>>>(in, G, cwl, cbl, nullptr, outb, Y);
        }
    }

    head_kernel<<<NB*NH, 256, HEAD_SM>>>(bufA, fc1w, fc1b, fc2w, fc2b, out);
}

// round 5
// speedup vs baseline: 1.2568x; 1.2568x over previous
#include <cuda_runtime.h>
#include <math.h>

// ---------------- problem constants ----------------
#define NB 8
#define NC 32
#define NH 256
#define NW 256
#define NM 16            // modes M1 = M2 = 16
#define NKX 32           // 16 top rows + 16 bottom rows
#define WSZ (32*32*16*16*2)   // per-layer w1/w2 float count

// ---------------- device scratch ----------------
__device__ float  g_bufA[NB*NC*NH*NW];
__device__ float  g_bufB[NB*NC*NH*NW];
__device__ float  g_bufC[NB*NC*NH*NW];
__device__ float2 g_Y[NB*NC*NH*NM];      // [b][c][h][ky]
__device__ float2 g_Zb[NB*NC*NKX*NM];    // [b][i][kx][ky]
__device__ float2 g_G[NB*NC*NH*NM];      // [b][o][h][ky]
__device__ float2 g_cs[NM*NW];           // [ky][w]  (cos,sin) of 2*pi*ky*w/256
__device__ float2 g_E1[NH*NKX];          // [h][kx]  e^{-i phi}
__device__ float2 g_E2[NKX*NH];          // [kx][h]  e^{+i phi}

// ---------------- helpers ----------------
__device__ __forceinline__ float2 ffma2(float2 a, float2 b, float2 c) {
    float2 d;
    asm("fma.rn.f32x2 %0, %1, %2, %3;"
        : "=l"(reinterpret_cast<unsigned long long&>(d))
        : "l"(reinterpret_cast<unsigned long long&>(a)),
          "l"(reinterpret_cast<unsigned long long&>(b)),
          "l"(reinterpret_cast<unsigned long long&>(c)));
    return d;
}
__device__ __forceinline__ float gelu_f(float v) {
    return 0.5f * v * (1.0f + erff(v * 0.7071067811865476f));
}

// ---------------- table init ----------------
__global__ void init_tables() {
    int gid = blockIdx.x * blockDim.x + threadIdx.x;
    int nth = gridDim.x * blockDim.x;
    for (int k = gid; k < NM*NW; k += nth) {
        int ky = k >> 8, w = k & 255;
        int m = (ky * w) & 255;                 // angle = 2*pi*m/256 = pi*m/128
        float a = (float)m * (1.0f/128.0f);
        g_cs[k] = make_float2(cospif(a), sinpif(a));
    }
    for (int k = gid; k < NH*NKX; k += nth) {
        int h = k >> 5, kx = k & 31;
        int fr = (kx < 16) ? kx : (kx - 32);
        int m = (fr * h) & 255;                 // correct mod for negatives (2's comp)
        float a = (float)m * (1.0f/128.0f);
        float cp = cospif(a), sp = sinpif(a);
        g_E1[k] = make_float2(cp, -sp);         // e^{-i phi}
        g_E2[kx*NH + h] = make_float2(cp, sp);  // e^{+i phi}
    }
}

// ---------------- shared forward partial W-DFT over a packed row ----------------
// orow2: float2[16][258], pair p holds channels (2p, 2p+1). cs2: float2[16][258].
__device__ __forceinline__ void fwd_dft_row2(const float2* orow2, const float2* cs2,
                                             float2* __restrict__ Y, int b, int h, int tid) {
    int q  = tid >> 4;       // channel-pair 0..15
    int ky = tid & 15;
    float2 yr = make_float2(0.f, 0.f);
    float2 yi = make_float2(0.f, 0.f);
    const float4* op = (const float4*)(orow2 + q*258);
    const float4* ep = (const float4*)(cs2  + ky*258);
#pragma unroll 8
    for (int w2 = 0; w2 < NW/2; w2++) {
        float4 o4 = op[w2];
        float4 e4 = ep[w2];
        yr = ffma2(make_float2(o4.x, o4.y), make_float2(e4.x,  e4.x), yr);
        yi = ffma2(make_float2(o4.x, o4.y), make_float2(-e4.y, -e4.y), yi);
        yr = ffma2(make_float2(o4.z, o4.w), make_float2(e4.z,  e4.z), yr);
        yi = ffma2(make_float2(o4.z, o4.w), make_float2(-e4.w, -e4.w), yi);
    }
    Y[((b*NC + 2*q    )*NH + h)*NM + ky] = make_float2(yr.x, yi.x);
    Y[((b*NC + 2*q + 1)*NH + h)*NM + ky] = make_float2(yr.y, yi.y);
}

// ---------------- lift ----------------
// smem: cs2[0..33024) | orow2[33024..66048) | w0s | b0s
static const int LIFT_SM = 33024 + 33024 + 1536 + 128;
__global__ void __launch_bounds__(256) lift_kernel(
        const float* __restrict__ x, const float* __restrict__ w0,
        const float* __restrict__ b0, float* __restrict__ out, float2* __restrict__ Y) {
    extern __shared__ unsigned char sm[];
    float2* cs2   = (float2*)sm;
    float2* orow2 = (float2*)(sm + 33024);
    float*  w0s   = (float*)(sm + 66048);
    float*  b0s   = (float*)(sm + 66048 + 1536);
    float*  orowf = (float*)orow2;

    int b = blockIdx.x >> 8, h = blockIdx.x & 255, tid = threadIdx.x;

    for (int k = tid; k < NM*NW; k += 256) { int ky=k>>8, w=k&255; cs2[ky*258+w] = g_cs[k]; }
    for (int k = tid; k < 384; k += 256) w0s[k] = w0[k];
    if (tid < 32) b0s[tid] = b0[tid];
    __syncthreads();

    int w = tid;
    const float* xp = x + (((b*NH) + h)*NW + w) * 10;
    float xv[10];
#pragma unroll
    for (int t = 0; t < 10; t++) xv[t] = xp[t];
    float gx = (float)h * (1.0f/255.0f);
    float gy = (float)w * (1.0f/255.0f);

    for (int c = 0; c < NC; c++) {
        float acc = b0s[c];
#pragma unroll
        for (int t = 0; t < 10; t++) acc = fmaf(xv[t], w0s[t*32 + c], acc);
        acc = fmaf(gx, w0s[10*32 + c], acc);
        acc = fmaf(gy, w0s[11*32 + c], acc);
        out[((b*NC + c)*NH + h)*NW + w] = acc;
        orowf[(c >> 1)*516 + 2*w + (c & 1)] = acc;
    }
    __syncthreads();
    fwd_dft_row2(orow2, cs2, Y, b, h, tid);
}

// ---------------- k2a: H-DFT  Y -> Z ----------------
static const int K2A_SM = 32768 + 65536;   // Ys, E1s
__global__ void __launch_bounds__(512, 2) k2a_kernel(
        const float2* __restrict__ Y, float2* __restrict__ Z) {
    extern __shared__ unsigned char sm[];
    float2* Ys  = (float2*)sm;             // [h][ky] 256*16
    float2* E1s = (float2*)(sm + 32768);   // [h][kx] 256*32

    int b = blockIdx.x >> 5, i = blockIdx.x & 31, tid = threadIdx.x;
    {
        const float4* src = (const float4*)(Y + (b*NC + i)*NH*NM);
        float4* dst = (float4*)Ys;
        for (int k = tid; k < 2048; k += 512) dst[k] = src[k];
        const float4* es = (const float4*)g_E1;
        float4* ed = (float4*)E1s;
        for (int k = tid; k < 4096; k += 512) ed[k] = es[k];
    }
    __syncthreads();

    int kx = tid >> 4, ky = tid & 15;
    float2 z = make_float2(0.f, 0.f);
#pragma unroll 4
    for (int h = 0; h < NH; h++) {
        float2 e = E1s[h*NKX + kx];
        float2 y = Ys[h*NM + ky];
        z = ffma2(make_float2(y.x, y.x), e, z);
        z = ffma2(make_float2(y.y, y.y), make_float2(-e.y, e.x), z);
    }
    Z[((b*NC + i)*NKX + kx)*NM + ky] = z;
}

// ---------------- k2bc: channel mix + inverse H-DFT  Z,W -> G ----------------
// block = (b,o). smem union: phase1 Z-chunk (64KB) / phase2 E2 (64KB); Ts 4KB.
static const int K2BC_SM = 65536 + 4096;
__global__ void __launch_bounds__(256, 3) k2bc_kernel(
        const float2* __restrict__ Z, const float* __restrict__ w1,
        const float* __restrict__ w2, float2* __restrict__ G) {
    extern __shared__ unsigned char sm[];
    float2* U  = (float2*)sm;              // Zs16 [16i][512] / E2s [32kx][256h]
    float2* Ts = (float2*)(sm + 65536);    // [kx][ky] 32*16

    int b = blockIdx.x >> 5, o = blockIdx.x & 31, tid = threadIdx.x;
    int ky = tid & 15, kxm = tid >> 4;     // kxm 0..15
    const float2* w1c = (const float2*)w1;
    const float2* w2c = (const float2*)w2;

    float2 t1 = make_float2(0.f, 0.f);
    float2 t2 = make_float2(0.f, 0.f);

    for (int g = 0; g < 2; g++) {
        {
            const float4* src = (const float4*)(Z + (b*NC + g*16)*NKX*NM);
            float4* dst = (float4*)U;
            for (int k = tid; k < 4096; k += 256) dst[k] = src[k];
        }
        __syncthreads();
#pragma unroll 4
        for (int ii = 0; ii < 16; ii++) {
            int i = g*16 + ii;
            float2 z1 = U[ii*512 + kxm*16 + ky];
            float2 z2 = U[ii*512 + (kxm+16)*16 + ky];
            float2 wv1 = w1c[((i*32 + o)*16 + kxm)*16 + ky];
            float2 wv2 = w2c[((i*32 + o)*16 + kxm)*16 + ky];
            t1 = ffma2(make_float2(z1.x, z1.x), wv1, t1);
            t1 = ffma2(make_float2(z1.y, z1.y), make_float2(-wv1.y, wv1.x), t1);
            t2 = ffma2(make_float2(z2.x, z2.x), wv2, t2);
            t2 = ffma2(make_float2(z2.y, z2.y), make_float2(-wv2.y, wv2.x), t2);
        }
        __syncthreads();
    }
    Ts[kxm*16 + ky]      = t1;
    Ts[(kxm+16)*16 + ky] = t2;
    {   // load E2 into the union region (Z chunk no longer needed)
        const float4* es = (const float4*)g_E2;
        float4* ed = (float4*)U;
        for (int k = tid; k < 4096; k += 256) ed[k] = es[k];
    }
    __syncthreads();

    // phase 2: inverse H-DFT, thread = h
    int h = tid;
    float2 acc[NM];
#pragma unroll
    for (int k = 0; k < NM; k++) acc[k] = make_float2(0.f, 0.f);
#pragma unroll 2
    for (int kx = 0; kx < NKX; kx++) {
        float2 e  = U[kx*NH + h];
        float2 en = make_float2(-e.y, e.x);
#pragma unroll
        for (int k = 0; k < NM; k++) {
            float2 t = Ts[kx*16 + k];
            acc[k] = ffma2(make_float2(t.x, t.x), e,  acc[k]);
            acc[k] = ffma2(make_float2(t.y, t.y), en, acc[k]);
        }
    }
    float4* gp = (float4*)(G + ((b*NC + o)*NH + h)*NM);
    const float s2 = 2.0f / 65536.0f;
#pragma unroll
    for (int k = 0; k < 8; k++) {
        float s0 = (k == 0) ? (1.0f/65536.0f) : s2;
        gp[k] = make_float4(acc[2*k].x*s0, acc[2*k].y*s0, acc[2*k+1].x*s2, acc[2*k+1].y*s2);
    }
}

// ---------------- fused layer row kernel v2 ----------------
// smem: g4[0,4096) | cwq[4096,8192) | cb2[8192,8320) | cs2[8320,41344)
//       | orow2[41344,74368) | xrow[74368,107264)
static const int ROW_SM = 107264;
template<bool HAS_SKIP, bool WRITE_Y>
__global__ void __launch_bounds__(256, 2) layer_kernel(
        const float* __restrict__ xin, const float2* __restrict__ G,
        const float* __restrict__ cw, const float* __restrict__ cb,
        const float* __restrict__ skip, float* __restrict__ xout,
        float2* __restrict__ Ynext) {
    extern __shared__ unsigned char sm[];
    float4* g4    = (float4*)sm;                 // [p][ky] 16*16
    float4* cwq   = (float4*)(sm + 4096);        // [c][p2] 32*8 (4 out-ch each)
    float2* cb2   = (float2*)(sm + 8192);        // 16
    float2* cs2   = (float2*)(sm + 8320);        // [ky][258]
    float2* orow2 = (float2*)(sm + 41344);       // [p][258]
    float*  xrow  = (float*)(sm + 74368);        // [c][257]

    int b = blockIdx.x >> 8, h = blockIdx.x & 255, tid = threadIdx.x;
    int w = tid;

    for (int k = tid; k < NM*NW; k += 256) { int ky=k>>8, ww=k&255; cs2[ky*258+ww] = g_cs[k]; }
    for (int c = 0; c < NC; c++) xrow[c*257 + tid] = xin[((b*NC + c)*NH + h)*NW + tid];
    {   // conv weights: cwq[c*8+p2] = (cw[4p2..4p2+3][c])
        int c = tid >> 3, p2 = tid & 7;
        cwq[tid] = make_float4(cw[(4*p2+0)*32+c], cw[(4*p2+1)*32+c],
                               cw[(4*p2+2)*32+c], cw[(4*p2+3)*32+c]);
    }
    if (tid < 16) cb2[tid] = make_float2(cb[2*tid], cb[2*tid+1]);
    {   // spectral row coefficients, packed (gr0,gr1,gi0,gi1)
        int p = tid >> 4, ky = tid & 15;
        float2 ga = G[((b*NC + 2*p    )*NH + h)*NM + ky];
        float2 gb = G[((b*NC + 2*p + 1)*NH + h)*NM + ky];
        g4[p*16 + ky] = make_float4(ga.x, gb.x, ga.y, gb.y);
    }
    __syncthreads();

    // per-thread twiddles for the synthesis (this w)
    float2 e_syn[NM];
#pragma unroll
    for (int ky = 0; ky < NM; ky++) e_syn[ky] = cs2[ky*258 + w];

#pragma unroll 1
    for (int ph = 0; ph < 2; ph++) {
        float2 acc[8];
#pragma unroll
        for (int k = 0; k < 8; k++) acc[k] = cb2[ph*8 + k];

        // 1x1 conv
#pragma unroll 4
        for (int c = 0; c < NC; c++) {
            float xv = xrow[c*257 + w];
            float2 xv2 = make_float2(xv, xv);
#pragma unroll
            for (int q2 = 0; q2 < 4; q2++) {
                float4 w4 = cwq[c*8 + ph*4 + q2];
                acc[2*q2    ] = ffma2(xv2, make_float2(w4.x, w4.y), acc[2*q2    ]);
                acc[2*q2 + 1] = ffma2(xv2, make_float2(w4.z, w4.w), acc[2*q2 + 1]);
            }
        }
        // spectral synthesis
#pragma unroll
        for (int pp = 0; pp < 8; pp++) {
            int p = ph*8 + pp;
#pragma unroll
            for (int ky = 0; ky < NM; ky++) {
                float4 g = g4[p*16 + ky];
                float2 e = e_syn[ky];
                acc[pp] = ffma2(make_float2(g.x, g.y), make_float2(e.x, e.x),  acc[pp]);
                acc[pp] = ffma2(make_float2(g.z, g.w), make_float2(-e.y, -e.y), acc[pp]);
            }
        }
        // epilogue
#pragma unroll
        for (int pp = 0; pp < 8; pp++) {
            int p = ph*8 + pp;
            float v0 = gelu_f(acc[pp].x);
            float v1 = gelu_f(acc[pp].y);
            int i0 = ((b*NC + 2*p)*NH + h)*NW + w;
            int i1 = i0 + NH*NW;
            if (HAS_SKIP) { v0 += skip[i0]; v1 += skip[i1]; }
            xout[i0] = v0; xout[i1] = v1;
            if (WRITE_Y) orow2[p*258 + w] = make_float2(v0, v1);
        }
    }
    if (WRITE_Y) {
        __syncthreads();
        fwd_dft_row2(orow2, cs2, Ynext, b, h, tid);
    }
}

// ---------------- head: fc1 + GELU + fc2 ----------------
// smem: w1s[0,16384) | xrow[16384,49280) | b1s[49280,49792) | w2p[49792,52864) | b2s
static const int HEAD_SM = 52896;
__global__ void __launch_bounds__(256, 3) head_kernel(
        const float* __restrict__ xin, const float* __restrict__ w1,
        const float* __restrict__ b1, const float* __restrict__ w2,
        const float* __restrict__ b2, float* __restrict__ out) {
    extern __shared__ unsigned char sm[];
    float*  w1s  = (float*)sm;                 // [c][128]
    float*  xrow = (float*)(sm + 16384);       // [c][257]
    float*  b1s  = (float*)(sm + 49280);       // 128
    float2* w2p  = (float2*)(sm + 49792);      // [j][3]
    float*  b2s  = (float*)(sm + 52864);       // 5

    int b = blockIdx.x >> 8, h = blockIdx.x & 255, tid = threadIdx.x;
    for (int c = 0; c < NC; c++) xrow[c*257 + tid] = xin[((b*NC + c)*NH + h)*NW + tid];
    for (int k = tid; k < 4096; k += 256) w1s[k] = w1[k];
    if (tid < 128) {
        b1s[tid] = b1[tid];
        w2p[tid*3 + 0] = make_float2(w2[tid*5 + 0], w2[tid*5 + 1]);
        w2p[tid*3 + 1] = make_float2(w2[tid*5 + 2], w2[tid*5 + 3]);
        w2p[tid*3 + 2] = make_float2(w2[tid*5 + 4], 0.0f);
    }
    if (tid < 5) b2s[tid] = b2[tid];
    __syncthreads();

    int w = tid;
    float2 o01 = make_float2(b2s[0], b2s[1]);
    float2 o23 = make_float2(b2s[2], b2s[3]);
    float2 o4z = make_float2(b2s[4], 0.0f);
    const float4* w1q = (const float4*)w1s;    // [c][32] quads of hidden units
    const float2* b1p = (const float2*)b1s;

#pragma unroll 1
    for (int q = 0; q < 4; q++) {              // hidden quarter: units [32q, 32q+32)
        float2 acc[16];
#pragma unroll
        for (int jj = 0; jj < 16; jj++) acc[jj] = b1p[q*16 + jj];
#pragma unroll 4
        for (int c = 0; c < NC; c++) {
            float xv = xrow[c*257 + w];
            float2 xv2 = make_float2(xv, xv);
#pragma unroll
            for (int j8 = 0; j8 < 8; j8++) {
                float4 w4 = w1q[c*32 + q*8 + j8];
                acc[2*j8    ] = ffma2(xv2, make_float2(w4.x, w4.y), acc[2*j8    ]);
                acc[2*j8 + 1] = ffma2(xv2, make_float2(w4.z, w4.w), acc[2*j8 + 1]);
            }
        }
#pragma unroll
        for (int jj = 0; jj < 16; jj++) {
            int j = 32*q + 2*jj;
            float h0 = gelu_f(acc[jj].x);
            float h1 = gelu_f(acc[jj].y);
            float2 h02 = make_float2(h0, h0), h12 = make_float2(h1, h1);
            o01 = ffma2(h02, w2p[j*3 + 0], o01);
            o23 = ffma2(h02, w2p[j*3 + 1], o23);
            o4z = ffma2(h02, w2p[j*3 + 2], o4z);
            o01 = ffma2(h12, w2p[(j+1)*3 + 0], o01);
            o23 = ffma2(h12, w2p[(j+1)*3 + 1], o23);
            o4z = ffma2(h12, w2p[(j+1)*3 + 2], o4z);
        }
    }
    float* op = out + (((b*NH) + h)*NW + w) * 5;
    op[0] = o01.x; op[1] = o01.y; op[2] = o23.x; op[3] = o23.y; op[4] = o4z.x;
}

// ---------------- host launcher ----------------
extern "C" void kernel_launch(void* const* d_in, const int* in_sizes, int n_in,
                              void* d_out, int out_size) {
    const float* x     = (const float*)d_in[0];
    const float* fc0w  = (const float*)d_in[1];
    const float* fc0b  = (const float*)d_in[2];
    const float* w1    = (const float*)d_in[3];
    const float* w2    = (const float*)d_in[4];
    const float* convw = (const float*)d_in[5];
    const float* convb = (const float*)d_in[6];
    const float* fc1w  = (const float*)d_in[7];
    const float* fc1b  = (const float*)d_in[8];
    const float* fc2w  = (const float*)d_in[9];
    const float* fc2b  = (const float*)d_in[10];
    float* out = (float*)d_out;

    float  *bufA, *bufB, *bufC;
    float2 *Y, *Z, *G;
    cudaGetSymbolAddress((void**)&bufA, g_bufA);
    cudaGetSymbolAddress((void**)&bufB, g_bufB);
    cudaGetSymbolAddress((void**)&bufC, g_bufC);
    cudaGetSymbolAddress((void**)&Y, g_Y);
    cudaGetSymbolAddress((void**)&Z, g_Zb);
    cudaGetSymbolAddress((void**)&G, g_G);

    cudaFuncSetAttribute(lift_kernel, cudaFuncAttributeMaxDynamicSharedMemorySize, LIFT_SM);
    cudaFuncSetAttribute(k2a_kernel,  cudaFuncAttributeMaxDynamicSharedMemorySize, K2A_SM);
    cudaFuncSetAttribute(k2bc_kernel, cudaFuncAttributeMaxDynamicSharedMemorySize, K2BC_SM);
    cudaFuncSetAttribute(head_kernel, cudaFuncAttributeMaxDynamicSharedMemorySize, HEAD_SM);
    cudaFuncSetAttribute(layer_kernel<false, false>, cudaFuncAttributeMaxDynamicSharedMemorySize, ROW_SM);
    cudaFuncSetAttribute(layer_kernel<false, true >, cudaFuncAttributeMaxDynamicSharedMemorySize, ROW_SM);
    cudaFuncSetAttribute(layer_kernel<true,  true >, cudaFuncAttributeMaxDynamicSharedMemorySize, ROW_SM);
    cudaFuncSetAttribute(layer_kernel<true,  false>, cudaFuncAttributeMaxDynamicSharedMemorySize, ROW_SM);

    init_tables<<<64, 256>>>();
    lift_kernel<<<NB*NH, 256, LIFT_SM>>>(x, fc0w, fc0b, bufA, Y);   // A = lift, Y = Y_lift

    // Reference DAG:
    //   h0 = L0(lift);  t1 = L1(lift);  t2 = L2(t1) + h0;
    //   h1 = L3(t2);    t4 = L4(t2);    out = L5(t4) + h1;
    // Y usage: L0,L1 share Y_lift; L2 uses Y_t1; L3,L4 share Y_t2; L5 uses Y_t4.
    struct Step { int in, out, skip; bool hasSkip, writeY; };
    const Step steps[6] = {
        {0, 1, -1, false, false},  // L0: A -> B (h0)
        {0, 2, -1, false, true },  // L1: A -> C (t1), write Y_t1
        {2, 0,  1, true,  true },  // L2: C -> A (t2) + skip B, write Y_t2
        {0, 1, -1, false, false},  // L3: A -> B (h1)
        {0, 2, -1, false, true },  // L4: A -> C (t4), write Y_t4
        {2, 0,  1, true,  false},  // L5: C -> A (final) + skip B
    };
    float* bufs[3] = { bufA, bufB, bufC };

    for (int l = 0; l < 6; l++) {
        const float* w1l = w1 + (size_t)l * WSZ;
        const float* w2l = w2 + (size_t)l * WSZ;
        const float* cwl = convw + l * 32 * 32;
        const float* cbl = convb + l * 32;

        k2a_kernel<<<NB*NC, 512, K2A_SM>>>(Y, Z);
        k2bc_kernel<<<NB*NC, 256, K2BC_SM>>>(Z, w1l, w2l, G);

        const Step& s = steps[l];
        const float* in   = bufs[s.in];
        float*       outb = bufs[s.out];
        const float* sk   = (s.skip >= 0) ? bufs[s.skip] : nullptr;
        if (s.hasSkip) {
            if (s.writeY)
                layer_kernel<true,  true ><<<NB*NH, 256, ROW_SM>>>(in, G, cwl, cbl, sk, outb, Y);
            else
                layer_kernel<true,  false><<<NB*NH, 256, ROW_SM>>>(in, G, cwl, cbl, sk, outb, Y);
        } else {
            if (s.writeY)
                layer_kernel<false, true ><<<NB*NH, 256, ROW_SM>>>(in, G, cwl, cbl, nullptr, outb, Y);
            else
                layer_kernel<false, false><<<NB*NH, 256, ROW_SM>>>(in, G, cwl, cbl, nullptr, outb, Y);
        }
    }

    head_kernel<<<NB*NH, 256, HEAD_SM>>>(bufA, fc1w, fc1b, fc2w, fc2b, out);
}

// round 6
// speedup vs baseline: 1.5223x; 1.2112x over previous
#include <cuda_runtime.h>
#include <math.h>

// ---------------- problem constants ----------------
#define NB 8
#define NC 32
#define NH 256
#define NW 256
#define NM 16            // modes M1 = M2 = 16
#define NKX 32           // 16 top rows + 16 bottom rows
#define WSZ (32*32*16*16*2)   // per-layer w1/w2 float count

// ---------------- device scratch ----------------
__device__ float  g_bufA[NB*NC*NH*NW];
__device__ float  g_bufB[NB*NC*NH*NW];
__device__ float  g_bufC[NB*NC*NH*NW];
__device__ float2 g_Y[NB*NC*NH*NM];      // [b][c][h][ky]
__device__ float2 g_Zb[NB*NC*NKX*NM];    // [b][i][kx][ky]
__device__ float2 g_G[NB*NC*NH*NM];      // [b][o][h][ky]
__device__ float2 g_cs[NM*NW];           // [ky][w]  (cos,sin) of 2*pi*ky*w/256
__device__ float2 g_E1[NH*NKX];          // [h][kx]  e^{-i phi}
__device__ float2 g_E2[NKX*NH];          // [kx][h]  e^{+i phi}

// ---------------- helpers ----------------
__device__ __forceinline__ float2 ffma2(float2 a, float2 b, float2 c) {
    float2 d;
    asm("fma.rn.f32x2 %0, %1, %2, %3;"
        : "=l"(reinterpret_cast<unsigned long long&>(d))
        : "l"(reinterpret_cast<unsigned long long&>(a)),
          "l"(reinterpret_cast<unsigned long long&>(b)),
          "l"(reinterpret_cast<unsigned long long&>(c)));
    return d;
}
__device__ __forceinline__ float gelu_f(float v) {
    return 0.5f * v * (1.0f + erff(v * 0.7071067811865476f));
}

// ---------------- table init ----------------
__global__ void init_tables() {
    int gid = blockIdx.x * blockDim.x + threadIdx.x;
    int nth = gridDim.x * blockDim.x;
    for (int k = gid; k < NM*NW; k += nth) {
        int ky = k >> 8, w = k & 255;
        int m = (ky * w) & 255;
        float a = (float)m * (1.0f/128.0f);
        g_cs[k] = make_float2(cospif(a), sinpif(a));
    }
    for (int k = gid; k < NH*NKX; k += nth) {
        int h = k >> 5, kx = k & 31;
        int fr = (kx < 16) ? kx : (kx - 32);
        int m = (fr * h) & 255;
        float a = (float)m * (1.0f/128.0f);
        float cp = cospif(a), sp = sinpif(a);
        g_E1[k] = make_float2(cp, -sp);         // e^{-i phi}
        g_E2[kx*NH + h] = make_float2(cp, sp);  // e^{+i phi}
    }
}

// ---------------- folded forward partial W-DFT ----------------
// orow2: float2[16][258], pair p holds channels (2p,2p+1).
// Layout AFTER folding: [p][w<128] = o(w)+o(w+128), [p][128+w] = o(w)-o(w+128).
// Y(ky) = sum_{w<128} sel_parity(w) * e(ky,w).
__device__ __forceinline__ void dft_fold(float2* orow2, int tid) {
    int wl = tid & 127, half = tid >> 7;
#pragma unroll
    for (int pp = 0; pp < 8; pp++) {
        int p = half*8 + pp;
        float2 a = orow2[p*258 + wl];
        float2 c = orow2[p*258 + 128 + wl];
        orow2[p*258 + wl]       = make_float2(a.x + c.x, a.y + c.y);
        orow2[p*258 + 128 + wl] = make_float2(a.x - c.x, a.y - c.y);
    }
}

__device__ __forceinline__ void fwd_dft_row3(const float2* orow2, const float2* cs2,
                                             float2* __restrict__ Y, int b, int h, int tid) {
    int q  = tid >> 4;       // channel-pair 0..15
    int ky = tid & 15;
    float2 yr = make_float2(0.f, 0.f);
    float2 yi = make_float2(0.f, 0.f);
    const float4* op = (const float4*)(orow2 + q*258 + ((ky & 1) ? 128 : 0));
    const float4* ep = (const float4*)(cs2  + ky*258);
#pragma unroll 8
    for (int w2 = 0; w2 < 64; w2++) {
        float4 o4 = op[w2];
        float4 e4 = ep[w2];
        yr = ffma2(make_float2(o4.x, o4.y), make_float2(e4.x,  e4.x), yr);
        yi = ffma2(make_float2(o4.x, o4.y), make_float2(-e4.y, -e4.y), yi);
        yr = ffma2(make_float2(o4.z, o4.w), make_float2(e4.z,  e4.z), yr);
        yi = ffma2(make_float2(o4.z, o4.w), make_float2(-e4.w, -e4.w), yi);
    }
    Y[((b*NC + 2*q    )*NH + h)*NM + ky] = make_float2(yr.x, yi.x);
    Y[((b*NC + 2*q + 1)*NH + h)*NM + ky] = make_float2(yr.y, yi.y);
}

// ---------------- lift ----------------
// smem: cs2[0..33024) | orow2[33024..66048) | w0s | b0s
static const int LIFT_SM = 33024 + 33024 + 1536 + 128;
__global__ void __launch_bounds__(256) lift_kernel(
        const float* __restrict__ x, const float* __restrict__ w0,
        const float* __restrict__ b0, float* __restrict__ out, float2* __restrict__ Y) {
    extern __shared__ unsigned char sm[];
    float2* cs2   = (float2*)sm;
    float2* orow2 = (float2*)(sm + 33024);
    float*  w0s   = (float*)(sm + 66048);
    float*  b0s   = (float*)(sm + 66048 + 1536);
    float*  orowf = (float*)orow2;

    int b = blockIdx.x >> 8, h = blockIdx.x & 255, tid = threadIdx.x;

    for (int k = tid; k < NM*NW; k += 256) { int ky=k>>8, w=k&255; cs2[ky*258+w] = g_cs[k]; }
    for (int k = tid; k < 384; k += 256) w0s[k] = w0[k];
    if (tid < 32) b0s[tid] = b0[tid];
    __syncthreads();

    int w = tid;
    const float* xp = x + (((b*NH) + h)*NW + w) * 10;
    float xv[10];
#pragma unroll
    for (int t = 0; t < 10; t++) xv[t] = xp[t];
    float gx = (float)h * (1.0f/255.0f);
    float gy = (float)w * (1.0f/255.0f);

    for (int c = 0; c < NC; c++) {
        float acc = b0s[c];
#pragma unroll
        for (int t = 0; t < 10; t++) acc = fmaf(xv[t], w0s[t*32 + c], acc);
        acc = fmaf(gx, w0s[10*32 + c], acc);
        acc = fmaf(gy, w0s[11*32 + c], acc);
        out[((b*NC + c)*NH + h)*NW + w] = acc;
        orowf[(c >> 1)*516 + 2*w + (c & 1)] = acc;
    }
    __syncthreads();
    dft_fold(orow2, tid);
    __syncthreads();
    fwd_dft_row3(orow2, cs2, Y, b, h, tid);
}

// ---------------- k2a: H-DFT  Y -> Z ----------------
static const int K2A_SM = 32768 + 65536;   // Ys, E1s
__global__ void __launch_bounds__(512, 2) k2a_kernel(
        const float2* __restrict__ Y, float2* __restrict__ Z) {
    extern __shared__ unsigned char sm[];
    float2* Ys  = (float2*)sm;             // [h][ky] 256*16
    float2* E1s = (float2*)(sm + 32768);   // [h][kx] 256*32

    int b = blockIdx.x >> 5, i = blockIdx.x & 31, tid = threadIdx.x;
    {
        const float4* src = (const float4*)(Y + (b*NC + i)*NH*NM);
        float4* dst = (float4*)Ys;
        for (int k = tid; k < 2048; k += 512) dst[k] = src[k];
        const float4* es = (const float4*)g_E1;
        float4* ed = (float4*)E1s;
        for (int k = tid; k < 4096; k += 512) ed[k] = es[k];
    }
    __syncthreads();

    int kx = tid >> 4, ky = tid & 15;
    float2 z = make_float2(0.f, 0.f);
#pragma unroll 4
    for (int h = 0; h < NH; h++) {
        float2 e = E1s[h*NKX + kx];
        float2 y = Ys[h*NM + ky];
        z = ffma2(make_float2(y.x, y.x), e, z);
        z = ffma2(make_float2(y.y, y.y), make_float2(-e.y, e.x), z);
    }
    Z[((b*NC + i)*NKX + kx)*NM + ky] = z;
}

// ---------------- k2bc v2: channel mix + inverse H-DFT  Z,W -> G ----------------
// block = (b,o). No bulk smem staging: Z / weights / E2 read directly from
// global (coalesced, L2-resident). Only Ts (4KB) shared between phases.
__global__ void __launch_bounds__(256) k2bc_kernel(
        const float2* __restrict__ Z, const float* __restrict__ w1,
        const float* __restrict__ w2, float2* __restrict__ G) {
    __shared__ float2 Ts[NKX*NM];          // [kx][ky] 32*16

    int b = blockIdx.x >> 5, o = blockIdx.x & 31, tid = threadIdx.x;
    int ky = tid & 15, kxm = tid >> 4;     // kxm 0..15
    const float2* w1c = (const float2*)w1;
    const float2* w2c = (const float2*)w2;
    const float2* zb  = Z + (size_t)b*NC*NKX*NM;

    float2 t1 = make_float2(0.f, 0.f);
    float2 t2 = make_float2(0.f, 0.f);
#pragma unroll 4
    for (int i = 0; i < NC; i++) {
        float2 z1 = zb[i*NKX*NM + kxm*NM + ky];
        float2 z2 = zb[i*NKX*NM + (kxm+16)*NM + ky];
        float2 wv1 = w1c[((i*32 + o)*16 + kxm)*16 + ky];
        float2 wv2 = w2c[((i*32 + o)*16 + kxm)*16 + ky];
        t1 = ffma2(make_float2(z1.x, z1.x), wv1, t1);
        t1 = ffma2(make_float2(z1.y, z1.y), make_float2(-wv1.y, wv1.x), t1);
        t2 = ffma2(make_float2(z2.x, z2.x), wv2, t2);
        t2 = ffma2(make_float2(z2.y, z2.y), make_float2(-wv2.y, wv2.x), t2);
    }
    Ts[kxm*16 + ky]      = t1;
    Ts[(kxm+16)*16 + ky] = t2;
    __syncthreads();

    // phase 2: inverse H-DFT, thread = h
    int h = tid;
    float2 acc[NM];
#pragma unroll
    for (int k = 0; k < NM; k++) acc[k] = make_float2(0.f, 0.f);
#pragma unroll 2
    for (int kx = 0; kx < NKX; kx++) {
        float2 e  = g_E2[kx*NH + h];
        float2 en = make_float2(-e.y, e.x);
#pragma unroll
        for (int k = 0; k < NM; k++) {
            float2 t = Ts[kx*16 + k];
            acc[k] = ffma2(make_float2(t.x, t.x), e,  acc[k]);
            acc[k] = ffma2(make_float2(t.y, t.y), en, acc[k]);
        }
    }
    float4* gp = (float4*)(G + ((b*NC + o)*NH + h)*NM);
    const float s2 = 2.0f / 65536.0f;
#pragma unroll
    for (int k = 0; k < 8; k++) {
        float s0 = (k == 0) ? (1.0f/65536.0f) : s2;
        gp[k] = make_float4(acc[2*k].x*s0, acc[2*k].y*s0, acc[2*k+1].x*s2, acc[2*k+1].y*s2);
    }
}

// ---------------- fused layer row kernel v3 (w/w+128 pairing + parity fold) ----------------
// smem: g4[0,4096) | cwq[4096,8192) | cb2[8192,8320) | cs2[8320,41344)
//       | orow2[41344,74368) | xrow[74368,107264)
static const int ROW_SM = 107264;
template<bool HAS_SKIP, bool WRITE_Y>
__global__ void __launch_bounds__(256, 2) layer_kernel(
        const float* __restrict__ xin, const float2* __restrict__ G,
        const float* __restrict__ cw, const float* __restrict__ cb,
        const float* __restrict__ skip, float* __restrict__ xout,
        float2* __restrict__ Ynext) {
    extern __shared__ unsigned char sm[];
    float4* g4    = (float4*)sm;                 // [p][ky] 16*16
    float4* cwq   = (float4*)(sm + 4096);        // [c][p2] 32*8 (4 out-ch each)
    float2* cb2   = (float2*)(sm + 8192);        // 16
    float2* cs2   = (float2*)(sm + 8320);        // [ky][258]
    float2* orow2 = (float2*)(sm + 41344);       // [p][258]
    float*  xrow  = (float*)(sm + 74368);        // [c][257]

    int b = blockIdx.x >> 8, h = blockIdx.x & 255, tid = threadIdx.x;

    for (int k = tid; k < NM*NW; k += 256) { int ky=k>>8, ww=k&255; cs2[ky*258+ww] = g_cs[k]; }
    for (int c = 0; c < NC; c++) xrow[c*257 + tid] = xin[((b*NC + c)*NH + h)*NW + tid];
    {   // conv weights: cwq[c*8+p2] = (cw[4p2..4p2+3][c])
        int c = tid >> 3, p2 = tid & 7;
        cwq[tid] = make_float4(cw[(4*p2+0)*32+c], cw[(4*p2+1)*32+c],
                               cw[(4*p2+2)*32+c], cw[(4*p2+3)*32+c]);
    }
    if (tid < 16) cb2[tid] = make_float2(cb[2*tid], cb[2*tid+1]);
    {   // spectral row coefficients, packed (gr0,gr1,gi0,gi1)
        int p = tid >> 4, ky = tid & 15;
        float2 ga = G[((b*NC + 2*p    )*NH + h)*NM + ky];
        float2 gb = G[((b*NC + 2*p + 1)*NH + h)*NM + ky];
        g4[p*16 + ky] = make_float4(ga.x, gb.x, ga.y, gb.y);
    }
    __syncthreads();

    // thread = (wl, channel-half). Handles w=wl and w=wl+128 for 8 channel-pairs.
    int wl = tid & 127, half = tid >> 7;

    float2 e_syn[NM];
#pragma unroll
    for (int ky = 0; ky < NM; ky++) e_syn[ky] = cs2[ky*258 + wl];

    float2 ca[8], cbv[8], aP[8], aQ[8];
#pragma unroll
    for (int k = 0; k < 8; k++) {
        float2 bias = cb2[half*8 + k];
        ca[k] = bias; cbv[k] = bias;
        aP[k] = make_float2(0.f, 0.f);
        aQ[k] = make_float2(0.f, 0.f);
    }

    // 1x1 conv for both w positions
#pragma unroll 4
    for (int c = 0; c < NC; c++) {
        float xa = xrow[c*257 + wl];
        float xb = xrow[c*257 + wl + 128];
        float2 xa2 = make_float2(xa, xa), xb2 = make_float2(xb, xb);
#pragma unroll
        for (int q2 = 0; q2 < 4; q2++) {
            float4 w4 = cwq[c*8 + half*4 + q2];
            ca [2*q2    ] = ffma2(xa2, make_float2(w4.x, w4.y), ca [2*q2    ]);
            ca [2*q2 + 1] = ffma2(xa2, make_float2(w4.z, w4.w), ca [2*q2 + 1]);
            cbv[2*q2    ] = ffma2(xb2, make_float2(w4.x, w4.y), cbv[2*q2    ]);
            cbv[2*q2 + 1] = ffma2(xb2, make_float2(w4.z, w4.w), cbv[2*q2 + 1]);
        }
    }

    // spectral synthesis: even-ky (P) and odd-ky (Q) partial sums; w+128 = P - Q
#pragma unroll
    for (int pp = 0; pp < 8; pp++) {
        int p = half*8 + pp;
#pragma unroll
        for (int ky = 0; ky < NM; ky++) {
            float4 g = g4[p*16 + ky];
            float2 e = e_syn[ky];
            if ((ky & 1) == 0) {
                aP[pp] = ffma2(make_float2(g.x, g.y), make_float2(e.x, e.x),   aP[pp]);
                aP[pp] = ffma2(make_float2(g.z, g.w), make_float2(-e.y, -e.y), aP[pp]);
            } else {
                aQ[pp] = ffma2(make_float2(g.x, g.y), make_float2(e.x, e.x),   aQ[pp]);
                aQ[pp] = ffma2(make_float2(g.z, g.w), make_float2(-e.y, -e.y), aQ[pp]);
            }
        }
    }

    // epilogue
#pragma unroll
    for (int pp = 0; pp < 8; pp++) {
        int p = half*8 + pp;
        float sa0 = ca[pp].x + (aP[pp].x + aQ[pp].x);
        float sa1 = ca[pp].y + (aP[pp].y + aQ[pp].y);
        float sb0 = cbv[pp].x + (aP[pp].x - aQ[pp].x);
        float sb1 = cbv[pp].y + (aP[pp].y - aQ[pp].y);
        float v0a = gelu_f(sa0), v1a = gelu_f(sa1);
        float v0b = gelu_f(sb0), v1b = gelu_f(sb1);
        int i0 = ((b*NC + 2*p)*NH + h)*NW + wl;
        int i1 = i0 + NH*NW;
        if (HAS_SKIP) {
            v0a += skip[i0];       v0b += skip[i0 + 128];
            v1a += skip[i1];       v1b += skip[i1 + 128];
        }
        xout[i0] = v0a; xout[i0 + 128] = v0b;
        xout[i1] = v1a; xout[i1 + 128] = v1b;
        if (WRITE_Y) {
            orow2[p*258 + wl]       = make_float2(v0a + v0b, v1a + v1b);
            orow2[p*258 + 128 + wl] = make_float2(v0a - v0b, v1a - v1b);
        }
    }
    if (WRITE_Y) {
        __syncthreads();
        fwd_dft_row3(orow2, cs2, Ynext, b, h, tid);
    }
}

// ---------------- head: fc1 + GELU + fc2 ----------------
// smem: w1s[0,16384) | xrow[16384,49280) | b1s[49280,49792) | w2p[49792,52864) | b2s
static const int HEAD_SM = 52896;
__global__ void __launch_bounds__(256, 3) head_kernel(
        const float* __restrict__ xin, const float* __restrict__ w1,
        const float* __restrict__ b1, const float* __restrict__ w2,
        const float* __restrict__ b2, float* __restrict__ out) {
    extern __shared__ unsigned char sm[];
    float*  w1s  = (float*)sm;                 // [c][128]
    float*  xrow = (float*)(sm + 16384);       // [c][257]
    float*  b1s  = (float*)(sm + 49280);       // 128
    float2* w2p  = (float2*)(sm + 49792);      // [j][3]
    float*  b2s  = (float*)(sm + 52864);       // 5

    int b = blockIdx.x >> 8, h = blockIdx.x & 255, tid = threadIdx.x;
    for (int c = 0; c < NC; c++) xrow[c*257 + tid] = xin[((b*NC + c)*NH + h)*NW + tid];
    for (int k = tid; k < 4096; k += 256) w1s[k] = w1[k];
    if (tid < 128) {
        b1s[tid] = b1[tid];
        w2p[tid*3 + 0] = make_float2(w2[tid*5 + 0], w2[tid*5 + 1]);
        w2p[tid*3 + 1] = make_float2(w2[tid*5 + 2], w2[tid*5 + 3]);
        w2p[tid*3 + 2] = make_float2(w2[tid*5 + 4], 0.0f);
    }
    if (tid < 5) b2s[tid] = b2[tid];
    __syncthreads();

    int w = tid;
    float2 o01 = make_float2(b2s[0], b2s[1]);
    float2 o23 = make_float2(b2s[2], b2s[3]);
    float2 o4z = make_float2(b2s[4], 0.0f);
    const float4* w1q = (const float4*)w1s;    // [c][32] quads of hidden units
    const float2* b1p = (const float2*)b1s;

#pragma unroll 1
    for (int q = 0; q < 4; q++) {              // hidden quarter: units [32q, 32q+32)
        float2 acc[16];
#pragma unroll
        for (int jj = 0; jj < 16; jj++) acc[jj] = b1p[q*16 + jj];
#pragma unroll 4
        for (int c = 0; c < NC; c++) {
            float xv = xrow[c*257 + w];
            float2 xv2 = make_float2(xv, xv);
#pragma unroll
            for (int j8 = 0; j8 < 8; j8++) {
                float4 w4 = w1q[c*32 + q*8 + j8];
                acc[2*j8    ] = ffma2(xv2, make_float2(w4.x, w4.y), acc[2*j8    ]);
                acc[2*j8 + 1] = ffma2(xv2, make_float2(w4.z, w4.w), acc[2*j8 + 1]);
            }
        }
#pragma unroll
        for (int jj = 0; jj < 16; jj++) {
            int j = 32*q + 2*jj;
            float h0 = gelu_f(acc[jj].x);
            float h1 = gelu_f(acc[jj].y);
            float2 h02 = make_float2(h0, h0), h12 = make_float2(h1, h1);
            o01 = ffma2(h02, w2p[j*3 + 0], o01);
            o23 = ffma2(h02, w2p[j*3 + 1], o23);
            o4z = ffma2(h02, w2p[j*3 + 2], o4z);
            o01 = ffma2(h12, w2p[(j+1)*3 + 0], o01);
            o23 = ffma2(h12, w2p[(j+1)*3 + 1], o23);
            o4z = ffma2(h12, w2p[(j+1)*3 + 2], o4z);
        }
    }
    float* op = out + (((b*NH) + h)*NW + w) * 5;
    op[0] = o01.x; op[1] = o01.y; op[2] = o23.x; op[3] = o23.y; op[4] = o4z.x;
}

// ---------------- host launcher ----------------
extern "C" void kernel_launch(void* const* d_in, const int* in_sizes, int n_in,
                              void* d_out, int out_size) {
    const float* x     = (const float*)d_in[0];
    const float* fc0w  = (const float*)d_in[1];
    const float* fc0b  = (const float*)d_in[2];
    const float* w1    = (const float*)d_in[3];
    const float* w2    = (const float*)d_in[4];
    const float* convw = (const float*)d_in[5];
    const float* convb = (const float*)d_in[6];
    const float* fc1w  = (const float*)d_in[7];
    const float* fc1b  = (const float*)d_in[8];
    const float* fc2w  = (const float*)d_in[9];
    const float* fc2b  = (const float*)d_in[10];
    float* out = (float*)d_out;

    float  *bufA, *bufB, *bufC;
    float2 *Y, *Z, *G;
    cudaGetSymbolAddress((void**)&bufA, g_bufA);
    cudaGetSymbolAddress((void**)&bufB, g_bufB);
    cudaGetSymbolAddress((void**)&bufC, g_bufC);
    cudaGetSymbolAddress((void**)&Y, g_Y);
    cudaGetSymbolAddress((void**)&Z, g_Zb);
    cudaGetSymbolAddress((void**)&G, g_G);

    cudaFuncSetAttribute(lift_kernel, cudaFuncAttributeMaxDynamicSharedMemorySize, LIFT_SM);
    cudaFuncSetAttribute(k2a_kernel,  cudaFuncAttributeMaxDynamicSharedMemorySize, K2A_SM);
    cudaFuncSetAttribute(head_kernel, cudaFuncAttributeMaxDynamicSharedMemorySize, HEAD_SM);
    cudaFuncSetAttribute(layer_kernel<false, false>, cudaFuncAttributeMaxDynamicSharedMemorySize, ROW_SM);
    cudaFuncSetAttribute(layer_kernel<false, true >, cudaFuncAttributeMaxDynamicSharedMemorySize, ROW_SM);
    cudaFuncSetAttribute(layer_kernel<true,  true >, cudaFuncAttributeMaxDynamicSharedMemorySize, ROW_SM);
    cudaFuncSetAttribute(layer_kernel<true,  false>, cudaFuncAttributeMaxDynamicSharedMemorySize, ROW_SM);

    init_tables<<<64, 256>>>();
    lift_kernel<<<NB*NH, 256, LIFT_SM>>>(x, fc0w, fc0b, bufA, Y);   // A = lift, Y = Y_lift

    // Reference DAG:
    //   h0 = L0(lift);  t1 = L1(lift);  t2 = L2(t1) + h0;
    //   h1 = L3(t2);    t4 = L4(t2);    out = L5(t4) + h1;
    // Z (= H-DFT of Y) is weight-independent -> shared by L0/L1 and by L3/L4.
    const float* w1p[6]; const float* w2p_[6]; const float* cwp[6]; const float* cbp[6];
    for (int l = 0; l < 6; l++) {
        w1p[l] = w1 + (size_t)l * WSZ;
        w2p_[l] = w2 + (size_t)l * WSZ;
        cwp[l] = convw + l * 32 * 32;
        cbp[l] = convb + l * 32;
    }

    // L0 + L1 share Z from Y_lift
    k2a_kernel<<<NB*NC, 512, K2A_SM>>>(Y, Z);
    k2bc_kernel<<<NB*NC, 256>>>(Z, w1p[0], w2p_[0], G);
    layer_kernel<false, false><<<NB*NH, 256, ROW_SM>>>(bufA, G, cwp[0], cbp[0], nullptr, bufB, Y); // h0
    k2bc_kernel<<<NB*NC, 256>>>(Z, w1p[1], w2p_[1], G);
    layer_kernel<false, true ><<<NB*NH, 256, ROW_SM>>>(bufA, G, cwp[1], cbp[1], nullptr, bufC, Y); // t1, Y_t1

    // L2
    k2a_kernel<<<NB*NC, 512, K2A_SM>>>(Y, Z);
    k2bc_kernel<<<NB*NC, 256>>>(Z, w1p[2], w2p_[2], G);
    layer_kernel<true,  true ><<<NB*NH, 256, ROW_SM>>>(bufC, G, cwp[2], cbp[2], bufB, bufA, Y);    // t2, Y_t2

    // L3 + L4 share Z from Y_t2
    k2a_kernel<<<NB*NC, 512, K2A_SM>>>(Y, Z);
    k2bc_kernel<<<NB*NC, 256>>>(Z, w1p[3], w2p_[3], G);
    layer_kernel<false, false><<<NB*NH, 256, ROW_SM>>>(bufA, G, cwp[3], cbp[3], nullptr, bufB, Y); // h1
    k2bc_kernel<<<NB*NC, 256>>>(Z, w1p[4], w2p_[4], G);
    layer_kernel<false, true ><<<NB*NH, 256, ROW_SM>>>(bufA, G, cwp[4], cbp[4], nullptr, bufC, Y); // t4, Y_t4

    // L5
    k2a_kernel<<<NB*NC, 512, K2A_SM>>>(Y, Z);
    k2bc_kernel<<<NB*NC, 256>>>(Z, w1p[5], w2p_[5], G);
    layer_kernel<true,  false><<<NB*NH, 256, ROW_SM>>>(bufC, G, cwp[5], cbp[5], bufB, bufA, Y);    // final

    head_kernel<<<NB*NH, 256, HEAD_SM>>>(bufA, fc1w, fc1b, fc2w, fc2b, out);
}

// round 7
// speedup vs baseline: 1.5442x; 1.0144x over previous
#include <cuda_runtime.h>
#include <math.h>

// ---------------- problem constants ----------------
#define NB 8
#define NC 32
#define NH 256
#define NW 256
#define NM 16            // modes M1 = M2 = 16
#define NKX 32           // 16 top rows + 16 bottom rows
#define WSZ (32*32*16*16*2)   // per-layer w1/w2 float count

// ---------------- device scratch ----------------
__device__ float  g_bufA[NB*NC*NH*NW];
__device__ float  g_bufB[NB*NC*NH*NW];
__device__ float  g_bufC[NB*NC*NH*NW];
__device__ float2 g_Y[NB*NC*NH*NM];      // [b][c][h][ky]
__device__ float2 g_Zb[NB*NC*NKX*NM];    // [b][i][kx][ky]
__device__ float2 g_G[NB*NC*NH*NM];      // [b][o][h][ky]
__device__ float2 g_G2[NB*NC*NH*NM];     // second G for paired layers
__device__ float2 g_cs[NM*NW];           // [ky][w]  (cos,sin) of 2*pi*ky*w/256
__device__ float2 g_E1[NH*NKX];          // [h][kx]  e^{-i phi}
__device__ float2 g_E2[NKX*NH];          // [kx][h]  e^{+i phi}

// ---------------- helpers ----------------
__device__ __forceinline__ float2 ffma2(float2 a, float2 b, float2 c) {
    float2 d;
    asm("fma.rn.f32x2 %0, %1, %2, %3;"
        : "=l"(reinterpret_cast<unsigned long long&>(d))
        : "l"(reinterpret_cast<unsigned long long&>(a)),
          "l"(reinterpret_cast<unsigned long long&>(b)),
          "l"(reinterpret_cast<unsigned long long&>(c)));
    return d;
}
__device__ __forceinline__ float gelu_f(float v) {
    return 0.5f * v * (1.0f + erff(v * 0.7071067811865476f));
}

// ---------------- table init ----------------
__global__ void init_tables() {
    int gid = blockIdx.x * blockDim.x + threadIdx.x;
    int nth = gridDim.x * blockDim.x;
    for (int k = gid; k < NM*NW; k += nth) {
        int ky = k >> 8, w = k & 255;
        int m = (ky * w) & 255;
        float a = (float)m * (1.0f/128.0f);
        g_cs[k] = make_float2(cospif(a), sinpif(a));
    }
    for (int k = gid; k < NH*NKX; k += nth) {
        int h = k >> 5, kx = k & 31;
        int fr = (kx < 16) ? kx : (kx - 32);
        int m = (fr * h) & 255;
        float a = (float)m * (1.0f/128.0f);
        float cp = cospif(a), sp = sinpif(a);
        g_E1[k] = make_float2(cp, -sp);         // e^{-i phi}
        g_E2[kx*NH + h] = make_float2(cp, sp);  // e^{+i phi}
    }
}

// ---------------- folded forward partial W-DFT ----------------
// orow2: float2[16][258], pair p holds channels (2p,2p+1).
// Layout AFTER folding: [p][w<128] = o(w)+o(w+128), [p][128+w] = o(w)-o(w+128).
__device__ __forceinline__ void dft_fold(float2* orow2, int tid) {
    int wl = tid & 127, half = tid >> 7;
#pragma unroll
    for (int pp = 0; pp < 8; pp++) {
        int p = half*8 + pp;
        float2 a = orow2[p*258 + wl];
        float2 c = orow2[p*258 + 128 + wl];
        orow2[p*258 + wl]       = make_float2(a.x + c.x, a.y + c.y);
        orow2[p*258 + 128 + wl] = make_float2(a.x - c.x, a.y - c.y);
    }
}

__device__ __forceinline__ void fwd_dft_row3(const float2* orow2, const float2* cs2,
                                             float2* __restrict__ Y, int b, int h, int tid) {
    int q  = tid >> 4;       // channel-pair 0..15
    int ky = tid & 15;
    float2 yr = make_float2(0.f, 0.f);
    float2 yi = make_float2(0.f, 0.f);
    const float4* op = (const float4*)(orow2 + q*258 + ((ky & 1) ? 128 : 0));
    const float4* ep = (const float4*)(cs2  + ky*258);
#pragma unroll 8
    for (int w2 = 0; w2 < 64; w2++) {
        float4 o4 = op[w2];
        float4 e4 = ep[w2];
        yr = ffma2(make_float2(o4.x, o4.y), make_float2(e4.x,  e4.x), yr);
        yi = ffma2(make_float2(o4.x, o4.y), make_float2(-e4.y, -e4.y), yi);
        yr = ffma2(make_float2(o4.z, o4.w), make_float2(e4.z,  e4.z), yr);
        yi = ffma2(make_float2(o4.z, o4.w), make_float2(-e4.w, -e4.w), yi);
    }
    Y[((b*NC + 2*q    )*NH + h)*NM + ky] = make_float2(yr.x, yi.x);
    Y[((b*NC + 2*q + 1)*NH + h)*NM + ky] = make_float2(yr.y, yi.y);
}

// ---------------- lift ----------------
static const int LIFT_SM = 33024 + 33024 + 1536 + 128;
__global__ void __launch_bounds__(256) lift_kernel(
        const float* __restrict__ x, const float* __restrict__ w0,
        const float* __restrict__ b0, float* __restrict__ out, float2* __restrict__ Y) {
    extern __shared__ unsigned char sm[];
    float2* cs2   = (float2*)sm;
    float2* orow2 = (float2*)(sm + 33024);
    float*  w0s   = (float*)(sm + 66048);
    float*  b0s   = (float*)(sm + 66048 + 1536);
    float*  orowf = (float*)orow2;

    int b = blockIdx.x >> 8, h = blockIdx.x & 255, tid = threadIdx.x;

    for (int k = tid; k < NM*NW; k += 256) { int ky=k>>8, w=k&255; cs2[ky*258+w] = g_cs[k]; }
    for (int k = tid; k < 384; k += 256) w0s[k] = w0[k];
    if (tid < 32) b0s[tid] = b0[tid];
    __syncthreads();

    int w = tid;
    const float* xp = x + (((b*NH) + h)*NW + w) * 10;
    float xv[10];
#pragma unroll
    for (int t = 0; t < 10; t++) xv[t] = xp[t];
    float gx = (float)h * (1.0f/255.0f);
    float gy = (float)w * (1.0f/255.0f);

    for (int c = 0; c < NC; c++) {
        float acc = b0s[c];
#pragma unroll
        for (int t = 0; t < 10; t++) acc = fmaf(xv[t], w0s[t*32 + c], acc);
        acc = fmaf(gx, w0s[10*32 + c], acc);
        acc = fmaf(gy, w0s[11*32 + c], acc);
        out[((b*NC + c)*NH + h)*NW + w] = acc;
        orowf[(c >> 1)*516 + 2*w + (c & 1)] = acc;
    }
    __syncthreads();
    dft_fold(orow2, tid);
    __syncthreads();
    fwd_dft_row3(orow2, cs2, Y, b, h, tid);
}

// ---------------- k2a: H-DFT  Y -> Z ----------------
static const int K2A_SM = 32768 + 65536;   // Ys, E1s
__global__ void __launch_bounds__(512, 2) k2a_kernel(
        const float2* __restrict__ Y, float2* __restrict__ Z) {
    extern __shared__ unsigned char sm[];
    float2* Ys  = (float2*)sm;             // [h][ky] 256*16
    float2* E1s = (float2*)(sm + 32768);   // [h][kx] 256*32

    int b = blockIdx.x >> 5, i = blockIdx.x & 31, tid = threadIdx.x;
    {
        const float4* src = (const float4*)(Y + (b*NC + i)*NH*NM);
        float4* dst = (float4*)Ys;
        for (int k = tid; k < 2048; k += 512) dst[k] = src[k];
        const float4* es = (const float4*)g_E1;
        float4* ed = (float4*)E1s;
        for (int k = tid; k < 4096; k += 512) ed[k] = es[k];
    }
    __syncthreads();

    int kx = tid >> 4, ky = tid & 15;
    float2 z = make_float2(0.f, 0.f);
#pragma unroll 4
    for (int h = 0; h < NH; h++) {
        float2 e = E1s[h*NKX + kx];
        float2 y = Ys[h*NM + ky];
        z = ffma2(make_float2(y.x, y.x), e, z);
        z = ffma2(make_float2(y.y, y.y), make_float2(-e.y, e.x), z);
    }
    Z[((b*NC + i)*NKX + kx)*NM + ky] = z;
}

// ---------------- k2bc: channel mix + inverse H-DFT, dual weight-set ----------------
// grid = 256 (single) or 512 (pair). sub = blockIdx.x >> 8 selects weight set.
__global__ void __launch_bounds__(256) k2bc_kernel(
        const float2* __restrict__ Z,
        const float* __restrict__ w1a, const float* __restrict__ w2a, float2* __restrict__ Ga,
        const float* __restrict__ w1b, const float* __restrict__ w2b, float2* __restrict__ Gb) {
    __shared__ float2 Ts[NKX*NM];          // [kx][ky] 32*16

    int sub = blockIdx.x >> 8, bid = blockIdx.x & 255;
    const float2* w1c = (const float2*)(sub ? w1b : w1a);
    const float2* w2c = (const float2*)(sub ? w2b : w2a);
    float2* G = sub ? Gb : Ga;

    int b = bid >> 5, o = bid & 31, tid = threadIdx.x;
    int ky = tid & 15, kxm = tid >> 4;     // kxm 0..15
    const float2* zb = Z + (size_t)b*NC*NKX*NM;

    float2 t1 = make_float2(0.f, 0.f);
    float2 t2 = make_float2(0.f, 0.f);
#pragma unroll 4
    for (int i = 0; i < NC; i++) {
        float2 z1 = zb[i*NKX*NM + kxm*NM + ky];
        float2 z2 = zb[i*NKX*NM + (kxm+16)*NM + ky];
        float2 wv1 = w1c[((i*32 + o)*16 + kxm)*16 + ky];
        float2 wv2 = w2c[((i*32 + o)*16 + kxm)*16 + ky];
        t1 = ffma2(make_float2(z1.x, z1.x), wv1, t1);
        t1 = ffma2(make_float2(z1.y, z1.y), make_float2(-wv1.y, wv1.x), t1);
        t2 = ffma2(make_float2(z2.x, z2.x), wv2, t2);
        t2 = ffma2(make_float2(z2.y, z2.y), make_float2(-wv2.y, wv2.x), t2);
    }
    Ts[kxm*16 + ky]      = t1;
    Ts[(kxm+16)*16 + ky] = t2;
    __syncthreads();

    // phase 2: inverse H-DFT, thread = h
    int h = tid;
    float2 acc[NM];
#pragma unroll
    for (int k = 0; k < NM; k++) acc[k] = make_float2(0.f, 0.f);
#pragma unroll 2
    for (int kx = 0; kx < NKX; kx++) {
        float2 e  = g_E2[kx*NH + h];
        float2 en = make_float2(-e.y, e.x);
#pragma unroll
        for (int k = 0; k < NM; k++) {
            float2 t = Ts[kx*16 + k];
            acc[k] = ffma2(make_float2(t.x, t.x), e,  acc[k]);
            acc[k] = ffma2(make_float2(t.y, t.y), en, acc[k]);
        }
    }
    float4* gp = (float4*)(G + ((b*NC + o)*NH + h)*NM);
    const float s2 = 2.0f / 65536.0f;
#pragma unroll
    for (int k = 0; k < 8; k++) {
        float s0 = (k == 0) ? (1.0f/65536.0f) : s2;
        gp[k] = make_float4(acc[2*k].x*s0, acc[2*k].y*s0, acc[2*k+1].x*s2, acc[2*k+1].y*s2);
    }
}

// ---------------- fused layer row kernel v4 ----------------
// Two channel-pair groups processed sequentially to keep regs < 128 (no spills).
// Supports running TWO independent layers in one launch (sub = blockIdx.x >> 11).
struct LArg {
    const float2* G;
    const float*  cw;
    const float*  cb;
    const float*  skip;   // nullptr = no skip
    float*        out;
    int           writeY; // 1 = compute forward W-DFT into Ynext
};

// smem: g4[0,4096) | cwq[4096,8192) | cb2[8192,8320) | cs2[8320,41344)
//       | orow2[41344,74368) | xrow[74368,107264)
static const int ROW_SM = 107264;
__global__ void __launch_bounds__(256, 2) layer_kernel(
        const float* __restrict__ xin0, const float* __restrict__ xin1,
        float2* __restrict__ Ynext, LArg a0, LArg a1) {
    extern __shared__ unsigned char sm[];
    float4* g4    = (float4*)sm;                 // [p][ky] 16*16
    float4* cwq   = (float4*)(sm + 4096);        // [c][p2] 32*8
    float2* cb2   = (float2*)(sm + 8192);        // 16
    float2* cs2   = (float2*)(sm + 8320);        // [ky][258]
    float2* orow2 = (float2*)(sm + 41344);       // [p][258]
    float*  xrow  = (float*)(sm + 74368);        // [c][257]

    int sub = blockIdx.x >> 11;
    int bid = blockIdx.x & 2047;
    const LArg la = sub ? a1 : a0;
    const float* xin = sub ? xin1 : xin0;

    int b = bid >> 8, h = bid & 255, tid = threadIdx.x;

    for (int k = tid; k < NM*NW; k += 256) { int ky=k>>8, ww=k&255; cs2[ky*258+ww] = g_cs[k]; }
    for (int c = 0; c < NC; c++) xrow[c*257 + tid] = xin[((b*NC + c)*NH + h)*NW + tid];
    {
        int c = tid >> 3, p2 = tid & 7;
        const float* cw = la.cw;
        cwq[tid] = make_float4(cw[(4*p2+0)*32+c], cw[(4*p2+1)*32+c],
                               cw[(4*p2+2)*32+c], cw[(4*p2+3)*32+c]);
    }
    if (tid < 16) cb2[tid] = make_float2(la.cb[2*tid], la.cb[2*tid+1]);
    {
        int p = tid >> 4, ky = tid & 15;
        float2 ga = la.G[((b*NC + 2*p    )*NH + h)*NM + ky];
        float2 gb = la.G[((b*NC + 2*p + 1)*NH + h)*NM + ky];
        g4[p*16 + ky] = make_float4(ga.x, gb.x, ga.y, gb.y);
    }
    __syncthreads();

    int wl = tid & 127, half = tid >> 7;

    float2 e_syn[NM];
#pragma unroll
    for (int ky = 0; ky < NM; ky++) e_syn[ky] = cs2[ky*258 + wl];

#pragma unroll 1
    for (int pg = 0; pg < 2; pg++) {             // 4 channel-pairs per group
        float2 ca[4], cbv[4], aP[4], aQ[4];
#pragma unroll
        for (int j = 0; j < 4; j++) {
            float2 bias = cb2[half*8 + pg*4 + j];
            ca[j] = bias; cbv[j] = bias;
            aP[j] = make_float2(0.f, 0.f);
            aQ[j] = make_float2(0.f, 0.f);
        }

        // 1x1 conv for both w positions (w = wl and wl+128)
#pragma unroll 4
        for (int c = 0; c < NC; c++) {
            float xa = xrow[c*257 + wl];
            float xb = xrow[c*257 + wl + 128];
            float2 xa2 = make_float2(xa, xa), xb2 = make_float2(xb, xb);
#pragma unroll
            for (int q2l = 0; q2l < 2; q2l++) {
                float4 w4 = cwq[c*8 + half*4 + pg*2 + q2l];
                ca [2*q2l    ] = ffma2(xa2, make_float2(w4.x, w4.y), ca [2*q2l    ]);
                ca [2*q2l + 1] = ffma2(xa2, make_float2(w4.z, w4.w), ca [2*q2l + 1]);
                cbv[2*q2l    ] = ffma2(xb2, make_float2(w4.x, w4.y), cbv[2*q2l    ]);
                cbv[2*q2l + 1] = ffma2(xb2, make_float2(w4.z, w4.w), cbv[2*q2l + 1]);
            }
        }

        // spectral synthesis: even-ky (P) / odd-ky (Q) partials; w+128 = P - Q
#pragma unroll
        for (int j = 0; j < 4; j++) {
            int p = half*8 + pg*4 + j;
#pragma unroll
            for (int ky = 0; ky < NM; ky++) {
                float4 g = g4[p*16 + ky];
                float2 e = e_syn[ky];
                if ((ky & 1) == 0) {
                    aP[j] = ffma2(make_float2(g.x, g.y), make_float2(e.x, e.x),   aP[j]);
                    aP[j] = ffma2(make_float2(g.z, g.w), make_float2(-e.y, -e.y), aP[j]);
                } else {
                    aQ[j] = ffma2(make_float2(g.x, g.y), make_float2(e.x, e.x),   aQ[j]);
                    aQ[j] = ffma2(make_float2(g.z, g.w), make_float2(-e.y, -e.y), aQ[j]);
                }
            }
        }

        // epilogue
#pragma unroll
        for (int j = 0; j < 4; j++) {
            int p = half*8 + pg*4 + j;
            float sa0 = ca[j].x + (aP[j].x + aQ[j].x);
            float sa1 = ca[j].y + (aP[j].y + aQ[j].y);
            float sb0 = cbv[j].x + (aP[j].x - aQ[j].x);
            float sb1 = cbv[j].y + (aP[j].y - aQ[j].y);
            float v0a = gelu_f(sa0), v1a = gelu_f(sa1);
            float v0b = gelu_f(sb0), v1b = gelu_f(sb1);
            int i0 = ((b*NC + 2*p)*NH + h)*NW + wl;
            int i1 = i0 + NH*NW;
            if (la.skip) {
                v0a += la.skip[i0];  v0b += la.skip[i0 + 128];
                v1a += la.skip[i1];  v1b += la.skip[i1 + 128];
            }
            la.out[i0] = v0a; la.out[i0 + 128] = v0b;
            la.out[i1] = v1a; la.out[i1 + 128] = v1b;
            if (la.writeY) {
                orow2[p*258 + wl]       = make_float2(v0a + v0b, v1a + v1b);
                orow2[p*258 + 128 + wl] = make_float2(v0a - v0b, v1a - v1b);
            }
        }
    }
    if (la.writeY) {
        __syncthreads();
        fwd_dft_row3(orow2, cs2, Ynext, b, h, tid);
    }
}

// ---------------- head: fc1 + GELU + fc2 ----------------
static const int HEAD_SM = 52896;
__global__ void __launch_bounds__(256, 3) head_kernel(
        const float* __restrict__ xin, const float* __restrict__ w1,
        const float* __restrict__ b1, const float* __restrict__ w2,
        const float* __restrict__ b2, float* __restrict__ out) {
    extern __shared__ unsigned char sm[];
    float*  w1s  = (float*)sm;                 // [c][128]
    float*  xrow = (float*)(sm + 16384);       // [c][257]
    float*  b1s  = (float*)(sm + 49280);       // 128
    float2* w2p  = (float2*)(sm + 49792);      // [j][3]
    float*  b2s  = (float*)(sm + 52864);       // 5

    int b = blockIdx.x >> 8, h = blockIdx.x & 255, tid = threadIdx.x;
    for (int c = 0; c < NC; c++) xrow[c*257 + tid] = xin[((b*NC + c)*NH + h)*NW + tid];
    for (int k = tid; k < 4096; k += 256) w1s[k] = w1[k];
    if (tid < 128) {
        b1s[tid] = b1[tid];
        w2p[tid*3 + 0] = make_float2(w2[tid*5 + 0], w2[tid*5 + 1]);
        w2p[tid*3 + 1] = make_float2(w2[tid*5 + 2], w2[tid*5 + 3]);
        w2p[tid*3 + 2] = make_float2(w2[tid*5 + 4], 0.0f);
    }
    if (tid < 5) b2s[tid] = b2[tid];
    __syncthreads();

    int w = tid;
    float2 o01 = make_float2(b2s[0], b2s[1]);
    float2 o23 = make_float2(b2s[2], b2s[3]);
    float2 o4z = make_float2(b2s[4], 0.0f);
    const float4* w1q = (const float4*)w1s;
    const float2* b1p = (const float2*)b1s;

#pragma unroll 1
    for (int q = 0; q < 4; q++) {
        float2 acc[16];
#pragma unroll
        for (int jj = 0; jj < 16; jj++) acc[jj] = b1p[q*16 + jj];
#pragma unroll 4
        for (int c = 0; c < NC; c++) {
            float xv = xrow[c*257 + w];
            float2 xv2 = make_float2(xv, xv);
#pragma unroll
            for (int j8 = 0; j8 < 8; j8++) {
                float4 w4 = w1q[c*32 + q*8 + j8];
                acc[2*j8    ] = ffma2(xv2, make_float2(w4.x, w4.y), acc[2*j8    ]);
                acc[2*j8 + 1] = ffma2(xv2, make_float2(w4.z, w4.w), acc[2*j8 + 1]);
            }
        }
#pragma unroll
        for (int jj = 0; jj < 16; jj++) {
            int j = 32*q + 2*jj;
            float h0 = gelu_f(acc[jj].x);
            float h1 = gelu_f(acc[jj].y);
            float2 h02 = make_float2(h0, h0), h12 = make_float2(h1, h1);
            o01 = ffma2(h02, w2p[j*3 + 0], o01);
            o23 = ffma2(h02, w2p[j*3 + 1], o23);
            o4z = ffma2(h02, w2p[j*3 + 2], o4z);
            o01 = ffma2(h12, w2p[(j+1)*3 + 0], o01);
            o23 = ffma2(h12, w2p[(j+1)*3 + 1], o23);
            o4z = ffma2(h12, w2p[(j+1)*3 + 2], o4z);
        }
    }
    float* op = out + (((b*NH) + h)*NW + w) * 5;
    op[0] = o01.x; op[1] = o01.y; op[2] = o23.x; op[3] = o23.y; op[4] = o4z.x;
}

// ---------------- host launcher ----------------
extern "C" void kernel_launch(void* const* d_in, const int* in_sizes, int n_in,
                              void* d_out, int out_size) {
    const float* x     = (const float*)d_in[0];
    const float* fc0w  = (const float*)d_in[1];
    const float* fc0b  = (const float*)d_in[2];
    const float* w1    = (const float*)d_in[3];
    const float* w2    = (const float*)d_in[4];
    const float* convw = (const float*)d_in[5];
    const float* convb = (const float*)d_in[6];
    const float* fc1w  = (const float*)d_in[7];
    const float* fc1b  = (const float*)d_in[8];
    const float* fc2w  = (const float*)d_in[9];
    const float* fc2b  = (const float*)d_in[10];
    float* out = (float*)d_out;

    float  *bufA, *bufB, *bufC;
    float2 *Y, *Z, *G0, *G1;
    cudaGetSymbolAddress((void**)&bufA, g_bufA);
    cudaGetSymbolAddress((void**)&bufB, g_bufB);
    cudaGetSymbolAddress((void**)&bufC, g_bufC);
    cudaGetSymbolAddress((void**)&Y, g_Y);
    cudaGetSymbolAddress((void**)&Z, g_Zb);
    cudaGetSymbolAddress((void**)&G0, g_G);
    cudaGetSymbolAddress((void**)&G1, g_G2);

    cudaFuncSetAttribute(lift_kernel,  cudaFuncAttributeMaxDynamicSharedMemorySize, LIFT_SM);
    cudaFuncSetAttribute(k2a_kernel,   cudaFuncAttributeMaxDynamicSharedMemorySize, K2A_SM);
    cudaFuncSetAttribute(head_kernel,  cudaFuncAttributeMaxDynamicSharedMemorySize, HEAD_SM);
    cudaFuncSetAttribute(layer_kernel, cudaFuncAttributeMaxDynamicSharedMemorySize, ROW_SM);

    const float* w1p[6]; const float* w2p_[6]; const float* cwp[6]; const float* cbp[6];
    for (int l = 0; l < 6; l++) {
        w1p[l]  = w1 + (size_t)l * WSZ;
        w2p_[l] = w2 + (size_t)l * WSZ;
        cwp[l]  = convw + l * 32 * 32;
        cbp[l]  = convb + l * 32;
    }

    init_tables<<<64, 256>>>();
    lift_kernel<<<NB*NH, 256, LIFT_SM>>>(x, fc0w, fc0b, bufA, Y);   // A = lift, Y = Y_lift

    // DAG:  h0 = L0(lift); t1 = L1(lift); t2 = L2(t1) + h0;
    //       h1 = L3(t2);   t4 = L4(t2);   out = L5(t4) + h1;
    // Z (H-DFT of Y) is weight-independent -> shared by L0/L1 and by L3/L4.

    // --- L0 + L1 (paired) ---
    k2a_kernel<<<NB*NC, 512, K2A_SM>>>(Y, Z);
    k2bc_kernel<<<2*NB*NC, 256>>>(Z, w1p[0], w2p_[0], G0, w1p[1], w2p_[1], G1);
    {
        LArg a0 = { G0, cwp[0], cbp[0], nullptr, bufB, 0 };   // h0
        LArg a1 = { G1, cwp[1], cbp[1], nullptr, bufC, 1 };   // t1 (+Y_t1)
        layer_kernel<<<2*NB*NH, 256, ROW_SM>>>(bufA, bufA, Y, a0, a1);
    }

    // --- L2 ---
    k2a_kernel<<<NB*NC, 512, K2A_SM>>>(Y, Z);
    k2bc_kernel<<<NB*NC, 256>>>(Z, w1p[2], w2p_[2], G0, w1p[2], w2p_[2], G0);
    {
        LArg a = { G0, cwp[2], cbp[2], bufB, bufA, 1 };       // t2 (+Y_t2)
        layer_kernel<<<NB*NH, 256, ROW_SM>>>(bufC, bufC, Y, a, a);
    }

    // --- L3 + L4 (paired) ---
    k2a_kernel<<<NB*NC, 512, K2A_SM>>>(Y, Z);
    k2bc_kernel<<<2*NB*NC, 256>>>(Z, w1p[3], w2p_[3], G0, w1p[4], w2p_[4], G1);
    {
        LArg a0 = { G0, cwp[3], cbp[3], nullptr, bufB, 0 };   // h1
        LArg a1 = { G1, cwp[4], cbp[4], nullptr, bufC, 1 };   // t4 (+Y_t4)
        layer_kernel<<<2*NB*NH, 256, ROW_SM>>>(bufA, bufA, Y, a0, a1);
    }

    // --- L5 ---
    k2a_kernel<<<NB*NC, 512, K2A_SM>>>(Y, Z);
    k2bc_kernel<<<NB*NC, 256>>>(Z, w1p[5], w2p_[5], G0, w1p[5], w2p_[5], G0);
    {
        LArg a = { G0, cwp[5], cbp[5], bufB, bufA, 0 };       // final
        layer_kernel<<<NB*NH, 256, ROW_SM>>>(bufC, bufC, Y, a, a);
    }

    head_kernel<<<NB*NH, 256, HEAD_SM>>>(bufA, fc1w, fc1b, fc2w, fc2b, out);
}

// round 9
// speedup vs baseline: 1.5926x; 1.0314x over previous
#include <cuda_runtime.h>
#include <math.h>

// ---------------- problem constants ----------------
#define NB 8
#define NC 32
#define NH 256
#define NW 256
#define NM 16            // modes M1 = M2 = 16
#define NKX 32           // 16 top rows + 16 bottom rows
#define WSZ (32*32*16*16*2)   // per-layer w1/w2 float count

// ---------------- device scratch ----------------
__device__ float  g_bufA[NB*NC*NH*NW];
__device__ float  g_bufB[NB*NC*NH*NW];
__device__ float  g_bufC[NB*NC*NH*NW];
__device__ float2 g_Y[NB*NC*NH*NM];      // [b][c][h][ky]
__device__ float2 g_Zb[NB*NC*NKX*NM];    // [b][i][kx][ky]
__device__ float2 g_G[NB*NC*NH*NM];      // [b][o][h][ky]
__device__ float2 g_G2[NB*NC*NH*NM];     // second G for paired layers

// ---------------- helpers ----------------
__device__ __forceinline__ float2 ffma2(float2 a, float2 b, float2 c) {
    float2 d;
    asm("fma.rn.f32x2 %0, %1, %2, %3;"
        : "=l"(reinterpret_cast<unsigned long long&>(d))
        : "l"(reinterpret_cast<unsigned long long&>(a)),
          "l"(reinterpret_cast<unsigned long long&>(b)),
          "l"(reinterpret_cast<unsigned long long&>(c)));
    return d;
}

// e^{i*2*pi*m/256} for any integer m (two's-complement & handles negatives)
__device__ __forceinline__ float2 cis_m(int m) {
    float a = (float)(m & 255) * (1.0f/128.0f);
    return make_float2(cospif(a), sinpif(a));
}

// branch-free GELU, exact-erf form via Abramowitz-Stegun 7.1.26 (|err_erf| < 1.5e-7)
__device__ __forceinline__ float gelu_f(float v) {
    float u = fabsf(v) * 0.7071067811865476f;
    float t = __frcp_rn(fmaf(0.3275911f, u, 1.0f));
    float p = t * fmaf(t, fmaf(t, fmaf(t, fmaf(t, 1.061405429f, -1.453152027f),
                                       1.421413741f), -0.284496736f), 0.254829592f);
    float e = __expf(-u * u);
    float erf_abs = fmaf(-p, e, 1.0f);           // erf(|u|)
    float erfv = copysignf(erf_abs, v);
    return 0.5f * v * (1.0f + erfv);
}

// ---------------- folded forward partial W-DFT ----------------
// orow2: float2[16][258], pair p holds channels (2p,2p+1).
// After folding: [p][w<128] = o(w)+o(w+128), [p][128+w] = o(w)-o(w+128).
// cs2: float2[16][130], only w<128 used.
__device__ __forceinline__ void fwd_dft_row3(const float2* orow2, const float2* cs2,
                                             float2* __restrict__ Y, int b, int h, int tid) {
    int q  = tid >> 4;       // channel-pair 0..15
    int ky = tid & 15;
    float2 yr = make_float2(0.f, 0.f);
    float2 yi = make_float2(0.f, 0.f);
    const float4* op = (const float4*)(orow2 + q*258 + ((ky & 1) ? 128 : 0));
    const float4* ep = (const float4*)(cs2  + ky*130);
#pragma unroll 8
    for (int w2 = 0; w2 < 64; w2++) {
        float4 o4 = op[w2];
        float4 e4 = ep[w2];
        yr = ffma2(make_float2(o4.x, o4.y), make_float2(e4.x,  e4.x), yr);
        yi = ffma2(make_float2(o4.x, o4.y), make_float2(-e4.y, -e4.y), yi);
        yr = ffma2(make_float2(o4.z, o4.w), make_float2(e4.z,  e4.z), yr);
        yi = ffma2(make_float2(o4.z, o4.w), make_float2(-e4.w, -e4.w), yi);
    }
    Y[((b*NC + 2*q    )*NH + h)*NM + ky] = make_float2(yr.x, yi.x);
    Y[((b*NC + 2*q + 1)*NH + h)*NM + ky] = make_float2(yr.y, yi.y);
}

// generate the [16][130] forward twiddle table (w<128) in-block (256 threads)
__device__ __forceinline__ void gen_cs2(float2* cs2, int tid) {
#pragma unroll
    for (int k = tid; k < 2048; k += 256) {
        int ky = k >> 7, w = k & 127;
        cs2[ky*130 + w] = cis_m(ky * w);
    }
}

// ---------------- lift ----------------
// smem: cs2[0,16640) | orow2[16640,49664) | w0s | b0s
static const int LIFT_SM = 16640 + 33024 + 1536 + 128;
__global__ void __launch_bounds__(256) lift_kernel(
        const float* __restrict__ x, const float* __restrict__ w0,
        const float* __restrict__ b0, float* __restrict__ out, float2* __restrict__ Y) {
    extern __shared__ unsigned char sm[];
    float2* cs2   = (float2*)sm;
    float2* orow2 = (float2*)(sm + 16640);
    float*  w0s   = (float*)(sm + 49664);
    float*  b0s   = (float*)(sm + 49664 + 1536);
    float*  orowf = (float*)orow2;

    int b = blockIdx.x >> 8, h = blockIdx.x & 255, tid = threadIdx.x;

    gen_cs2(cs2, tid);
    for (int k = tid; k < 384; k += 256) w0s[k] = w0[k];
    if (tid < 32) b0s[tid] = b0[tid];
    __syncthreads();

    int w = tid;
    const float* xp = x + (((b*NH) + h)*NW + w) * 10;
    float xv[10];
#pragma unroll
    for (int t = 0; t < 10; t++) xv[t] = xp[t];
    float gx = (float)h * (1.0f/255.0f);
    float gy = (float)w * (1.0f/255.0f);

    for (int c = 0; c < NC; c++) {
        float acc = b0s[c];
#pragma unroll
        for (int t = 0; t < 10; t++) acc = fmaf(xv[t], w0s[t*32 + c], acc);
        acc = fmaf(gx, w0s[10*32 + c], acc);
        acc = fmaf(gy, w0s[11*32 + c], acc);
        out[((b*NC + c)*NH + h)*NW + w] = acc;
        orowf[(c >> 1)*516 + 2*w + (c & 1)] = acc;
    }
    __syncthreads();
    // fold w / w+128
    {
        int wl = tid & 127, half = tid >> 7;
#pragma unroll
        for (int pp = 0; pp < 8; pp++) {
            int p = half*8 + pp;
            float2 a = orow2[p*258 + wl];
            float2 c = orow2[p*258 + 128 + wl];
            orow2[p*258 + wl]       = make_float2(a.x + c.x, a.y + c.y);
            orow2[p*258 + 128 + wl] = make_float2(a.x - c.x, a.y - c.y);
        }
    }
    __syncthreads();
    fwd_dft_row3(orow2, cs2, Y, b, h, tid);
}

// ---------------- k2a: H-DFT  Y -> Z ----------------
static const int K2A_SM = 32768 + 65536;   // Ys, E1s
__global__ void __launch_bounds__(512, 2) k2a_kernel(
        const float2* __restrict__ Y, float2* __restrict__ Z) {
    extern __shared__ unsigned char sm[];
    float2* Ys  = (float2*)sm;             // [h][ky] 256*16
    float2* E1s = (float2*)(sm + 32768);   // [h][kx] 256*32

    int b = blockIdx.x >> 5, i = blockIdx.x & 31, tid = threadIdx.x;
    {
        const float4* src = (const float4*)(Y + (b*NC + i)*NH*NM);
        float4* dst = (float4*)Ys;
        for (int k = tid; k < 2048; k += 512) dst[k] = src[k];
    }
#pragma unroll
    for (int k = tid; k < NH*NKX; k += 512) {
        int h = k >> 5, kx = k & 31;
        int fr = (kx < 16) ? kx : (kx - 32);
        float2 e = cis_m(fr * h);
        E1s[k] = make_float2(e.x, -e.y);   // e^{-i phi}
    }
    __syncthreads();

    int kx = tid >> 4, ky = tid & 15;
    float2 z = make_float2(0.f, 0.f);
#pragma unroll 4
    for (int h = 0; h < NH; h++) {
        float2 e = E1s[h*NKX + kx];
        float2 y = Ys[h*NM + ky];
        z = ffma2(make_float2(y.x, y.x), e, z);
        z = ffma2(make_float2(y.y, y.y), make_float2(-e.y, e.x), z);
    }
    Z[((b*NC + i)*NKX + kx)*NM + ky] = z;
}

// ---------------- k2bc: channel mix + inverse H-DFT, dual weight-set ----------------
// grid = 256 (single) or 512 (pair). sub = blockIdx.x >> 8 selects weight set.
__global__ void __launch_bounds__(256) k2bc_kernel(
        const float2* __restrict__ Z,
        const float* __restrict__ w1a, const float* __restrict__ w2a, float2* __restrict__ Ga,
        const float* __restrict__ w1b, const float* __restrict__ w2b, float2* __restrict__ Gb) {
    __shared__ float2 Ts[NKX*NM];          // [kx][ky] 32*16

    int sub = blockIdx.x >> 8, bid = blockIdx.x & 255;
    const float2* w1c = (const float2*)(sub ? w1b : w1a);
    const float2* w2c = (const float2*)(sub ? w2b : w2a);
    float2* G = sub ? Gb : Ga;

    int b = bid >> 5, o = bid & 31, tid = threadIdx.x;
    int ky = tid & 15, kxm = tid >> 4;     // kxm 0..15
    const float2* zb = Z + (size_t)b*NC*NKX*NM;

    float2 t1 = make_float2(0.f, 0.f);
    float2 t2 = make_float2(0.f, 0.f);
#pragma unroll 4
    for (int i = 0; i < NC; i++) {
        float2 z1 = zb[i*NKX*NM + kxm*NM + ky];
        float2 z2 = zb[i*NKX*NM + (kxm+16)*NM + ky];
        float2 wv1 = w1c[((i*32 + o)*16 + kxm)*16 + ky];
        float2 wv2 = w2c[((i*32 + o)*16 + kxm)*16 + ky];
        t1 = ffma2(make_float2(z1.x, z1.x), wv1, t1);
        t1 = ffma2(make_float2(z1.y, z1.y), make_float2(-wv1.y, wv1.x), t1);
        t2 = ffma2(make_float2(z2.x, z2.x), wv2, t2);
        t2 = ffma2(make_float2(z2.y, z2.y), make_float2(-wv2.y, wv2.x), t2);
    }
    Ts[kxm*16 + ky]      = t1;
    Ts[(kxm+16)*16 + ky] = t2;
    __syncthreads();

    // phase 2: inverse H-DFT, thread = h; twiddles computed on the fly
    int h = tid;
    float2 acc[NM];
#pragma unroll
    for (int k = 0; k < NM; k++) acc[k] = make_float2(0.f, 0.f);
#pragma unroll 2
    for (int kx = 0; kx < NKX; kx++) {
        int fr = (kx < 16) ? kx : (kx - 32);
        float2 e = cis_m(fr * h);          // e^{+i phi}
        float2 en = make_float2(-e.y, e.x);
#pragma unroll
        for (int k = 0; k < NM; k++) {
            float2 t = Ts[kx*16 + k];
            acc[k] = ffma2(make_float2(t.x, t.x), e,  acc[k]);
            acc[k] = ffma2(make_float2(t.y, t.y), en, acc[k]);
        }
    }
    float4* gp = (float4*)(G + ((b*NC + o)*NH + h)*NM);
    const float s2 = 2.0f / 65536.0f;
#pragma unroll
    for (int k = 0; k < 8; k++) {
        float s0 = (k == 0) ? (1.0f/65536.0f) : s2;
        gp[k] = make_float4(acc[2*k].x*s0, acc[2*k].y*s0, acc[2*k+1].x*s2, acc[2*k+1].y*s2);
    }
}

// ---------------- fused layer row kernel v5 ----------------
struct LArg {
    const float2* G;
    const float*  cw;
    const float*  cb;
    const float*  skip;   // nullptr = no skip
    float*        out;
    int           writeY; // 1 = compute forward W-DFT into Ynext
};

// smem: g4[0,4096) | cwq[4096,8192) | cb2[8192,8320) | cs2[8320,24960)
//       | orow2[24960,57984) | xrow[57984,90880)
static const int ROW_SM = 90880;
__global__ void __launch_bounds__(256, 2) layer_kernel(
        const float* __restrict__ xin0, const float* __restrict__ xin1,
        float2* __restrict__ Ynext, LArg a0, LArg a1) {
    extern __shared__ unsigned char sm[];
    float4* g4    = (float4*)sm;                 // [p][ky] 16*16
    float4* cwq   = (float4*)(sm + 4096);        // [c][p2] 32*8
    float2* cb2   = (float2*)(sm + 8192);        // 16
    float2* cs2   = (float2*)(sm + 8320);        // [ky][130], w<128
    float2* orow2 = (float2*)(sm + 24960);       // [p][258]
    float*  xrow  = (float*)(sm + 57984);        // [c][257]

    int sub = blockIdx.x >> 11;
    int bid = blockIdx.x & 2047;
    const LArg la = sub ? a1 : a0;
    const float* xin = sub ? xin1 : xin0;

    int b = bid >> 8, h = bid & 255, tid = threadIdx.x;

    gen_cs2(cs2, tid);
    for (int c = 0; c < NC; c++) xrow[c*257 + tid] = xin[((b*NC + c)*NH + h)*NW + tid];
    {
        int c = tid >> 3, p2 = tid & 7;
        const float* cw = la.cw;
        cwq[tid] = make_float4(cw[(4*p2+0)*32+c], cw[(4*p2+1)*32+c],
                               cw[(4*p2+2)*32+c], cw[(4*p2+3)*32+c]);
    }
    if (tid < 16) cb2[tid] = make_float2(la.cb[2*tid], la.cb[2*tid+1]);
    {
        int p = tid >> 4, ky = tid & 15;
        float2 ga = la.G[((b*NC + 2*p    )*NH + h)*NM + ky];
        float2 gb = la.G[((b*NC + 2*p + 1)*NH + h)*NM + ky];
        g4[p*16 + ky] = make_float4(ga.x, gb.x, ga.y, gb.y);
    }
    __syncthreads();

    int wl = tid & 127, half = tid >> 7;

    float2 e_syn[NM];
#pragma unroll
    for (int ky = 0; ky < NM; ky++) e_syn[ky] = cs2[ky*130 + wl];

#pragma unroll 1
    for (int pg = 0; pg < 2; pg++) {             // 4 channel-pairs per group
        float2 ca[4], cbv[4], aP[4], aQ[4];
#pragma unroll
        for (int j = 0; j < 4; j++) {
            float2 bias = cb2[half*8 + pg*4 + j];
            ca[j] = bias; cbv[j] = bias;
            aP[j] = make_float2(0.f, 0.f);
            aQ[j] = make_float2(0.f, 0.f);
        }

        // 1x1 conv for both w positions (w = wl and wl+128)
#pragma unroll 4
        for (int c = 0; c < NC; c++) {
            float xa = xrow[c*257 + wl];
            float xb = xrow[c*257 + wl + 128];
            float2 xa2 = make_float2(xa, xa), xb2 = make_float2(xb, xb);
#pragma unroll
            for (int q2l = 0; q2l < 2; q2l++) {
                float4 w4 = cwq[c*8 + half*4 + pg*2 + q2l];
                ca [2*q2l    ] = ffma2(xa2, make_float2(w4.x, w4.y), ca [2*q2l    ]);
                ca [2*q2l + 1] = ffma2(xa2, make_float2(w4.z, w4.w), ca [2*q2l + 1]);
                cbv[2*q2l    ] = ffma2(xb2, make_float2(w4.x, w4.y), cbv[2*q2l    ]);
                cbv[2*q2l + 1] = ffma2(xb2, make_float2(w4.z, w4.w), cbv[2*q2l + 1]);
            }
        }

        // spectral synthesis: even-ky (P) / odd-ky (Q) partials; w+128 = P - Q
#pragma unroll
        for (int j = 0; j < 4; j++) {
            int p = half*8 + pg*4 + j;
#pragma unroll
            for (int ky = 0; ky < NM; ky++) {
                float4 g = g4[p*16 + ky];
                float2 e = e_syn[ky];
                if ((ky & 1) == 0) {
                    aP[j] = ffma2(make_float2(g.x, g.y), make_float2(e.x, e.x),   aP[j]);
                    aP[j] = ffma2(make_float2(g.z, g.w), make_float2(-e.y, -e.y), aP[j]);
                } else {
                    aQ[j] = ffma2(make_float2(g.x, g.y), make_float2(e.x, e.x),   aQ[j]);
                    aQ[j] = ffma2(make_float2(g.z, g.w), make_float2(-e.y, -e.y), aQ[j]);
                }
            }
        }

        // epilogue
#pragma unroll
        for (int j = 0; j < 4; j++) {
            int p = half*8 + pg*4 + j;
            float sa0 = ca[j].x + (aP[j].x + aQ[j].x);
            float sa1 = ca[j].y + (aP[j].y + aQ[j].y);
            float sb0 = cbv[j].x + (aP[j].x - aQ[j].x);
            float sb1 = cbv[j].y + (aP[j].y - aQ[j].y);
            float v0a = gelu_f(sa0), v1a = gelu_f(sa1);
            float v0b = gelu_f(sb0), v1b = gelu_f(sb1);
            int i0 = ((b*NC + 2*p)*NH + h)*NW + wl;
            int i1 = i0 + NH*NW;
            if (la.skip) {
                v0a += la.skip[i0];  v0b += la.skip[i0 + 128];
                v1a += la.skip[i1];  v1b += la.skip[i1 + 128];
            }
            la.out[i0] = v0a; la.out[i0 + 128] = v0b;
            la.out[i1] = v1a; la.out[i1 + 128] = v1b;
            if (la.writeY) {
                orow2[p*258 + wl]       = make_float2(v0a + v0b, v1a + v1b);
                orow2[p*258 + 128 + wl] = make_float2(v0a - v0b, v1a - v1b);
            }
        }
    }
    if (la.writeY) {
        __syncthreads();
        fwd_dft_row3(orow2, cs2, Ynext, b, h, tid);
    }
}

// ---------------- head: fc1 + GELU + fc2 ----------------
static const int HEAD_SM = 52896;
__global__ void __launch_bounds__(256, 3) head_kernel(
        const float* __restrict__ xin, const float* __restrict__ w1,
        const float* __restrict__ b1, const float* __restrict__ w2,
        const float* __restrict__ b2, float* __restrict__ out) {
    extern __shared__ unsigned char sm[];
    float*  w1s  = (float*)sm;                 // [c][128]
    float*  xrow = (float*)(sm + 16384);       // [c][257]
    float*  b1s  = (float*)(sm + 49280);       // 128
    float2* w2p  = (float2*)(sm + 49792);      // [j][3]
    float*  b2s  = (float*)(sm + 52864);       // 5

    int b = blockIdx.x >> 8, h = blockIdx.x & 255, tid = threadIdx.x;
    for (int c = 0; c < NC; c++) xrow[c*257 + tid] = xin[((b*NC + c)*NH + h)*NW + tid];
    for (int k = tid; k < 4096; k += 256) w1s[k] = w1[k];
    if (tid < 128) {
        b1s[tid] = b1[tid];
        w2p[tid*3 + 0] = make_float2(w2[tid*5 + 0], w2[tid*5 + 1]);
        w2p[tid*3 + 1] = make_float2(w2[tid*5 + 2], w2[tid*5 + 3]);
        w2p[tid*3 + 2] = make_float2(w2[tid*5 + 4], 0.0f);
    }
    if (tid < 5) b2s[tid] = b2[tid];
    __syncthreads();

    int w = tid;
    float2 o01 = make_float2(b2s[0], b2s[1]);
    float2 o23 = make_float2(b2s[2], b2s[3]);
    float2 o4z = make_float2(b2s[4], 0.0f);
    const float4* w1q = (const float4*)w1s;
    const float2* b1p = (const float2*)b1s;

#pragma unroll 1
    for (int q = 0; q < 4; q++) {
        float2 acc[16];
#pragma unroll
        for (int jj = 0; jj < 16; jj++) acc[jj] = b1p[q*16 + jj];
#pragma unroll 4
        for (int c = 0; c < NC; c++) {
            float xv = xrow[c*257 + w];
            float2 xv2 = make_float2(xv, xv);
#pragma unroll
            for (int j8 = 0; j8 < 8; j8++) {
                float4 w4 = w1q[c*32 + q*8 + j8];
                acc[2*j8    ] = ffma2(xv2, make_float2(w4.x, w4.y), acc[2*j8    ]);
                acc[2*j8 + 1] = ffma2(xv2, make_float2(w4.z, w4.w), acc[2*j8 + 1]);
            }
        }
#pragma unroll
        for (int jj = 0; jj < 16; jj++) {
            int j = 32*q + 2*jj;
            float h0 = gelu_f(acc[jj].x);
            float h1 = gelu_f(acc[jj].y);
            float2 h02 = make_float2(h0, h0), h12 = make_float2(h1, h1);
            o01 = ffma2(h02, w2p[j*3 + 0], o01);
            o23 = ffma2(h02, w2p[j*3 + 1], o23);
            o4z = ffma2(h02, w2p[j*3 + 2], o4z);
            o01 = ffma2(h12, w2p[(j+1)*3 + 0], o01);
            o23 = ffma2(h12, w2p[(j+1)*3 + 1], o23);
            o4z = ffma2(h12, w2p[(j+1)*3 + 2], o4z);
        }
    }
    float* op = out + (((b*NH) + h)*NW + w) * 5;
    op[0] = o01.x; op[1] = o01.y; op[2] = o23.x; op[3] = o23.y; op[4] = o4z.x;
}

// ---------------- host launcher ----------------
extern "C" void kernel_launch(void* const* d_in, const int* in_sizes, int n_in,
                              void* d_out, int out_size) {
    const float* x     = (const float*)d_in[0];
    const float* fc0w  = (const float*)d_in[1];
    const float* fc0b  = (const float*)d_in[2];
    const float* w1    = (const float*)d_in[3];
    const float* w2    = (const float*)d_in[4];
    const float* convw = (const float*)d_in[5];
    const float* convb = (const float*)d_in[6];
    const float* fc1w  = (const float*)d_in[7];
    const float* fc1b  = (const float*)d_in[8];
    const float* fc2w  = (const float*)d_in[9];
    const float* fc2b  = (const float*)d_in[10];
    float* out = (float*)d_out;

    float  *bufA, *bufB, *bufC;
    float2 *Y, *Z, *G0, *G1;
    cudaGetSymbolAddress((void**)&bufA, g_bufA);
    cudaGetSymbolAddress((void**)&bufB, g_bufB);
    cudaGetSymbolAddress((void**)&bufC, g_bufC);
    cudaGetSymbolAddress((void**)&Y, g_Y);
    cudaGetSymbolAddress((void**)&Z, g_Zb);
    cudaGetSymbolAddress((void**)&G0, g_G);
    cudaGetSymbolAddress((void**)&G1, g_G2);

    cudaFuncSetAttribute(lift_kernel,  cudaFuncAttributeMaxDynamicSharedMemorySize, LIFT_SM);
    cudaFuncSetAttribute(k2a_kernel,   cudaFuncAttributeMaxDynamicSharedMemorySize, K2A_SM);
    cudaFuncSetAttribute(head_kernel,  cudaFuncAttributeMaxDynamicSharedMemorySize, HEAD_SM);
    cudaFuncSetAttribute(layer_kernel, cudaFuncAttributeMaxDynamicSharedMemorySize, ROW_SM);

    const float* w1p[6]; const float* w2p_[6]; const float* cwp[6]; const float* cbp[6];
    for (int l = 0; l < 6; l++) {
        w1p[l]  = w1 + (size_t)l * WSZ;
        w2p_[l] = w2 + (size_t)l * WSZ;
        cwp[l]  = convw + l * 32 * 32;
        cbp[l]  = convb + l * 32;
    }

    // DAG:  h0 = L0(lift); t1 = L1(lift); t2 = L2(t1) + h0;
    //       h1 = L3(t2);   t4 = L4(t2);   out = L5(t4) + h1;
    // Z (H-DFT of Y) is weight-independent -> shared by L0/L1 and by L3/L4.
    // Launch order puts the dual layer kernel at index 3 (the ncu-profiled slot).

    lift_kernel<<<NB*NH, 256, LIFT_SM>>>(x, fc0w, fc0b, bufA, Y);   // (0) A = lift, Y_lift

    // --- L0 + L1 (paired) ---
    k2a_kernel<<<NB*NC, 512, K2A_SM>>>(Y, Z);                                           // (1)
    k2bc_kernel<<<2*NB*NC, 256>>>(Z, w1p[0], w2p_[0], G0, w1p[1], w2p_[1], G1);         // (2)
    {
        LArg a0 = { G0, cwp[0], cbp[0], nullptr, bufB, 0 };   // h0
        LArg a1 = { G1, cwp[1], cbp[1], nullptr, bufC, 1 };   // t1 (+Y_t1)
        layer_kernel<<<2*NB*NH, 256, ROW_SM>>>(bufA, bufA, Y, a0, a1);                  // (3) <- profiled
    }

    // --- L2 ---
    k2a_kernel<<<NB*NC, 512, K2A_SM>>>(Y, Z);
    k2bc_kernel<<<NB*NC, 256>>>(Z, w1p[2], w2p_[2], G0, w1p[2], w2p_[2], G0);
    {
        LArg a = { G0, cwp[2], cbp[2], bufB, bufA, 1 };       // t2 (+Y_t2)
        layer_kernel<<<NB*NH, 256, ROW_SM>>>(bufC, bufC, Y, a, a);
    }

    // --- L3 + L4 (paired) ---
    k2a_kernel<<<NB*NC, 512, K2A_SM>>>(Y, Z);
    k2bc_kernel<<<2*NB*NC, 256>>>(Z, w1p[3], w2p_[3], G0, w1p[4], w2p_[4], G1);
    {
        LArg a0 = { G0, cwp[3], cbp[3], nullptr, bufB, 0 };   // h1
        LArg a1 = { G1, cwp[4], cbp[4], nullptr, bufC, 1 };   // t4 (+Y_t4)
        layer_kernel<<<2*NB*NH, 256, ROW_SM>>>(bufA, bufA, Y, a0, a1);
    }

    // --- L5 ---
    k2a_kernel<<<NB*NC, 512, K2A_SM>>>(Y, Z);
    k2bc_kernel<<<NB*NC, 256>>>(Z, w1p[5], w2p_[5], G0, w1p[5], w2p_[5], G0);
    {
        LArg a = { G0, cwp[5], cbp[5], bufB, bufA, 0 };       // final
        layer_kernel<<<NB*NH, 256, ROW_SM>>>(bufC, bufC, Y, a, a);
    }

    head_kernel<<<NB*NH, 256, HEAD_SM>>>(bufA, fc1w, fc1b, fc2w, fc2b, out);
}

// round 12
// speedup vs baseline: 1.6150x; 1.0141x over previous
#include <cuda_runtime.h>
#include <math.h>

// ---------------- problem constants ----------------
#define NB 8
#define NC 32
#define NH 256
#define NW 256
#define NM 16
#define NKX 32
#define WSZ (32*32*16*16*2)

// ---------------- device scratch ----------------
__device__ float  g_bufA[NB*NC*NH*NW];
__device__ float  g_bufB[NB*NC*NH*NW];
__device__ float  g_bufC[NB*NC*NH*NW];
__device__ float2 g_Y[NB*NC*NH*NM];
__device__ float2 g_Zb[NB*NC*NKX*NM];
__device__ float2 g_G[NB*NC*NH*NM];
__device__ float2 g_G2[NB*NC*NH*NM];

// ---------------- helpers ----------------
__device__ __forceinline__ float2 ffma2(float2 a, float2 b, float2 c) {
    float2 d;
    asm("fma.rn.f32x2 %0, %1, %2, %3;"
        : "=l"(reinterpret_cast<unsigned long long&>(d))
        : "l"(reinterpret_cast<unsigned long long&>(a)),
          "l"(reinterpret_cast<unsigned long long&>(b)),
          "l"(reinterpret_cast<unsigned long long&>(c)));
    return d;
}
__device__ __forceinline__ float2 cis_m(int m) {
    float a = (float)(m & 255) * (1.0f/128.0f);
    return make_float2(cospif(a), sinpif(a));
}
// branch-free GELU (Abramowitz-Stegun erf, |err| < 1.5e-7)
__device__ __forceinline__ float gelu_f(float v) {
    float u = fabsf(v) * 0.7071067811865476f;
    float t = __frcp_rn(fmaf(0.3275911f, u, 1.0f));
    float p = t * fmaf(t, fmaf(t, fmaf(t, fmaf(t, 1.061405429f, -1.453152027f),
                                       1.421413741f), -0.284496736f), 0.254829592f);
    float e = __expf(-u * u);
    float erfv = copysignf(fmaf(-p, e, 1.0f), v);
    return 0.5f * v * (1.0f + erfv);
}

// cs4[ky*65+u] = (cos(ky,2u), sin(ky,2u), cos(ky,2u+1), sin(ky,2u+1)), angles 2*pi*ky*w/256
__device__ __forceinline__ void gen_cs4(float4* cs4, int tid) {
#pragma unroll
    for (int k = tid; k < 1024; k += 256) {
        int ky = k >> 6, u = k & 63;
        float2 e0 = cis_m(ky * (2*u));
        float2 e1 = cis_m(ky * (2*u + 1));
        cs4[ky*65 + u] = make_float4(e0.x, e0.y, e1.x, e1.y);
    }
}

// folded forward W-DFT: orow float2[16][258]; [p][w<128]=v(w)+v(w+128), [p][128+w]=v(w)-v(w+128)
__device__ __forceinline__ void fwd_dft(const float2* orow, const float4* cs4,
                                        float2* __restrict__ Y, int b, int h, int tid) {
    int q  = tid >> 4;
    int ky = tid & 15;
    float2 yr = make_float2(0.f, 0.f);
    float2 yi = make_float2(0.f, 0.f);
    const float4* op = (const float4*)(orow + q*258 + ((ky & 1) ? 128 : 0));
    const float4* ep = cs4 + ky*65;
#pragma unroll 8
    for (int w2 = 0; w2 < 64; w2++) {
        float4 o4 = op[w2];
        float4 e4 = ep[w2];
        yr = ffma2(make_float2(o4.x, o4.y), make_float2(e4.x,  e4.x), yr);
        yi = ffma2(make_float2(o4.x, o4.y), make_float2(-e4.y, -e4.y), yi);
        yr = ffma2(make_float2(o4.z, o4.w), make_float2(e4.z,  e4.z), yr);
        yi = ffma2(make_float2(o4.z, o4.w), make_float2(-e4.w, -e4.w), yi);
    }
    Y[((b*NC + 2*q    )*NH + h)*NM + ky] = make_float2(yr.x, yi.x);
    Y[((b*NC + 2*q + 1)*NH + h)*NM + ky] = make_float2(yr.y, yi.y);
}

// ---------------- shared conv + spectral-synthesis core (w-quad mapping) ----------------
// thread: u = tid&63 -> w in {2u,2u+1,2u+128,2u+129}; qg = tid>>6 -> pairs 4qg..4qg+3.
// acc[j*4+wpos] = (ch 2p, ch 2p+1) at that w position.
__device__ __forceinline__ void compute_vals(
        const float4* g4, const float4* cwq, const float2* cb2, const float4* cs4,
        const float2* xrow2, int u, int qg, float2* acc) {
#pragma unroll
    for (int j = 0; j < 4; j++) {
        float2 bias = cb2[4*qg + j];
        acc[j*4+0] = bias; acc[j*4+1] = bias; acc[j*4+2] = bias; acc[j*4+3] = bias;
    }
    // 1x1 conv
#pragma unroll 4
    for (int c = 0; c < NC; c++) {
        float2 xa = xrow2[c*130 + u];
        float2 xb = xrow2[c*130 + u + 64];
        float4 wA = cwq[c*8 + qg*2 + 0];
        float4 wB = cwq[c*8 + qg*2 + 1];
        float2 wj0 = make_float2(wA.x, wA.y), wj1 = make_float2(wA.z, wA.w);
        float2 wj2 = make_float2(wB.x, wB.y), wj3 = make_float2(wB.z, wB.w);
        float2 x0 = make_float2(xa.x, xa.x), x1 = make_float2(xa.y, xa.y);
        float2 x2 = make_float2(xb.x, xb.x), x3 = make_float2(xb.y, xb.y);
        acc[0]  = ffma2(x0, wj0, acc[0]);  acc[1]  = ffma2(x1, wj0, acc[1]);
        acc[2]  = ffma2(x2, wj0, acc[2]);  acc[3]  = ffma2(x3, wj0, acc[3]);
        acc[4]  = ffma2(x0, wj1, acc[4]);  acc[5]  = ffma2(x1, wj1, acc[5]);
        acc[6]  = ffma2(x2, wj1, acc[6]);  acc[7]  = ffma2(x3, wj1, acc[7]);
        acc[8]  = ffma2(x0, wj2, acc[8]);  acc[9]  = ffma2(x1, wj2, acc[9]);
        acc[10] = ffma2(x2, wj2, acc[10]); acc[11] = ffma2(x3, wj2, acc[11]);
        acc[12] = ffma2(x0, wj3, acc[12]); acc[13] = ffma2(x1, wj3, acc[13]);
        acc[14] = ffma2(x2, wj3, acc[14]); acc[15] = ffma2(x3, wj3, acc[15]);
    }
    // spectral synthesis with ky-parity fold: w+128 value = P - Q
#pragma unroll
    for (int j = 0; j < 4; j++) {
        int p = 4*qg + j;
        float2 P0 = make_float2(0.f,0.f), Q0 = make_float2(0.f,0.f);
        float2 P1 = make_float2(0.f,0.f), Q1 = make_float2(0.f,0.f);
#pragma unroll
        for (int ky = 0; ky < NM; ky++) {
            float4 e4 = cs4[ky*65 + u];
            float4 g  = g4[p*16 + ky];
            float2 gr = make_float2(g.x, g.y), gi = make_float2(g.z, g.w);
            if ((ky & 1) == 0) {
                P0 = ffma2(gr, make_float2(e4.x, e4.x), P0);
                P0 = ffma2(gi, make_float2(-e4.y, -e4.y), P0);
                P1 = ffma2(gr, make_float2(e4.z, e4.z), P1);
                P1 = ffma2(gi, make_float2(-e4.w, -e4.w), P1);
            } else {
                Q0 = ffma2(gr, make_float2(e4.x, e4.x), Q0);
                Q0 = ffma2(gi, make_float2(-e4.y, -e4.y), Q0);
                Q1 = ffma2(gr, make_float2(e4.z, e4.z), Q1);
                Q1 = ffma2(gi, make_float2(-e4.w, -e4.w), Q1);
            }
        }
        acc[j*4+0] = make_float2(acc[j*4+0].x + P0.x + Q0.x, acc[j*4+0].y + P0.y + Q0.y);
        acc[j*4+1] = make_float2(acc[j*4+1].x + P1.x + Q1.x, acc[j*4+1].y + P1.y + Q1.y);
        acc[j*4+2] = make_float2(acc[j*4+2].x + P0.x - Q0.x, acc[j*4+2].y + P0.y - Q0.y);
        acc[j*4+3] = make_float2(acc[j*4+3].x + P1.x - Q1.x, acc[j*4+3].y + P1.y - Q1.y);
    }
}

// shared prologue staging (layer kernels)
__device__ __forceinline__ void stage_layer(
        float4* g4, float4* cwq, float2* cb2, float* xrowf,
        const float* xin, const float2* G, const float* cw, const float* cb,
        int b, int h, int tid) {
    for (int c = 0; c < NC; c++) xrowf[c*260 + tid] = xin[((b*NC + c)*NH + h)*NW + tid];
    {
        int c = tid >> 3, p2 = tid & 7;
        cwq[tid] = make_float4(cw[(4*p2+0)*32+c], cw[(4*p2+1)*32+c],
                               cw[(4*p2+2)*32+c], cw[(4*p2+3)*32+c]);
    }
    if (tid < 16) cb2[tid] = make_float2(cb[2*tid], cb[2*tid+1]);
    {
        int p = tid >> 4, ky = tid & 15;
        float2 ga = G[((b*NC + 2*p    )*NH + h)*NM + ky];
        float2 gb = G[((b*NC + 2*p + 1)*NH + h)*NM + ky];
        g4[p*16 + ky] = make_float4(ga.x, gb.x, ga.y, gb.y);
    }
}

// ---------------- lift ----------------
// smem: cs4[0,16640) | orow[16640,49664) | w0s[49664,51200) | b0s[51200,51328)
static const int LIFT_SM = 51328;
__global__ void __launch_bounds__(256) lift_kernel(
        const float* __restrict__ x, const float* __restrict__ w0,
        const float* __restrict__ b0, float* __restrict__ out, float2* __restrict__ Y) {
    extern __shared__ unsigned char sm[];
    float4* cs4  = (float4*)sm;
    float2* orow = (float2*)(sm + 16640);
    float*  w0s  = (float*)(sm + 49664);
    float*  b0s  = (float*)(sm + 51200);
    float*  orowf = (float*)orow;

    int b = blockIdx.x >> 8, h = blockIdx.x & 255, tid = threadIdx.x;

    gen_cs4(cs4, tid);
    for (int k = tid; k < 384; k += 256) w0s[k] = w0[k];
    if (tid < 32) b0s[tid] = b0[tid];
    __syncthreads();

    int w = tid;
    const float* xp = x + (((b*NH) + h)*NW + w) * 10;
    float xv[10];
#pragma unroll
    for (int t = 0; t < 10; t++) xv[t] = xp[t];
    float gx = (float)h * (1.0f/255.0f);
    float gy = (float)w * (1.0f/255.0f);

    for (int c = 0; c < NC; c++) {
        float acc = b0s[c];
#pragma unroll
        for (int t = 0; t < 10; t++) acc = fmaf(xv[t], w0s[t*32 + c], acc);
        acc = fmaf(gx, w0s[10*32 + c], acc);
        acc = fmaf(gy, w0s[11*32 + c], acc);
        out[((b*NC + c)*NH + h)*NW + w] = acc;
        orowf[(c >> 1)*516 + 2*w + (c & 1)] = acc;
    }
    __syncthreads();
    {   // fold w / w+128
        int wl = tid & 127, half = tid >> 7;
#pragma unroll
        for (int pp = 0; pp < 8; pp++) {
            int p = half*8 + pp;
            float2 a = orow[p*258 + wl];
            float2 c = orow[p*258 + 128 + wl];
            orow[p*258 + wl]       = make_float2(a.x + c.x, a.y + c.y);
            orow[p*258 + 128 + wl] = make_float2(a.x - c.x, a.y - c.y);
        }
    }
    __syncthreads();
    fwd_dft(orow, cs4, Y, b, h, tid);
}

// ---------------- k2a: H-DFT  Y -> Z ----------------
static const int K2A_SM = 32768 + 65536;
__global__ void __launch_bounds__(512, 2) k2a_kernel(
        const float2* __restrict__ Y, float2* __restrict__ Z) {
    extern __shared__ unsigned char sm[];
    float2* Ys  = (float2*)sm;
    float2* E1s = (float2*)(sm + 32768);

    int b = blockIdx.x >> 5, i = blockIdx.x & 31, tid = threadIdx.x;
    {
        const float4* src = (const float4*)(Y + (b*NC + i)*NH*NM);
        float4* dst = (float4*)Ys;
        for (int k = tid; k < 2048; k += 512) dst[k] = src[k];
    }
#pragma unroll
    for (int k = tid; k < NH*NKX; k += 512) {
        int h = k >> 5, kx = k & 31;
        int fr = (kx < 16) ? kx : (kx - 32);
        float2 e = cis_m(fr * h);
        E1s[k] = make_float2(e.x, -e.y);
    }
    __syncthreads();

    int kx = tid >> 4, ky = tid & 15;
    float2 z = make_float2(0.f, 0.f);
#pragma unroll 4
    for (int h = 0; h < NH; h++) {
        float2 e = E1s[h*NKX + kx];
        float2 y = Ys[h*NM + ky];
        z = ffma2(make_float2(y.x, y.x), e, z);
        z = ffma2(make_float2(y.y, y.y), make_float2(-e.y, e.x), z);
    }
    Z[((b*NC + i)*NKX + kx)*NM + ky] = z;
}

// ---------------- k2bc: channel mix + inverse H-DFT, dual weight-set ----------------
__global__ void __launch_bounds__(256) k2bc_kernel(
        const float2* __restrict__ Z,
        const float* __restrict__ w1a, const float* __restrict__ w2a, float2* __restrict__ Ga,
        const float* __restrict__ w1b, const float* __restrict__ w2b, float2* __restrict__ Gb) {
    __shared__ float2 Ts[NKX*NM];

    int sub = blockIdx.x >> 8, bid = blockIdx.x & 255;
    const float2* w1c = (const float2*)(sub ? w1b : w1a);
    const float2* w2c = (const float2*)(sub ? w2b : w2a);
    float2* G = sub ? Gb : Ga;

    int b = bid >> 5, o = bid & 31, tid = threadIdx.x;
    int ky = tid & 15, kxm = tid >> 4;
    const float2* zb = Z + (size_t)b*NC*NKX*NM;

    float2 t1 = make_float2(0.f, 0.f);
    float2 t2 = make_float2(0.f, 0.f);
#pragma unroll 4
    for (int i = 0; i < NC; i++) {
        float2 z1 = zb[i*NKX*NM + kxm*NM + ky];
        float2 z2 = zb[i*NKX*NM + (kxm+16)*NM + ky];
        float2 wv1 = w1c[((i*32 + o)*16 + kxm)*16 + ky];
        float2 wv2 = w2c[((i*32 + o)*16 + kxm)*16 + ky];
        t1 = ffma2(make_float2(z1.x, z1.x), wv1, t1);
        t1 = ffma2(make_float2(z1.y, z1.y), make_float2(-wv1.y, wv1.x), t1);
        t2 = ffma2(make_float2(z2.x, z2.x), wv2, t2);
        t2 = ffma2(make_float2(z2.y, z2.y), make_float2(-wv2.y, wv2.x), t2);
    }
    Ts[kxm*16 + ky]      = t1;
    Ts[(kxm+16)*16 + ky] = t2;
    __syncthreads();

    int h = tid;
    float2 acc[NM];
#pragma unroll
    for (int k = 0; k < NM; k++) acc[k] = make_float2(0.f, 0.f);
#pragma unroll 2
    for (int kx = 0; kx < NKX; kx++) {
        int fr = (kx < 16) ? kx : (kx - 32);
        float2 e = cis_m(fr * h);
        float2 en = make_float2(-e.y, e.x);
#pragma unroll
        for (int k = 0; k < NM; k++) {
            float2 t = Ts[kx*16 + k];
            acc[k] = ffma2(make_float2(t.x, t.x), e,  acc[k]);
            acc[k] = ffma2(make_float2(t.y, t.y), en, acc[k]);
        }
    }
    float4* gp = (float4*)(G + ((b*NC + o)*NH + h)*NM);
    const float s2 = 2.0f / 65536.0f;
#pragma unroll
    for (int k = 0; k < 8; k++) {
        float s0 = (k == 0) ? (1.0f/65536.0f) : s2;
        gp[k] = make_float4(acc[2*k].x*s0, acc[2*k].y*s0, acc[2*k+1].x*s2, acc[2*k+1].y*s2);
    }
}

// ---------------- fused layer row kernel v6 ----------------
struct LArg {
    const float2* G;
    const float*  cw;
    const float*  cb;
    const float*  skip;   // nullptr = no skip
    float*        out;
    int           writeY;
};

// smem: g4[0,4096) | cwq[4096,8192) | cb2[8192,8320) | cs4[8320,24960) | xrow/orow[24960,58240)
static const int ROW_SM = 58240;
__global__ void __launch_bounds__(256, 3) layer_kernel(
        const float* __restrict__ xin0, const float* __restrict__ xin1,
        float2* __restrict__ Ynext, LArg a0, LArg a1) {
    extern __shared__ unsigned char sm[];
    float4* g4    = (float4*)sm;
    float4* cwq   = (float4*)(sm + 4096);
    float2* cb2   = (float2*)(sm + 8192);
    float4* cs4   = (float4*)(sm + 8320);
    float2* xrow2 = (float2*)(sm + 24960);   // [c][130] pairs; aliased by orow after conv
    float2* orow  = (float2*)(sm + 24960);   // [p][258] folded

    int sub = blockIdx.x >> 11;
    int bid = blockIdx.x & 2047;
    const LArg la = sub ? a1 : a0;
    const float* xin = sub ? xin1 : xin0;

    int b = bid >> 8, h = bid & 255, tid = threadIdx.x;

    gen_cs4(cs4, tid);
    stage_layer(g4, cwq, cb2, (float*)xrow2, xin, la.G, la.cw, la.cb, b, h, tid);
    __syncthreads();

    int u = tid & 63, qg = tid >> 6;
    float2 acc[16];
    compute_vals(g4, cwq, cb2, cs4, xrow2, u, qg, acc);

    // gelu + skip + global stores
#pragma unroll
    for (int j = 0; j < 4; j++) {
        int p = 4*qg + j;
        int base0 = ((b*NC + 2*p)*NH + h)*NW;
        int base1 = base0 + NH*NW;
#pragma unroll
        for (int wp = 0; wp < 4; wp++) {
            acc[j*4+wp].x = gelu_f(acc[j*4+wp].x);
            acc[j*4+wp].y = gelu_f(acc[j*4+wp].y);
        }
        if (la.skip) {
            float2 sA0 = ((const float2*)(la.skip + base0))[u];
            float2 sA1 = ((const float2*)(la.skip + base0))[u + 64];
            float2 sB0 = ((const float2*)(la.skip + base1))[u];
            float2 sB1 = ((const float2*)(la.skip + base1))[u + 64];
            acc[j*4+0].x += sA0.x; acc[j*4+1].x += sA0.y;
            acc[j*4+2].x += sA1.x; acc[j*4+3].x += sA1.y;
            acc[j*4+0].y += sB0.x; acc[j*4+1].y += sB0.y;
            acc[j*4+2].y += sB1.x; acc[j*4+3].y += sB1.y;
        }
        ((float2*)(la.out + base0))[u]      = make_float2(acc[j*4+0].x, acc[j*4+1].x);
        ((float2*)(la.out + base0))[u + 64] = make_float2(acc[j*4+2].x, acc[j*4+3].x);
        ((float2*)(la.out + base1))[u]      = make_float2(acc[j*4+0].y, acc[j*4+1].y);
        ((float2*)(la.out + base1))[u + 64] = make_float2(acc[j*4+2].y, acc[j*4+3].y);
    }

    if (la.writeY) {
        __syncthreads();   // all conv reads of xrow done before orow overwrite
#pragma unroll
        for (int j = 0; j < 4; j++) {
            int p = 4*qg + j;
            float2 s0 = make_float2(acc[j*4+0].x + acc[j*4+2].x, acc[j*4+0].y + acc[j*4+2].y);
            float2 s1 = make_float2(acc[j*4+1].x + acc[j*4+3].x, acc[j*4+1].y + acc[j*4+3].y);
            float2 d0 = make_float2(acc[j*4+0].x - acc[j*4+2].x, acc[j*4+0].y - acc[j*4+2].y);
            float2 d1 = make_float2(acc[j*4+1].x - acc[j*4+3].x, acc[j*4+1].y - acc[j*4+3].y);
            *(float4*)(orow + p*258 + 2*u)       = make_float4(s0.x, s0.y, s1.x, s1.y);
            *(float4*)(orow + p*258 + 128 + 2*u) = make_float4(d0.x, d0.y, d1.x, d1.y);
        }
        __syncthreads();
        fwd_dft(orow, cs4, Ynext, b, h, tid);
    }
}

// ---------------- L5 + head fused kernel ----------------
// smem: layer regions [0,58240) | w1s[58240,74624) | w2p[74624,77696) | b1s[77696,78208) | b2s[78208,78240)
static const int HEAD5_SM = 78240;
__global__ void __launch_bounds__(256, 2) layer5_head_kernel(
        const float* __restrict__ xin, LArg a0,
        const float* __restrict__ fw1, const float* __restrict__ fb1,
        const float* __restrict__ fw2, const float* __restrict__ fb2,
        float* __restrict__ out) {
    extern __shared__ unsigned char sm[];
    float4* g4    = (float4*)sm;
    float4* cwq   = (float4*)(sm + 4096);
    float2* cb2   = (float2*)(sm + 8192);
    float4* cs4   = (float4*)(sm + 8320);
    float2* xrow2 = (float2*)(sm + 24960);
    float*  vrow  = (float*)(sm + 24960);     // [c][258] floats, aliases xrow
    float*  w1s   = (float*)(sm + 58240);
    float2* w2p   = (float2*)(sm + 74624);
    float*  b1s   = (float*)(sm + 77696);
    float*  b2s   = (float*)(sm + 78208);

    int b = blockIdx.x >> 8, h = blockIdx.x & 255, tid = threadIdx.x;

    gen_cs4(cs4, tid);
    stage_layer(g4, cwq, cb2, (float*)xrow2, xin, a0.G, a0.cw, a0.cb, b, h, tid);
    for (int k = tid; k < 4096; k += 256) w1s[k] = fw1[k];
    if (tid < 128) {
        b1s[tid] = fb1[tid];
        w2p[tid*3 + 0] = make_float2(fw2[tid*5 + 0], fw2[tid*5 + 1]);
        w2p[tid*3 + 1] = make_float2(fw2[tid*5 + 2], fw2[tid*5 + 3]);
        w2p[tid*3 + 2] = make_float2(fw2[tid*5 + 4], 0.0f);
    }
    if (tid < 5) b2s[tid] = fb2[tid];
    __syncthreads();

    int u = tid & 63, qg = tid >> 6;
    float2 acc[16];
    compute_vals(g4, cwq, cb2, cs4, xrow2, u, qg, acc);

    // gelu + skip (no global store of the layer output)
#pragma unroll
    for (int j = 0; j < 4; j++) {
        int p = 4*qg + j;
        int base0 = ((b*NC + 2*p)*NH + h)*NW;
        int base1 = base0 + NH*NW;
#pragma unroll
        for (int wp = 0; wp < 4; wp++) {
            acc[j*4+wp].x = gelu_f(acc[j*4+wp].x);
            acc[j*4+wp].y = gelu_f(acc[j*4+wp].y);
        }
        float2 sA0 = ((const float2*)(a0.skip + base0))[u];
        float2 sA1 = ((const float2*)(a0.skip + base0))[u + 64];
        float2 sB0 = ((const float2*)(a0.skip + base1))[u];
        float2 sB1 = ((const float2*)(a0.skip + base1))[u + 64];
        acc[j*4+0].x += sA0.x; acc[j*4+1].x += sA0.y;
        acc[j*4+2].x += sA1.x; acc[j*4+3].x += sA1.y;
        acc[j*4+0].y += sB0.x; acc[j*4+1].y += sB0.y;
        acc[j*4+2].y += sB1.x; acc[j*4+3].y += sB1.y;
    }

    __syncthreads();   // conv reads done -> safe to overwrite xrow with vrow
#pragma unroll
    for (int j = 0; j < 4; j++) {
        int p = 4*qg + j;
        int ch0 = 2*p, ch1 = 2*p + 1;
        ((float2*)(vrow + ch0*258))[u]      = make_float2(acc[j*4+0].x, acc[j*4+1].x);
        ((float2*)(vrow + ch0*258))[u + 64] = make_float2(acc[j*4+2].x, acc[j*4+3].x);
        ((float2*)(vrow + ch1*258))[u]      = make_float2(acc[j*4+0].y, acc[j*4+1].y);
        ((float2*)(vrow + ch1*258))[u + 64] = make_float2(acc[j*4+2].y, acc[j*4+3].y);
    }
    __syncthreads();

    // head: fc1 + GELU + fc2 for w = tid
    int w = tid;
    float2 o01 = make_float2(b2s[0], b2s[1]);
    float2 o23 = make_float2(b2s[2], b2s[3]);
    float2 o4z = make_float2(b2s[4], 0.0f);
    const float4* w1q = (const float4*)w1s;
    const float2* b1p = (const float2*)b1s;

#pragma unroll 1
    for (int q = 0; q < 4; q++) {
        float2 hacc[16];
#pragma unroll
        for (int jj = 0; jj < 16; jj++) hacc[jj] = b1p[q*16 + jj];
#pragma unroll 4
        for (int c = 0; c < NC; c++) {
            float xv = vrow[c*258 + w];
            float2 xv2 = make_float2(xv, xv);
#pragma unroll
            for (int j8 = 0; j8 < 8; j8++) {
                float4 w4 = w1q[c*32 + q*8 + j8];
                hacc[2*j8    ] = ffma2(xv2, make_float2(w4.x, w4.y), hacc[2*j8    ]);
                hacc[2*j8 + 1] = ffma2(xv2, make_float2(w4.z, w4.w), hacc[2*j8 + 1]);
            }
        }
#pragma unroll
        for (int jj = 0; jj < 16; jj++) {
            int j = 32*q + 2*jj;
            float h0 = gelu_f(hacc[jj].x);
            float h1 = gelu_f(hacc[jj].y);
            float2 h02 = make_float2(h0, h0), h12 = make_float2(h1, h1);
            o01 = ffma2(h02, w2p[j*3 + 0], o01);
            o23 = ffma2(h02, w2p[j*3 + 1], o23);
            o4z = ffma2(h02, w2p[j*3 + 2], o4z);
            o01 = ffma2(h12, w2p[(j+1)*3 + 0], o01);
            o23 = ffma2(h12, w2p[(j+1)*3 + 1], o23);
            o4z = ffma2(h12, w2p[(j+1)*3 + 2], o4z);
        }
    }
    float* op = out + (((b*NH) + h)*NW + w) * 5;
    op[0] = o01.x; op[1] = o01.y; op[2] = o23.x; op[3] = o23.y; op[4] = o4z.x;
}

// ---------------- host launcher ----------------
extern "C" void kernel_launch(void* const* d_in, const int* in_sizes, int n_in,
                              void* d_out, int out_size) {
    const float* x     = (const float*)d_in[0];
    const float* fc0w  = (const float*)d_in[1];
    const float* fc0b  = (const float*)d_in[2];
    const float* w1    = (const float*)d_in[3];
    const float* w2    = (const float*)d_in[4];
    const float* convw = (const float*)d_in[5];
    const float* convb = (const float*)d_in[6];
    const float* fc1w  = (const float*)d_in[7];
    const float* fc1b  = (const float*)d_in[8];
    const float* fc2w  = (const float*)d_in[9];
    const float* fc2b  = (const float*)d_in[10];
    float* out = (float*)d_out;

    float  *bufA, *bufB, *bufC;
    float2 *Y, *Z, *G0, *G1;
    cudaGetSymbolAddress((void**)&bufA, g_bufA);
    cudaGetSymbolAddress((void**)&bufB, g_bufB);
    cudaGetSymbolAddress((void**)&bufC, g_bufC);
    cudaGetSymbolAddress((void**)&Y, g_Y);
    cudaGetSymbolAddress((void**)&Z, g_Zb);
    cudaGetSymbolAddress((void**)&G0, g_G);
    cudaGetSymbolAddress((void**)&G1, g_G2);

    cudaFuncSetAttribute(lift_kernel,       cudaFuncAttributeMaxDynamicSharedMemorySize, LIFT_SM);
    cudaFuncSetAttribute(k2a_kernel,        cudaFuncAttributeMaxDynamicSharedMemorySize, K2A_SM);
    cudaFuncSetAttribute(layer_kernel,      cudaFuncAttributeMaxDynamicSharedMemorySize, ROW_SM);
    cudaFuncSetAttribute(layer5_head_kernel,cudaFuncAttributeMaxDynamicSharedMemorySize, HEAD5_SM);

    const float* w1p[6]; const float* w2p_[6]; const float* cwp[6]; const float* cbp[6];
    for (int l = 0; l < 6; l++) {
        w1p[l]  = w1 + (size_t)l * WSZ;
        w2p_[l] = w2 + (size_t)l * WSZ;
        cwp[l]  = convw + l * 32 * 32;
        cbp[l]  = convb + l * 32;
    }

    // DAG:  h0 = L0(lift); t1 = L1(lift); t2 = L2(t1) + h0;
    //       h1 = L3(t2);   t4 = L4(t2);   out = head(L5(t4) + h1);
    lift_kernel<<<NB*NH, 256, LIFT_SM>>>(x, fc0w, fc0b, bufA, Y);   // A = lift, Y_lift

    // L0 + L1 (share Z of Y_lift)
    k2a_kernel<<<NB*NC, 512, K2A_SM>>>(Y, Z);
    k2bc_kernel<<<2*NB*NC, 256>>>(Z, w1p[0], w2p_[0], G0, w1p[1], w2p_[1], G1);
    {
        LArg a0 = { G0, cwp[0], cbp[0], nullptr, bufB, 0 };   // h0
        LArg a1 = { G1, cwp[1], cbp[1], nullptr, bufC, 1 };   // t1 (+Y_t1)
        layer_kernel<<<2*NB*NH, 256, ROW_SM>>>(bufA, bufA, Y, a0, a1);
    }

    // L2
    k2a_kernel<<<NB*NC, 512, K2A_SM>>>(Y, Z);
    k2bc_kernel<<<NB*NC, 256>>>(Z, w1p[2], w2p_[2], G0, w1p[2], w2p_[2], G0);
    {
        LArg a = { G0, cwp[2], cbp[2], bufB, bufA, 1 };       // t2 (+Y_t2)
        layer_kernel<<<NB*NH, 256, ROW_SM>>>(bufC, bufC, Y, a, a);
    }

    // L3 + L4 (share Z of Y_t2)
    k2a_kernel<<<NB*NC, 512, K2A_SM>>>(Y, Z);
    k2bc_kernel<<<2*NB*NC, 256>>>(Z, w1p[3], w2p_[3], G0, w1p[4], w2p_[4], G1);
    {
        LArg a0 = { G0, cwp[3], cbp[3], nullptr, bufB, 0 };   // h1
        LArg a1 = { G1, cwp[4], cbp[4], nullptr, bufC, 1 };   // t4 (+Y_t4)
        layer_kernel<<<2*NB*NH, 256, ROW_SM>>>(bufA, bufA, Y, a0, a1);
    }

    // L5 + head fused
    k2a_kernel<<<NB*NC, 512, K2A_SM>>>(Y, Z);
    k2bc_kernel<<<NB*NC, 256>>>(Z, w1p[5], w2p_[5], G0, w1p[5], w2p_[5], G0);
    {
        LArg a = { G0, cwp[5], cbp[5], bufB, nullptr, 0 };    // final (consumed in-kernel)
        layer5_head_kernel<<<NB*NH, 256, HEAD5_SM>>>(bufC, a, fc1w, fc1b, fc2w, fc2b, out);
    }
}

// round 13
// speedup vs baseline: 1.7712x; 1.0967x over previous
#include <cuda_runtime.h>
#include <math.h>

// ---------------- problem constants ----------------
#define NB 8
#define NC 32
#define NH 256
#define NW 256
#define NM 16
#define NKX 32
#define WSZ (32*32*16*16*2)

// ---------------- device scratch ----------------
__device__ float  g_bufA[NB*NC*NH*NW];
__device__ float  g_bufB[NB*NC*NH*NW];
__device__ float  g_bufC[NB*NC*NH*NW];
__device__ float2 g_Y[NB*NC*NH*NM];
__device__ float2 g_Zb[NB*NC*NKX*NM];
__device__ float2 g_G[NB*NC*NH*NM];
__device__ float2 g_G2[NB*NC*NH*NM];

// ---------------- helpers ----------------
__device__ __forceinline__ float2 ffma2(float2 a, float2 b, float2 c) {
    float2 d;
    asm("fma.rn.f32x2 %0, %1, %2, %3;"
        : "=l"(reinterpret_cast<unsigned long long&>(d))
        : "l"(reinterpret_cast<unsigned long long&>(a)),
          "l"(reinterpret_cast<unsigned long long&>(b)),
          "l"(reinterpret_cast<unsigned long long&>(c)));
    return d;
}
__device__ __forceinline__ float2 cis_m(int m) {
    float a = (float)(m & 255) * (1.0f/128.0f);
    return make_float2(cospif(a), sinpif(a));
}
// branch-free GELU (Abramowitz-Stegun erf, |err| < 1.5e-7)
__device__ __forceinline__ float gelu_f(float v) {
    float u = fabsf(v) * 0.7071067811865476f;
    float t = __frcp_rn(fmaf(0.3275911f, u, 1.0f));
    float p = t * fmaf(t, fmaf(t, fmaf(t, fmaf(t, 1.061405429f, -1.453152027f),
                                       1.421413741f), -0.284496736f), 0.254829592f);
    float e = __expf(-u * u);
    float erfv = copysignf(fmaf(-p, e, 1.0f), v);
    return 0.5f * v * (1.0f + erfv);
}

// split twiddle tables: cs_a[ky*33+u5] = e(ky,4u5), e(ky,4u5+1); cs_b: +2, +3
__device__ __forceinline__ void gen_cs(float4* cs_a, float4* cs_b, int tid) {
#pragma unroll
    for (int k = tid; k < 512; k += 256) {
        int ky = k >> 5, u5 = k & 31;
        float2 e0 = cis_m(ky * (4*u5    ));
        float2 e1 = cis_m(ky * (4*u5 + 1));
        float2 e2 = cis_m(ky * (4*u5 + 2));
        float2 e3 = cis_m(ky * (4*u5 + 3));
        cs_a[ky*33 + u5] = make_float4(e0.x, e0.y, e1.x, e1.y);
        cs_b[ky*33 + u5] = make_float4(e2.x, e2.y, e3.x, e3.y);
    }
}

// folded forward W-DFT: orow float2[16][258]; [p][w<128]=v(w)+v(w+128), [p][128+w]=v(w)-v(w+128)
__device__ __forceinline__ void fwd_dft(const float2* orow,
                                        const float4* cs_a, const float4* cs_b,
                                        float2* __restrict__ Y, int b, int h, int tid) {
    int q  = tid >> 4;
    int ky = tid & 15;
    float2 yr = make_float2(0.f, 0.f);
    float2 yi = make_float2(0.f, 0.f);
    const float4* op = (const float4*)(orow + q*258 + ((ky & 1) ? 128 : 0));
    const float4* ea = cs_a + ky*33;
    const float4* eb = cs_b + ky*33;
#pragma unroll 8
    for (int t = 0; t < 32; t++) {
        float4 o0 = op[2*t], o1 = op[2*t + 1];
        float4 e4a = ea[t],  e4b = eb[t];
        yr = ffma2(make_float2(o0.x, o0.y), make_float2(e4a.x,  e4a.x), yr);
        yi = ffma2(make_float2(o0.x, o0.y), make_float2(-e4a.y, -e4a.y), yi);
        yr = ffma2(make_float2(o0.z, o0.w), make_float2(e4a.z,  e4a.z), yr);
        yi = ffma2(make_float2(o0.z, o0.w), make_float2(-e4a.w, -e4a.w), yi);
        yr = ffma2(make_float2(o1.x, o1.y), make_float2(e4b.x,  e4b.x), yr);
        yi = ffma2(make_float2(o1.x, o1.y), make_float2(-e4b.y, -e4b.y), yi);
        yr = ffma2(make_float2(o1.z, o1.w), make_float2(e4b.z,  e4b.z), yr);
        yi = ffma2(make_float2(o1.z, o1.w), make_float2(-e4b.w, -e4b.w), yi);
    }
    Y[((b*NC + 2*q    )*NH + h)*NM + ky] = make_float2(yr.x, yi.x);
    Y[((b*NC + 2*q + 1)*NH + h)*NM + ky] = make_float2(yr.y, yi.y);
}

// ---------------- shared conv + spectral-synthesis core v7 ----------------
// thread: u5 = tid&31 -> w in {4u5..4u5+3} (+128 fold); pg = tid>>5 -> pairs {2pg, 2pg+1}.
// acc[j*8+wp]: j=pair, wp 0..3 = w 4u5+wp, wp 4..7 = +128.  float2 = (ch 2p, ch 2p+1).
__device__ __forceinline__ void compute_vals(
        const float4* g4, const float4* cwq, const float2* cb2,
        const float4* cs_a, const float4* cs_b,
        const float* xrowf, int u5, int pg, float2* acc) {
#pragma unroll
    for (int j = 0; j < 2; j++) {
        float2 bias = cb2[2*pg + j];
#pragma unroll
        for (int wp = 0; wp < 8; wp++) acc[j*8 + wp] = bias;
    }
    // 1x1 conv
#pragma unroll 4
    for (int c = 0; c < NC; c++) {
        float4 xa = *(const float4*)(xrowf + c*260 + 4*u5);
        float4 xb = *(const float4*)(xrowf + c*260 + 128 + 4*u5);
        float4 w4 = cwq[c*8 + pg];
        float2 wj0 = make_float2(w4.x, w4.y), wj1 = make_float2(w4.z, w4.w);
        acc[0]  = ffma2(make_float2(xa.x, xa.x), wj0, acc[0]);
        acc[1]  = ffma2(make_float2(xa.y, xa.y), wj0, acc[1]);
        acc[2]  = ffma2(make_float2(xa.z, xa.z), wj0, acc[2]);
        acc[3]  = ffma2(make_float2(xa.w, xa.w), wj0, acc[3]);
        acc[4]  = ffma2(make_float2(xb.x, xb.x), wj0, acc[4]);
        acc[5]  = ffma2(make_float2(xb.y, xb.y), wj0, acc[5]);
        acc[6]  = ffma2(make_float2(xb.z, xb.z), wj0, acc[6]);
        acc[7]  = ffma2(make_float2(xb.w, xb.w), wj0, acc[7]);
        acc[8]  = ffma2(make_float2(xa.x, xa.x), wj1, acc[8]);
        acc[9]  = ffma2(make_float2(xa.y, xa.y), wj1, acc[9]);
        acc[10] = ffma2(make_float2(xa.z, xa.z), wj1, acc[10]);
        acc[11] = ffma2(make_float2(xa.w, xa.w), wj1, acc[11]);
        acc[12] = ffma2(make_float2(xb.x, xb.x), wj1, acc[12]);
        acc[13] = ffma2(make_float2(xb.y, xb.y), wj1, acc[13]);
        acc[14] = ffma2(make_float2(xb.z, xb.z), wj1, acc[14]);
        acc[15] = ffma2(make_float2(xb.w, xb.w), wj1, acc[15]);
    }
    // spectral synthesis with ky-parity fold
#pragma unroll
    for (int j = 0; j < 2; j++) {
        int p = 2*pg + j;
        float2 P0 = make_float2(0.f,0.f), P1 = P0, P2 = P0, P3 = P0;
        float2 Q0 = P0, Q1 = P0, Q2 = P0, Q3 = P0;
#pragma unroll
        for (int ky = 0; ky < NM; ky++) {
            float4 g  = g4[p*16 + ky];
            float2 gr = make_float2(g.x, g.y), gi = make_float2(g.z, g.w);
            float4 ea = cs_a[ky*33 + u5];
            float4 eb = cs_b[ky*33 + u5];
            if ((ky & 1) == 0) {
                P0 = ffma2(gr, make_float2(ea.x, ea.x), P0);
                P0 = ffma2(gi, make_float2(-ea.y, -ea.y), P0);
                P1 = ffma2(gr, make_float2(ea.z, ea.z), P1);
                P1 = ffma2(gi, make_float2(-ea.w, -ea.w), P1);
                P2 = ffma2(gr, make_float2(eb.x, eb.x), P2);
                P2 = ffma2(gi, make_float2(-eb.y, -eb.y), P2);
                P3 = ffma2(gr, make_float2(eb.z, eb.z), P3);
                P3 = ffma2(gi, make_float2(-eb.w, -eb.w), P3);
            } else {
                Q0 = ffma2(gr, make_float2(ea.x, ea.x), Q0);
                Q0 = ffma2(gi, make_float2(-ea.y, -ea.y), Q0);
                Q1 = ffma2(gr, make_float2(ea.z, ea.z), Q1);
                Q1 = ffma2(gi, make_float2(-ea.w, -ea.w), Q1);
                Q2 = ffma2(gr, make_float2(eb.x, eb.x), Q2);
                Q2 = ffma2(gi, make_float2(-eb.y, -eb.y), Q2);
                Q3 = ffma2(gr, make_float2(eb.z, eb.z), Q3);
                Q3 = ffma2(gi, make_float2(-eb.w, -eb.w), Q3);
            }
        }
        acc[j*8+0] = make_float2(acc[j*8+0].x + P0.x + Q0.x, acc[j*8+0].y + P0.y + Q0.y);
        acc[j*8+1] = make_float2(acc[j*8+1].x + P1.x + Q1.x, acc[j*8+1].y + P1.y + Q1.y);
        acc[j*8+2] = make_float2(acc[j*8+2].x + P2.x + Q2.x, acc[j*8+2].y + P2.y + Q2.y);
        acc[j*8+3] = make_float2(acc[j*8+3].x + P3.x + Q3.x, acc[j*8+3].y + P3.y + Q3.y);
        acc[j*8+4] = make_float2(acc[j*8+4].x + P0.x - Q0.x, acc[j*8+4].y + P0.y - Q0.y);
        acc[j*8+5] = make_float2(acc[j*8+5].x + P1.x - Q1.x, acc[j*8+5].y + P1.y - Q1.y);
        acc[j*8+6] = make_float2(acc[j*8+6].x + P2.x - Q2.x, acc[j*8+6].y + P2.y - Q2.y);
        acc[j*8+7] = make_float2(acc[j*8+7].x + P3.x - Q3.x, acc[j*8+7].y + P3.y - Q3.y);
    }
}

// shared prologue staging (layer kernels); xrowf stride 260
__device__ __forceinline__ void stage_layer(
        float4* g4, float4* cwq, float2* cb2, float* xrowf,
        const float* xin, const float2* G, const float* cw, const float* cb,
        int b, int h, int tid) {
    for (int c = 0; c < NC; c++) xrowf[c*260 + tid] = xin[((b*NC + c)*NH + h)*NW + tid];
    {
        int c = tid >> 3, p2 = tid & 7;
        cwq[tid] = make_float4(cw[(4*p2+0)*32+c], cw[(4*p2+1)*32+c],
                               cw[(4*p2+2)*32+c], cw[(4*p2+3)*32+c]);
    }
    if (tid < 16) cb2[tid] = make_float2(cb[2*tid], cb[2*tid+1]);
    {
        int p = tid >> 4, ky = tid & 15;
        float2 ga = G[((b*NC + 2*p    )*NH + h)*NM + ky];
        float2 gb = G[((b*NC + 2*p + 1)*NH + h)*NM + ky];
        g4[p*16 + ky] = make_float4(ga.x, gb.x, ga.y, gb.y);
    }
}

// ---------------- lift ----------------
// smem: cs_a[0,8448) | cs_b[8448,16896) | orow[16896,49920) | w0s[49920,51456)
//       | b0s[51456,51584) | xstage[51584,61824)
static const int LIFT_SM = 61824;
__global__ void __launch_bounds__(256) lift_kernel(
        const float* __restrict__ x, const float* __restrict__ w0,
        const float* __restrict__ b0, float* __restrict__ out, float2* __restrict__ Y) {
    extern __shared__ unsigned char sm[];
    float4* cs_a = (float4*)sm;
    float4* cs_b = (float4*)(sm + 8448);
    float2* orow = (float2*)(sm + 16896);
    float*  w0s  = (float*)(sm + 49920);
    float*  b0s  = (float*)(sm + 51456);
    float*  xst  = (float*)(sm + 51584);
    float*  orowf = (float*)orow;

    int b = blockIdx.x >> 8, h = blockIdx.x & 255, tid = threadIdx.x;

    gen_cs(cs_a, cs_b, tid);
    for (int k = tid; k < 384; k += 256) w0s[k] = w0[k];
    if (tid < 32) b0s[tid] = b0[tid];
    {   // stage x row [256 w][10] via coalesced float4 loads
        const float4* xp4 = (const float4*)(x + (size_t)((b*NH) + h) * NW * 10);
        float4* xs4 = (float4*)xst;
        for (int k = tid; k < 640; k += 256) xs4[k] = xp4[k];
    }
    __syncthreads();

    int w = tid;
    float xv[10];
#pragma unroll
    for (int t = 0; t < 10; t++) xv[t] = xst[w*10 + t];
    float gx = (float)h * (1.0f/255.0f);
    float gy = (float)w * (1.0f/255.0f);

    for (int c = 0; c < NC; c++) {
        float acc = b0s[c];
#pragma unroll
        for (int t = 0; t < 10; t++) acc = fmaf(xv[t], w0s[t*32 + c], acc);
        acc = fmaf(gx, w0s[10*32 + c], acc);
        acc = fmaf(gy, w0s[11*32 + c], acc);
        out[((b*NC + c)*NH + h)*NW + w] = acc;
        orowf[(c >> 1)*516 + 2*w + (c & 1)] = acc;
    }
    __syncthreads();
    {   // fold w / w+128
        int wl = tid & 127, half = tid >> 7;
#pragma unroll
        for (int pp = 0; pp < 8; pp++) {
            int p = half*8 + pp;
            float2 a = orow[p*258 + wl];
            float2 c = orow[p*258 + 128 + wl];
            orow[p*258 + wl]       = make_float2(a.x + c.x, a.y + c.y);
            orow[p*258 + 128 + wl] = make_float2(a.x - c.x, a.y - c.y);
        }
    }
    __syncthreads();
    fwd_dft(orow, cs_a, cs_b, Y, b, h, tid);
}

// ---------------- k2a: H-DFT  Y -> Z ----------------
static const int K2A_SM = 32768 + 65536;
__global__ void __launch_bounds__(512, 2) k2a_kernel(
        const float2* __restrict__ Y, float2* __restrict__ Z) {
    extern __shared__ unsigned char sm[];
    float2* Ys  = (float2*)sm;
    float2* E1s = (float2*)(sm + 32768);

    int b = blockIdx.x >> 5, i = blockIdx.x & 31, tid = threadIdx.x;
    {
        const float4* src = (const float4*)(Y + (b*NC + i)*NH*NM);
        float4* dst = (float4*)Ys;
        for (int k = tid; k < 2048; k += 512) dst[k] = src[k];
    }
#pragma unroll
    for (int k = tid; k < NH*NKX; k += 512) {
        int h = k >> 5, kx = k & 31;
        int fr = (kx < 16) ? kx : (kx - 32);
        float2 e = cis_m(fr * h);
        E1s[k] = make_float2(e.x, -e.y);
    }
    __syncthreads();

    int kx = tid >> 4, ky = tid & 15;
    float2 z = make_float2(0.f, 0.f);
#pragma unroll 4
    for (int h = 0; h < NH; h++) {
        float2 e = E1s[h*NKX + kx];
        float2 y = Ys[h*NM + ky];
        z = ffma2(make_float2(y.x, y.x), e, z);
        z = ffma2(make_float2(y.y, y.y), make_float2(-e.y, e.x), z);
    }
    Z[((b*NC + i)*NKX + kx)*NM + ky] = z;
}

// ---------------- k2bc: channel mix + inverse H-DFT, dual weight-set ----------------
__global__ void __launch_bounds__(256) k2bc_kernel(
        const float2* __restrict__ Z,
        const float* __restrict__ w1a, const float* __restrict__ w2a, float2* __restrict__ Ga,
        const float* __restrict__ w1b, const float* __restrict__ w2b, float2* __restrict__ Gb) {
    __shared__ float2 Ts[NKX*NM];

    int sub = blockIdx.x >> 8, bid = blockIdx.x & 255;
    const float2* w1c = (const float2*)(sub ? w1b : w1a);
    const float2* w2c = (const float2*)(sub ? w2b : w2a);
    float2* G = sub ? Gb : Ga;

    int b = bid >> 5, o = bid & 31, tid = threadIdx.x;
    int ky = tid & 15, kxm = tid >> 4;
    const float2* zb = Z + (size_t)b*NC*NKX*NM;

    float2 t1 = make_float2(0.f, 0.f);
    float2 t2 = make_float2(0.f, 0.f);
#pragma unroll 4
    for (int i = 0; i < NC; i++) {
        float2 z1 = zb[i*NKX*NM + kxm*NM + ky];
        float2 z2 = zb[i*NKX*NM + (kxm+16)*NM + ky];
        float2 wv1 = w1c[((i*32 + o)*16 + kxm)*16 + ky];
        float2 wv2 = w2c[((i*32 + o)*16 + kxm)*16 + ky];
        t1 = ffma2(make_float2(z1.x, z1.x), wv1, t1);
        t1 = ffma2(make_float2(z1.y, z1.y), make_float2(-wv1.y, wv1.x), t1);
        t2 = ffma2(make_float2(z2.x, z2.x), wv2, t2);
        t2 = ffma2(make_float2(z2.y, z2.y), make_float2(-wv2.y, wv2.x), t2);
    }
    Ts[kxm*16 + ky]      = t1;
    Ts[(kxm+16)*16 + ky] = t2;
    __syncthreads();

    int h = tid;
    float2 acc[NM];
#pragma unroll
    for (int k = 0; k < NM; k++) acc[k] = make_float2(0.f, 0.f);
#pragma unroll 2
    for (int kx = 0; kx < NKX; kx++) {
        int fr = (kx < 16) ? kx : (kx - 32);
        float2 e = cis_m(fr * h);
        float2 en = make_float2(-e.y, e.x);
#pragma unroll
        for (int k = 0; k < NM; k++) {
            float2 t = Ts[kx*16 + k];
            acc[k] = ffma2(make_float2(t.x, t.x), e,  acc[k]);
            acc[k] = ffma2(make_float2(t.y, t.y), en, acc[k]);
        }
    }
    float4* gp = (float4*)(G + ((b*NC + o)*NH + h)*NM);
    const float s2 = 2.0f / 65536.0f;
#pragma unroll
    for (int k = 0; k < 8; k++) {
        float s0 = (k == 0) ? (1.0f/65536.0f) : s2;
        gp[k] = make_float4(acc[2*k].x*s0, acc[2*k].y*s0, acc[2*k+1].x*s2, acc[2*k+1].y*s2);
    }
}

// ---------------- fused layer row kernel v7 ----------------
struct LArg {
    const float2* G;
    const float*  cw;
    const float*  cb;
    const float*  skip;   // nullptr = no skip
    float*        out;
    int           writeY;
};

// smem: g4[0,4096) | cwq[4096,8192) | cb2[8192,8320) | cs_a[8320,16768)
//       | cs_b[16768,25216) | xrow/orow[25216,58496)
static const int ROW_SM = 58496;
__global__ void __launch_bounds__(256, 3) layer_kernel(
        const float* __restrict__ xin0, const float* __restrict__ xin1,
        float2* __restrict__ Ynext, LArg a0, LArg a1) {
    extern __shared__ unsigned char sm[];
    float4* g4   = (float4*)sm;
    float4* cwq  = (float4*)(sm + 4096);
    float2* cb2  = (float2*)(sm + 8192);
    float4* cs_a = (float4*)(sm + 8320);
    float4* cs_b = (float4*)(sm + 16768);
    float*  xrowf = (float*)(sm + 25216);    // [c][260]; aliased by orow after conv
    float2* orow  = (float2*)(sm + 25216);   // [p][258] folded

    int sub = blockIdx.x >> 11;
    int bid = blockIdx.x & 2047;
    const LArg la = sub ? a1 : a0;
    const float* xin = sub ? xin1 : xin0;

    int b = bid >> 8, h = bid & 255, tid = threadIdx.x;

    gen_cs(cs_a, cs_b, tid);
    stage_layer(g4, cwq, cb2, xrowf, xin, la.G, la.cw, la.cb, b, h, tid);
    __syncthreads();

    int u5 = tid & 31, pg = tid >> 5;
    float2 acc[16];
    compute_vals(g4, cwq, cb2, cs_a, cs_b, xrowf, u5, pg, acc);

    // gelu
#pragma unroll
    for (int k = 0; k < 16; k++) {
        acc[k].x = gelu_f(acc[k].x);
        acc[k].y = gelu_f(acc[k].y);
    }
    // skip + global stores: 4 channels x (lo,hi) float4
#pragma unroll
    for (int j = 0; j < 2; j++) {
#pragma unroll
        for (int k = 0; k < 2; k++) {
            int ch = 4*pg + 2*j + k;
            int base = ((b*NC + ch)*NH + h)*NW;
            float4 lo, hi;
            if (k == 0) {
                lo = make_float4(acc[j*8+0].x, acc[j*8+1].x, acc[j*8+2].x, acc[j*8+3].x);
                hi = make_float4(acc[j*8+4].x, acc[j*8+5].x, acc[j*8+6].x, acc[j*8+7].x);
            } else {
                lo = make_float4(acc[j*8+0].y, acc[j*8+1].y, acc[j*8+2].y, acc[j*8+3].y);
                hi = make_float4(acc[j*8+4].y, acc[j*8+5].y, acc[j*8+6].y, acc[j*8+7].y);
            }
            if (la.skip) {
                float4 slo = *(const float4*)(la.skip + base + 4*u5);
                float4 shi = *(const float4*)(la.skip + base + 128 + 4*u5);
                lo.x += slo.x; lo.y += slo.y; lo.z += slo.z; lo.w += slo.w;
                hi.x += shi.x; hi.y += shi.y; hi.z += shi.z; hi.w += shi.w;
                // write back into acc for writeY path
                if (k == 0) {
                    acc[j*8+0].x = lo.x; acc[j*8+1].x = lo.y; acc[j*8+2].x = lo.z; acc[j*8+3].x = lo.w;
                    acc[j*8+4].x = hi.x; acc[j*8+5].x = hi.y; acc[j*8+6].x = hi.z; acc[j*8+7].x = hi.w;
                } else {
                    acc[j*8+0].y = lo.x; acc[j*8+1].y = lo.y; acc[j*8+2].y = lo.z; acc[j*8+3].y = lo.w;
                    acc[j*8+4].y = hi.x; acc[j*8+5].y = hi.y; acc[j*8+6].y = hi.z; acc[j*8+7].y = hi.w;
                }
            }
            *(float4*)(la.out + base + 4*u5)       = lo;
            *(float4*)(la.out + base + 128 + 4*u5) = hi;
        }
    }

    if (la.writeY) {
        __syncthreads();   // all conv reads of xrow done before orow overwrite
#pragma unroll
        for (int j = 0; j < 2; j++) {
            int p = 2*pg + j;
            float2 s0 = make_float2(acc[j*8+0].x + acc[j*8+4].x, acc[j*8+0].y + acc[j*8+4].y);
            float2 s1 = make_float2(acc[j*8+1].x + acc[j*8+5].x, acc[j*8+1].y + acc[j*8+5].y);
            float2 s2 = make_float2(acc[j*8+2].x + acc[j*8+6].x, acc[j*8+2].y + acc[j*8+6].y);
            float2 s3 = make_float2(acc[j*8+3].x + acc[j*8+7].x, acc[j*8+3].y + acc[j*8+7].y);
            float2 d0 = make_float2(acc[j*8+0].x - acc[j*8+4].x, acc[j*8+0].y - acc[j*8+4].y);
            float2 d1 = make_float2(acc[j*8+1].x - acc[j*8+5].x, acc[j*8+1].y - acc[j*8+5].y);
            float2 d2 = make_float2(acc[j*8+2].x - acc[j*8+6].x, acc[j*8+2].y - acc[j*8+6].y);
            float2 d3 = make_float2(acc[j*8+3].x - acc[j*8+7].x, acc[j*8+3].y - acc[j*8+7].y);
            *(float4*)(orow + p*258 + 4*u5)           = make_float4(s0.x, s0.y, s1.x, s1.y);
            *(float4*)(orow + p*258 + 4*u5 + 2)       = make_float4(s2.x, s2.y, s3.x, s3.y);
            *(float4*)(orow + p*258 + 128 + 4*u5)     = make_float4(d0.x, d0.y, d1.x, d1.y);
            *(float4*)(orow + p*258 + 128 + 4*u5 + 2) = make_float4(d2.x, d2.y, d3.x, d3.y);
        }
        __syncthreads();
        fwd_dft(orow, cs_a, cs_b, Ynext, b, h, tid);
    }
}

// ---------------- L5 + head fused kernel ----------------
// smem: layer regions [0,58496) | w1s[58496,74880) | w2p[74880,77952) | b1s[77952,78464) | b2s[78464,78496)
static const int HEAD5_SM = 78496;
__global__ void __launch_bounds__(256, 2) layer5_head_kernel(
        const float* __restrict__ xin, LArg a0,
        const float* __restrict__ fw1, const float* __restrict__ fb1,
        const float* __restrict__ fw2, const float* __restrict__ fb2,
        float* __restrict__ out) {
    extern __shared__ unsigned char sm[];
    float4* g4   = (float4*)sm;
    float4* cwq  = (float4*)(sm + 4096);
    float2* cb2  = (float2*)(sm + 8192);
    float4* cs_a = (float4*)(sm + 8320);
    float4* cs_b = (float4*)(sm + 16768);
    float*  xrowf = (float*)(sm + 25216);     // [c][260]; aliased by vrow
    float*  vrow  = (float*)(sm + 25216);     // [c][260]
    float*  w1s  = (float*)(sm + 58496);
    float2* w2p  = (float2*)(sm + 74880);
    float*  b1s  = (float*)(sm + 77952);
    float*  b2s  = (float*)(sm + 78464);

    int b = blockIdx.x >> 8, h = blockIdx.x & 255, tid = threadIdx.x;

    gen_cs(cs_a, cs_b, tid);
    stage_layer(g4, cwq, cb2, xrowf, xin, a0.G, a0.cw, a0.cb, b, h, tid);
    for (int k = tid; k < 4096; k += 256) w1s[k] = fw1[k];
    if (tid < 128) {
        b1s[tid] = fb1[tid];
        w2p[tid*3 + 0] = make_float2(fw2[tid*5 + 0], fw2[tid*5 + 1]);
        w2p[tid*3 + 1] = make_float2(fw2[tid*5 + 2], fw2[tid*5 + 3]);
        w2p[tid*3 + 2] = make_float2(fw2[tid*5 + 4], 0.0f);
    }
    if (tid < 5) b2s[tid] = fb2[tid];
    __syncthreads();

    int u5 = tid & 31, pg = tid >> 5;
    float2 acc[16];
    compute_vals(g4, cwq, cb2, cs_a, cs_b, xrowf, u5, pg, acc);

    // gelu + skip (always present)
#pragma unroll
    for (int k = 0; k < 16; k++) {
        acc[k].x = gelu_f(acc[k].x);
        acc[k].y = gelu_f(acc[k].y);
    }
#pragma unroll
    for (int j = 0; j < 2; j++) {
#pragma unroll
        for (int k = 0; k < 2; k++) {
            int ch = 4*pg + 2*j + k;
            int base = ((b*NC + ch)*NH + h)*NW;
            float4 slo = *(const float4*)(a0.skip + base + 4*u5);
            float4 shi = *(const float4*)(a0.skip + base + 128 + 4*u5);
            if (k == 0) {
                acc[j*8+0].x += slo.x; acc[j*8+1].x += slo.y; acc[j*8+2].x += slo.z; acc[j*8+3].x += slo.w;
                acc[j*8+4].x += shi.x; acc[j*8+5].x += shi.y; acc[j*8+6].x += shi.z; acc[j*8+7].x += shi.w;
            } else {
                acc[j*8+0].y += slo.x; acc[j*8+1].y += slo.y; acc[j*8+2].y += slo.z; acc[j*8+3].y += slo.w;
                acc[j*8+4].y += shi.x; acc[j*8+5].y += shi.y; acc[j*8+6].y += shi.z; acc[j*8+7].y += shi.w;
            }
        }
    }

    __syncthreads();   // conv reads done -> safe to overwrite xrow with vrow
#pragma unroll
    for (int j = 0; j < 2; j++) {
#pragma unroll
        for (int k = 0; k < 2; k++) {
            int ch = 4*pg + 2*j + k;
            float4 lo, hi;
            if (k == 0) {
                lo = make_float4(acc[j*8+0].x, acc[j*8+1].x, acc[j*8+2].x, acc[j*8+3].x);
                hi = make_float4(acc[j*8+4].x, acc[j*8+5].x, acc[j*8+6].x, acc[j*8+7].x);
            } else {
                lo = make_float4(acc[j*8+0].y, acc[j*8+1].y, acc[j*8+2].y, acc[j*8+3].y);
                hi = make_float4(acc[j*8+4].y, acc[j*8+5].y, acc[j*8+6].y, acc[j*8+7].y);
            }
            *(float4*)(vrow + ch*260 + 4*u5)       = lo;
            *(float4*)(vrow + ch*260 + 128 + 4*u5) = hi;
        }
    }
    __syncthreads();

    // head: fc1 + GELU + fc2 for w = tid
    int w = tid;
    float2 o01 = make_float2(b2s[0], b2s[1]);
    float2 o23 = make_float2(b2s[2], b2s[3]);
    float2 o4z = make_float2(b2s[4], 0.0f);
    const float4* w1q = (const float4*)w1s;
    const float2* b1p = (const float2*)b1s;

#pragma unroll 1
    for (int q = 0; q < 4; q++) {
        float2 hacc[16];
#pragma unroll
        for (int jj = 0; jj < 16; jj++) hacc[jj] = b1p[q*16 + jj];
#pragma unroll 4
        for (int c = 0; c < NC; c++) {
            float xv = vrow[c*260 + w];
            float2 xv2 = make_float2(xv, xv);
#pragma unroll
            for (int j8 = 0; j8 < 8; j8++) {
                float4 w4 = w1q[c*32 + q*8 + j8];
                hacc[2*j8    ] = ffma2(xv2, make_float2(w4.x, w4.y), hacc[2*j8    ]);
                hacc[2*j8 + 1] = ffma2(xv2, make_float2(w4.z, w4.w), hacc[2*j8 + 1]);
            }
        }
#pragma unroll
        for (int jj = 0; jj < 16; jj++) {
            int j = 32*q + 2*jj;
            float h0 = gelu_f(hacc[jj].x);
            float h1 = gelu_f(hacc[jj].y);
            float2 h02 = make_float2(h0, h0), h12 = make_float2(h1, h1);
            o01 = ffma2(h02, w2p[j*3 + 0], o01);
            o23 = ffma2(h02, w2p[j*3 + 1], o23);
            o4z = ffma2(h02, w2p[j*3 + 2], o4z);
            o01 = ffma2(h12, w2p[(j+1)*3 + 0], o01);
            o23 = ffma2(h12, w2p[(j+1)*3 + 1], o23);
            o4z = ffma2(h12, w2p[(j+1)*3 + 2], o4z);
        }
    }
    float* op = out + (((b*NH) + h)*NW + w) * 5;
    op[0] = o01.x; op[1] = o01.y; op[2] = o23.x; op[3] = o23.y; op[4] = o4z.x;
}

// ---------------- host launcher ----------------
extern "C" void kernel_launch(void* const* d_in, const int* in_sizes, int n_in,
                              void* d_out, int out_size) {
    const float* x     = (const float*)d_in[0];
    const float* fc0w  = (const float*)d_in[1];
    const float* fc0b  = (const float*)d_in[2];
    const float* w1    = (const float*)d_in[3];
    const float* w2    = (const float*)d_in[4];
    const float* convw = (const float*)d_in[5];
    const float* convb = (const float*)d_in[6];
    const float* fc1w  = (const float*)d_in[7];
    const float* fc1b  = (const float*)d_in[8];
    const float* fc2w  = (const float*)d_in[9];
    const float* fc2b  = (const float*)d_in[10];
    float* out = (float*)d_out;

    float  *bufA, *bufB, *bufC;
    float2 *Y, *Z, *G0, *G1;
    cudaGetSymbolAddress((void**)&bufA, g_bufA);
    cudaGetSymbolAddress((void**)&bufB, g_bufB);
    cudaGetSymbolAddress((void**)&bufC, g_bufC);
    cudaGetSymbolAddress((void**)&Y, g_Y);
    cudaGetSymbolAddress((void**)&Z, g_Zb);
    cudaGetSymbolAddress((void**)&G0, g_G);
    cudaGetSymbolAddress((void**)&G1, g_G2);

    cudaFuncSetAttribute(lift_kernel,       cudaFuncAttributeMaxDynamicSharedMemorySize, LIFT_SM);
    cudaFuncSetAttribute(k2a_kernel,        cudaFuncAttributeMaxDynamicSharedMemorySize, K2A_SM);
    cudaFuncSetAttribute(layer_kernel,      cudaFuncAttributeMaxDynamicSharedMemorySize, ROW_SM);
    cudaFuncSetAttribute(layer5_head_kernel,cudaFuncAttributeMaxDynamicSharedMemorySize, HEAD5_SM);

    const float* w1p[6]; const float* w2p_[6]; const float* cwp[6]; const float* cbp[6];
    for (int l = 0; l < 6; l++) {
        w1p[l]  = w1 + (size_t)l * WSZ;
        w2p_[l] = w2 + (size_t)l * WSZ;
        cwp[l]  = convw + l * 32 * 32;
        cbp[l]  = convb + l * 32;
    }

    // DAG:  h0 = L0(lift); t1 = L1(lift); t2 = L2(t1) + h0;
    //       h1 = L3(t2);   t4 = L4(t2);   out = head(L5(t4) + h1);
    lift_kernel<<<NB*NH, 256, LIFT_SM>>>(x, fc0w, fc0b, bufA, Y);   // A = lift, Y_lift

    // L0 + L1 (share Z of Y_lift)
    k2a_kernel<<<NB*NC, 512, K2A_SM>>>(Y, Z);
    k2bc_kernel<<<2*NB*NC, 256>>>(Z, w1p[0], w2p_[0], G0, w1p[1], w2p_[1], G1);
    {
        LArg a0 = { G0, cwp[0], cbp[0], nullptr, bufB, 0 };   // h0
        LArg a1 = { G1, cwp[1], cbp[1], nullptr, bufC, 1 };   // t1 (+Y_t1)
        layer_kernel<<<2*NB*NH, 256, ROW_SM>>>(bufA, bufA, Y, a0, a1);
    }

    // L2
    k2a_kernel<<<NB*NC, 512, K2A_SM>>>(Y, Z);
    k2bc_kernel<<<NB*NC, 256>>>(Z, w1p[2], w2p_[2], G0, w1p[2], w2p_[2], G0);
    {
        LArg a = { G0, cwp[2], cbp[2], bufB, bufA, 1 };       // t2 (+Y_t2)
        layer_kernel<<<NB*NH, 256, ROW_SM>>>(bufC, bufC, Y, a, a);
    }

    // L3 + L4 (share Z of Y_t2)
    k2a_kernel<<<NB*NC, 512, K2A_SM>>>(Y, Z);
    k2bc_kernel<<<2*NB*NC, 256>>>(Z, w1p[3], w2p_[3], G0, w1p[4], w2p_[4], G1);
    {
        LArg a0 = { G0, cwp[3], cbp[3], nullptr, bufB, 0 };   // h1
        LArg a1 = { G1, cwp[4], cbp[4], nullptr, bufC, 1 };   // t4 (+Y_t4)
        layer_kernel<<<2*NB*NH, 256, ROW_SM>>>(bufA, bufA, Y, a0, a1);
    }

    // L5 + head fused
    k2a_kernel<<<NB*NC, 512, K2A_SM>>>(Y, Z);
    k2bc_kernel<<<NB*NC, 256>>>(Z, w1p[5], w2p_[5], G0, w1p[5], w2p_[5], G0);
    {
        LArg a = { G0, cwp[5], cbp[5], bufB, nullptr, 0 };    // final (consumed in-kernel)
        layer5_head_kernel<<<NB*NH, 256, HEAD5_SM>>>(bufC, a, fc1w, fc1b, fc2w, fc2b, out);
    }
}

// round 14
// speedup vs baseline: 1.7757x; 1.0025x over previous
#include <cuda_runtime.h>
#include <math.h>

// ---------------- problem constants ----------------
#define NB 8
#define NC 32
#define NH 256
#define NW 256
#define NM 16
#define NKX 32
#define WSZ (32*32*16*16*2)

// ---------------- device scratch ----------------
__device__ float  g_bufA[NB*NC*NH*NW];
__device__ float  g_bufB[NB*NC*NH*NW];
__device__ float  g_bufC[NB*NC*NH*NW];
__device__ float2 g_Y[NB*NC*NH*NM];
__device__ float2 g_Zb[NB*NC*NKX*NM];
__device__ float2 g_G[NB*NC*NH*NM];
__device__ float2 g_G2[NB*NC*NH*NM];

// ---------------- helpers ----------------
__device__ __forceinline__ float2 ffma2(float2 a, float2 b, float2 c) {
    float2 d;
    asm("fma.rn.f32x2 %0, %1, %2, %3;"
        : "=l"(reinterpret_cast<unsigned long long&>(d))
        : "l"(reinterpret_cast<unsigned long long&>(a)),
          "l"(reinterpret_cast<unsigned long long&>(b)),
          "l"(reinterpret_cast<unsigned long long&>(c)));
    return d;
}
__device__ __forceinline__ float2 cis_m(int m) {
    float a = (float)(m & 255) * (1.0f/128.0f);
    return make_float2(cospif(a), sinpif(a));
}
// branch-free GELU (Abramowitz-Stegun erf, |err| < 1.5e-7)
__device__ __forceinline__ float gelu_f(float v) {
    float u = fabsf(v) * 0.7071067811865476f;
    float t = __frcp_rn(fmaf(0.3275911f, u, 1.0f));
    float p = t * fmaf(t, fmaf(t, fmaf(t, fmaf(t, 1.061405429f, -1.453152027f),
                                       1.421413741f), -0.284496736f), 0.254829592f);
    float e = __expf(-u * u);
    float erfv = copysignf(fmaf(-p, e, 1.0f), v);
    return 0.5f * v * (1.0f + erfv);
}

// split twiddle tables: cs_a[ky*33+u5] = e(ky,4u5), e(ky,4u5+1); cs_b: +2, +3
__device__ __forceinline__ void gen_cs(float4* cs_a, float4* cs_b, int tid) {
#pragma unroll
    for (int k = tid; k < 512; k += 256) {
        int ky = k >> 5, u5 = k & 31;
        float2 e0 = cis_m(ky * (4*u5    ));
        float2 e1 = cis_m(ky * (4*u5 + 1));
        float2 e2 = cis_m(ky * (4*u5 + 2));
        float2 e3 = cis_m(ky * (4*u5 + 3));
        cs_a[ky*33 + u5] = make_float4(e0.x, e0.y, e1.x, e1.y);
        cs_b[ky*33 + u5] = make_float4(e2.x, e2.y, e3.x, e3.y);
    }
}

// folded forward W-DFT: orow float2[16][258]; [p][w<128]=v(w)+v(w+128), [p][128+w]=v(w)-v(w+128)
__device__ __forceinline__ void fwd_dft(const float2* orow,
                                        const float4* cs_a, const float4* cs_b,
                                        float2* __restrict__ Y, int b, int h, int tid) {
    int q  = tid >> 4;
    int ky = tid & 15;
    float2 yr = make_float2(0.f, 0.f);
    float2 yi = make_float2(0.f, 0.f);
    const float4* op = (const float4*)(orow + q*258 + ((ky & 1) ? 128 : 0));
    const float4* ea = cs_a + ky*33;
    const float4* eb = cs_b + ky*33;
#pragma unroll 8
    for (int t = 0; t < 32; t++) {
        float4 o0 = op[2*t], o1 = op[2*t + 1];
        float4 e4a = ea[t],  e4b = eb[t];
        yr = ffma2(make_float2(o0.x, o0.y), make_float2(e4a.x,  e4a.x), yr);
        yi = ffma2(make_float2(o0.x, o0.y), make_float2(-e4a.y, -e4a.y), yi);
        yr = ffma2(make_float2(o0.z, o0.w), make_float2(e4a.z,  e4a.z), yr);
        yi = ffma2(make_float2(o0.z, o0.w), make_float2(-e4a.w, -e4a.w), yi);
        yr = ffma2(make_float2(o1.x, o1.y), make_float2(e4b.x,  e4b.x), yr);
        yi = ffma2(make_float2(o1.x, o1.y), make_float2(-e4b.y, -e4b.y), yi);
        yr = ffma2(make_float2(o1.z, o1.w), make_float2(e4b.z,  e4b.z), yr);
        yi = ffma2(make_float2(o1.z, o1.w), make_float2(-e4b.w, -e4b.w), yi);
    }
    Y[((b*NC + 2*q    )*NH + h)*NM + ky] = make_float2(yr.x, yi.x);
    Y[((b*NC + 2*q + 1)*NH + h)*NM + ky] = make_float2(yr.y, yi.y);
}

// ---------------- shared conv + spectral-synthesis core v8 ----------------
// thread: u5 = tid&31 -> w in {4u5..4u5+3} (+128 fold); pg = tid>>5 -> pairs {2pg, 2pg+1}.
// Synthesis FIRST (ky-outer, both pairs share each twiddle load), then conv adds.
// acc[j*8+wp]: j=pair, wp 0..3 = w 4u5+wp, wp 4..7 = +128.  float2 = (ch 2p, ch 2p+1).
__device__ __forceinline__ void compute_vals(
        const float4* g4, const float4* cwq, const float2* cb2,
        const float4* cs_a, const float4* cs_b,
        const float* xrowf, int u5, int pg, float2* acc) {
    float2 P[8], Q[8];
#pragma unroll
    for (int k = 0; k < 8; k++) {
        P[k] = make_float2(0.f, 0.f);
        Q[k] = make_float2(0.f, 0.f);
    }
#pragma unroll
    for (int ky = 0; ky < NM; ky++) {
        float4 ea = cs_a[ky*33 + u5];
        float4 eb = cs_b[ky*33 + u5];
        if ((ky & 1) == 0) {
#pragma unroll
            for (int j = 0; j < 2; j++) {
                float4 g  = g4[(2*pg + j)*16 + ky];
                float2 gr = make_float2(g.x, g.y), gi = make_float2(g.z, g.w);
                P[j*4+0] = ffma2(gr, make_float2(ea.x, ea.x),   P[j*4+0]);
                P[j*4+0] = ffma2(gi, make_float2(-ea.y, -ea.y), P[j*4+0]);
                P[j*4+1] = ffma2(gr, make_float2(ea.z, ea.z),   P[j*4+1]);
                P[j*4+1] = ffma2(gi, make_float2(-ea.w, -ea.w), P[j*4+1]);
                P[j*4+2] = ffma2(gr, make_float2(eb.x, eb.x),   P[j*4+2]);
                P[j*4+2] = ffma2(gi, make_float2(-eb.y, -eb.y), P[j*4+2]);
                P[j*4+3] = ffma2(gr, make_float2(eb.z, eb.z),   P[j*4+3]);
                P[j*4+3] = ffma2(gi, make_float2(-eb.w, -eb.w), P[j*4+3]);
            }
        } else {
#pragma unroll
            for (int j = 0; j < 2; j++) {
                float4 g  = g4[(2*pg + j)*16 + ky];
                float2 gr = make_float2(g.x, g.y), gi = make_float2(g.z, g.w);
                Q[j*4+0] = ffma2(gr, make_float2(ea.x, ea.x),   Q[j*4+0]);
                Q[j*4+0] = ffma2(gi, make_float2(-ea.y, -ea.y), Q[j*4+0]);
                Q[j*4+1] = ffma2(gr, make_float2(ea.z, ea.z),   Q[j*4+1]);
                Q[j*4+1] = ffma2(gi, make_float2(-ea.w, -ea.w), Q[j*4+1]);
                Q[j*4+2] = ffma2(gr, make_float2(eb.x, eb.x),   Q[j*4+2]);
                Q[j*4+2] = ffma2(gi, make_float2(-eb.y, -eb.y), Q[j*4+2]);
                Q[j*4+3] = ffma2(gr, make_float2(eb.z, eb.z),   Q[j*4+3]);
                Q[j*4+3] = ffma2(gi, make_float2(-eb.w, -eb.w), Q[j*4+3]);
            }
        }
    }
#pragma unroll
    for (int j = 0; j < 2; j++) {
        float2 bias = cb2[2*pg + j];
#pragma unroll
        for (int t = 0; t < 4; t++) {
            acc[j*8+t]     = make_float2(bias.x + P[j*4+t].x + Q[j*4+t].x,
                                         bias.y + P[j*4+t].y + Q[j*4+t].y);
            acc[j*8+4+t]   = make_float2(bias.x + P[j*4+t].x - Q[j*4+t].x,
                                         bias.y + P[j*4+t].y - Q[j*4+t].y);
        }
    }
    // 1x1 conv adds on top
#pragma unroll 4
    for (int c = 0; c < NC; c++) {
        float4 xa = *(const float4*)(xrowf + c*260 + 4*u5);
        float4 xb = *(const float4*)(xrowf + c*260 + 128 + 4*u5);
        float4 w4 = cwq[c*8 + pg];
        float2 wj0 = make_float2(w4.x, w4.y), wj1 = make_float2(w4.z, w4.w);
        acc[0]  = ffma2(make_float2(xa.x, xa.x), wj0, acc[0]);
        acc[1]  = ffma2(make_float2(xa.y, xa.y), wj0, acc[1]);
        acc[2]  = ffma2(make_float2(xa.z, xa.z), wj0, acc[2]);
        acc[3]  = ffma2(make_float2(xa.w, xa.w), wj0, acc[3]);
        acc[4]  = ffma2(make_float2(xb.x, xb.x), wj0, acc[4]);
        acc[5]  = ffma2(make_float2(xb.y, xb.y), wj0, acc[5]);
        acc[6]  = ffma2(make_float2(xb.z, xb.z), wj0, acc[6]);
        acc[7]  = ffma2(make_float2(xb.w, xb.w), wj0, acc[7]);
        acc[8]  = ffma2(make_float2(xa.x, xa.x), wj1, acc[8]);
        acc[9]  = ffma2(make_float2(xa.y, xa.y), wj1, acc[9]);
        acc[10] = ffma2(make_float2(xa.z, xa.z), wj1, acc[10]);
        acc[11] = ffma2(make_float2(xa.w, xa.w), wj1, acc[11]);
        acc[12] = ffma2(make_float2(xb.x, xb.x), wj1, acc[12]);
        acc[13] = ffma2(make_float2(xb.y, xb.y), wj1, acc[13]);
        acc[14] = ffma2(make_float2(xb.z, xb.z), wj1, acc[14]);
        acc[15] = ffma2(make_float2(xb.w, xb.w), wj1, acc[15]);
    }
}

// shared prologue staging (layer kernels); xrowf stride 260
__device__ __forceinline__ void stage_layer(
        float4* g4, float4* cwq, float2* cb2, float* xrowf,
        const float* xin, const float2* G, const float* cw, const float* cb,
        int b, int h, int tid) {
    for (int c = 0; c < NC; c++) xrowf[c*260 + tid] = xin[((b*NC + c)*NH + h)*NW + tid];
    {
        int c = tid >> 3, p2 = tid & 7;
        cwq[tid] = make_float4(cw[(4*p2+0)*32+c], cw[(4*p2+1)*32+c],
                               cw[(4*p2+2)*32+c], cw[(4*p2+3)*32+c]);
    }
    if (tid < 16) cb2[tid] = make_float2(cb[2*tid], cb[2*tid+1]);
    {
        int p = tid >> 4, ky = tid & 15;
        float2 ga = G[((b*NC + 2*p    )*NH + h)*NM + ky];
        float2 gb = G[((b*NC + 2*p + 1)*NH + h)*NM + ky];
        g4[p*16 + ky] = make_float4(ga.x, gb.x, ga.y, gb.y);
    }
}

// ---------------- lift ----------------
// smem: cs_a[0,8448) | cs_b[8448,16896) | orow[16896,49920) | w0s[49920,51456)
//       | b0s[51456,51584) | xstage[51584,61824)
static const int LIFT_SM = 61824;
__global__ void __launch_bounds__(256) lift_kernel(
        const float* __restrict__ x, const float* __restrict__ w0,
        const float* __restrict__ b0, float* __restrict__ out, float2* __restrict__ Y) {
    extern __shared__ unsigned char sm[];
    float4* cs_a = (float4*)sm;
    float4* cs_b = (float4*)(sm + 8448);
    float2* orow = (float2*)(sm + 16896);
    float*  w0s  = (float*)(sm + 49920);
    float*  b0s  = (float*)(sm + 51456);
    float*  xst  = (float*)(sm + 51584);
    float*  orowf = (float*)orow;

    int b = blockIdx.x >> 8, h = blockIdx.x & 255, tid = threadIdx.x;

    gen_cs(cs_a, cs_b, tid);
    for (int k = tid; k < 384; k += 256) w0s[k] = w0[k];
    if (tid < 32) b0s[tid] = b0[tid];
    {   // stage x row [256 w][10] via coalesced float4 loads
        const float4* xp4 = (const float4*)(x + (size_t)((b*NH) + h) * NW * 10);
        float4* xs4 = (float4*)xst;
        for (int k = tid; k < 640; k += 256) xs4[k] = xp4[k];
    }
    __syncthreads();

    int w = tid;
    float xv[10];
#pragma unroll
    for (int t = 0; t < 10; t++) xv[t] = xst[w*10 + t];
    float gx = (float)h * (1.0f/255.0f);
    float gy = (float)w * (1.0f/255.0f);

    for (int c = 0; c < NC; c++) {
        float acc = b0s[c];
#pragma unroll
        for (int t = 0; t < 10; t++) acc = fmaf(xv[t], w0s[t*32 + c], acc);
        acc = fmaf(gx, w0s[10*32 + c], acc);
        acc = fmaf(gy, w0s[11*32 + c], acc);
        out[((b*NC + c)*NH + h)*NW + w] = acc;
        orowf[(c >> 1)*516 + 2*w + (c & 1)] = acc;
    }
    __syncthreads();
    {   // fold w / w+128
        int wl = tid & 127, half = tid >> 7;
#pragma unroll
        for (int pp = 0; pp < 8; pp++) {
            int p = half*8 + pp;
            float2 a = orow[p*258 + wl];
            float2 c = orow[p*258 + 128 + wl];
            orow[p*258 + wl]       = make_float2(a.x + c.x, a.y + c.y);
            orow[p*258 + 128 + wl] = make_float2(a.x - c.x, a.y - c.y);
        }
    }
    __syncthreads();
    fwd_dft(orow, cs_a, cs_b, Y, b, h, tid);
}

// ---------------- k2a: H-DFT  Y -> Z ----------------
static const int K2A_SM = 32768 + 65536;
__global__ void __launch_bounds__(512, 2) k2a_kernel(
        const float2* __restrict__ Y, float2* __restrict__ Z) {
    extern __shared__ unsigned char sm[];
    float2* Ys  = (float2*)sm;
    float2* E1s = (float2*)(sm + 32768);

    int b = blockIdx.x >> 5, i = blockIdx.x & 31, tid = threadIdx.x;
    {
        const float4* src = (const float4*)(Y + (b*NC + i)*NH*NM);
        float4* dst = (float4*)Ys;
        for (int k = tid; k < 2048; k += 512) dst[k] = src[k];
    }
#pragma unroll
    for (int k = tid; k < NH*NKX; k += 512) {
        int h = k >> 5, kx = k & 31;
        int fr = (kx < 16) ? kx : (kx - 32);
        float2 e = cis_m(fr * h);
        E1s[k] = make_float2(e.x, -e.y);
    }
    __syncthreads();

    int kx = tid >> 4, ky = tid & 15;
    float2 z = make_float2(0.f, 0.f);
#pragma unroll 4
    for (int h = 0; h < NH; h++) {
        float2 e = E1s[h*NKX + kx];
        float2 y = Ys[h*NM + ky];
        z = ffma2(make_float2(y.x, y.x), e, z);
        z = ffma2(make_float2(y.y, y.y), make_float2(-e.y, e.x), z);
    }
    Z[((b*NC + i)*NKX + kx)*NM + ky] = z;
}

// ---------------- k2bc v3: 512 threads — channel mix + inverse H-DFT, dual weight-set ----------------
// grid = 256 (single) or 512 (pair). sub = blockIdx.x >> 8 selects weight set.
// phase 1: one (kx,ky) per thread.  phase 2: 2 threads per h, 8 ky each.
__global__ void __launch_bounds__(512) k2bc_kernel(
        const float2* __restrict__ Z,
        const float* __restrict__ w1a, const float* __restrict__ w2a, float2* __restrict__ Ga,
        const float* __restrict__ w1b, const float* __restrict__ w2b, float2* __restrict__ Gb) {
    __shared__ float2 Ts[NKX*NM];

    int sub = blockIdx.x >> 8, bid = blockIdx.x & 255;
    const float2* w1c = (const float2*)(sub ? w1b : w1a);
    const float2* w2c = (const float2*)(sub ? w2b : w2a);
    float2* G = sub ? Gb : Ga;

    int b = bid >> 5, o = bid & 31, tid = threadIdx.x;

    {   // phase 1
        int kx = tid >> 4, ky = tid & 15, kxm = kx & 15;
        const float2* wc = (kx < 16) ? w1c : w2c;
        const float2* zb = Z + (size_t)b*NC*NKX*NM;
        float2 t = make_float2(0.f, 0.f);
#pragma unroll 8
        for (int i = 0; i < NC; i++) {
            float2 z = zb[i*NKX*NM + kx*NM + ky];
            float2 wv = wc[((i*32 + o)*16 + kxm)*16 + ky];
            t = ffma2(make_float2(z.x, z.x), wv, t);
            t = ffma2(make_float2(z.y, z.y), make_float2(-wv.y, wv.x), t);
        }
        Ts[kx*16 + ky] = t;
    }
    __syncthreads();

    // phase 2: inverse H-DFT; thread = (h, half), half covers ky 8*half..8*half+7
    int h = tid & 255, half = tid >> 8;
    float2 acc[8];
#pragma unroll
    for (int k = 0; k < 8; k++) acc[k] = make_float2(0.f, 0.f);
#pragma unroll 4
    for (int kx = 0; kx < NKX; kx++) {
        int fr = (kx < 16) ? kx : (kx - 32);
        float2 e = cis_m(fr * h);
        float2 en = make_float2(-e.y, e.x);
        const float2* tp = Ts + kx*16 + half*8;
#pragma unroll
        for (int k = 0; k < 8; k++) {
            float2 t = tp[k];
            acc[k] = ffma2(make_float2(t.x, t.x), e,  acc[k]);
            acc[k] = ffma2(make_float2(t.y, t.y), en, acc[k]);
        }
    }
    float4* gp = (float4*)(G + ((b*NC + o)*NH + h)*NM + half*8);
    const float s2 = 2.0f / 65536.0f;
#pragma unroll
    for (int k = 0; k < 4; k++) {
        float sA = (half == 0 && k == 0) ? (1.0f/65536.0f) : s2;
        gp[k] = make_float4(acc[2*k].x*sA, acc[2*k].y*sA, acc[2*k+1].x*s2, acc[2*k+1].y*s2);
    }
}

// ---------------- fused layer row kernel v8 ----------------
struct LArg {
    const float2* G;
    const float*  cw;
    const float*  cb;
    const float*  skip;   // nullptr = no skip
    float*        out;
    int           writeY;
};

// smem: g4[0,4096) | cwq[4096,8192) | cb2[8192,8320) | cs_a[8320,16768)
//       | cs_b[16768,25216) | xrow/orow[25216,58496)
static const int ROW_SM = 58496;
__global__ void __launch_bounds__(256, 3) layer_kernel(
        const float* __restrict__ xin0, const float* __restrict__ xin1,
        float2* __restrict__ Ynext, LArg a0, LArg a1) {
    extern __shared__ unsigned char sm[];
    float4* g4   = (float4*)sm;
    float4* cwq  = (float4*)(sm + 4096);
    float2* cb2  = (float2*)(sm + 8192);
    float4* cs_a = (float4*)(sm + 8320);
    float4* cs_b = (float4*)(sm + 16768);
    float*  xrowf = (float*)(sm + 25216);    // [c][260]; aliased by orow after conv
    float2* orow  = (float2*)(sm + 25216);   // [p][258] folded

    int sub = blockIdx.x >> 11;
    int bid = blockIdx.x & 2047;
    const LArg la = sub ? a1 : a0;
    const float* xin = sub ? xin1 : xin0;

    int b = bid >> 8, h = bid & 255, tid = threadIdx.x;

    gen_cs(cs_a, cs_b, tid);
    stage_layer(g4, cwq, cb2, xrowf, xin, la.G, la.cw, la.cb, b, h, tid);
    __syncthreads();

    int u5 = tid & 31, pg = tid >> 5;
    float2 acc[16];
    compute_vals(g4, cwq, cb2, cs_a, cs_b, xrowf, u5, pg, acc);

    // gelu
#pragma unroll
    for (int k = 0; k < 16; k++) {
        acc[k].x = gelu_f(acc[k].x);
        acc[k].y = gelu_f(acc[k].y);
    }
    // skip + global stores: 4 channels x (lo,hi) float4
#pragma unroll
    for (int j = 0; j < 2; j++) {
#pragma unroll
        for (int k = 0; k < 2; k++) {
            int ch = 4*pg + 2*j + k;
            int base = ((b*NC + ch)*NH + h)*NW;
            float4 lo, hi;
            if (k == 0) {
                lo = make_float4(acc[j*8+0].x, acc[j*8+1].x, acc[j*8+2].x, acc[j*8+3].x);
                hi = make_float4(acc[j*8+4].x, acc[j*8+5].x, acc[j*8+6].x, acc[j*8+7].x);
            } else {
                lo = make_float4(acc[j*8+0].y, acc[j*8+1].y, acc[j*8+2].y, acc[j*8+3].y);
                hi = make_float4(acc[j*8+4].y, acc[j*8+5].y, acc[j*8+6].y, acc[j*8+7].y);
            }
            if (la.skip) {
                float4 slo = *(const float4*)(la.skip + base + 4*u5);
                float4 shi = *(const float4*)(la.skip + base + 128 + 4*u5);
                lo.x += slo.x; lo.y += slo.y; lo.z += slo.z; lo.w += slo.w;
                hi.x += shi.x; hi.y += shi.y; hi.z += shi.z; hi.w += shi.w;
                if (k == 0) {
                    acc[j*8+0].x = lo.x; acc[j*8+1].x = lo.y; acc[j*8+2].x = lo.z; acc[j*8+3].x = lo.w;
                    acc[j*8+4].x = hi.x; acc[j*8+5].x = hi.y; acc[j*8+6].x = hi.z; acc[j*8+7].x = hi.w;
                } else {
                    acc[j*8+0].y = lo.x; acc[j*8+1].y = lo.y; acc[j*8+2].y = lo.z; acc[j*8+3].y = lo.w;
                    acc[j*8+4].y = hi.x; acc[j*8+5].y = hi.y; acc[j*8+6].y = hi.z; acc[j*8+7].y = hi.w;
                }
            }
            *(float4*)(la.out + base + 4*u5)       = lo;
            *(float4*)(la.out + base + 128 + 4*u5) = hi;
        }
    }

    if (la.writeY) {
        __syncthreads();   // all conv reads of xrow done before orow overwrite
#pragma unroll
        for (int j = 0; j < 2; j++) {
            int p = 2*pg + j;
            float2 s0 = make_float2(acc[j*8+0].x + acc[j*8+4].x, acc[j*8+0].y + acc[j*8+4].y);
            float2 s1 = make_float2(acc[j*8+1].x + acc[j*8+5].x, acc[j*8+1].y + acc[j*8+5].y);
            float2 s2 = make_float2(acc[j*8+2].x + acc[j*8+6].x, acc[j*8+2].y + acc[j*8+6].y);
            float2 s3 = make_float2(acc[j*8+3].x + acc[j*8+7].x, acc[j*8+3].y + acc[j*8+7].y);
            float2 d0 = make_float2(acc[j*8+0].x - acc[j*8+4].x, acc[j*8+0].y - acc[j*8+4].y);
            float2 d1 = make_float2(acc[j*8+1].x - acc[j*8+5].x, acc[j*8+1].y - acc[j*8+5].y);
            float2 d2 = make_float2(acc[j*8+2].x - acc[j*8+6].x, acc[j*8+2].y - acc[j*8+6].y);
            float2 d3 = make_float2(acc[j*8+3].x - acc[j*8+7].x, acc[j*8+3].y - acc[j*8+7].y);
            *(float4*)(orow + p*258 + 4*u5)           = make_float4(s0.x, s0.y, s1.x, s1.y);
            *(float4*)(orow + p*258 + 4*u5 + 2)       = make_float4(s2.x, s2.y, s3.x, s3.y);
            *(float4*)(orow + p*258 + 128 + 4*u5)     = make_float4(d0.x, d0.y, d1.x, d1.y);
            *(float4*)(orow + p*258 + 128 + 4*u5 + 2) = make_float4(d2.x, d2.y, d3.x, d3.y);
        }
        __syncthreads();
        fwd_dft(orow, cs_a, cs_b, Ynext, b, h, tid);
    }
}

// ---------------- L5 + head fused kernel ----------------
// smem: layer regions [0,58496) | w1s[58496,74880) | w2p[74880,77952) | b1s[77952,78464) | b2s[78464,78496)
static const int HEAD5_SM = 78496;
__global__ void __launch_bounds__(256, 2) layer5_head_kernel(
        const float* __restrict__ xin, LArg a0,
        const float* __restrict__ fw1, const float* __restrict__ fb1,
        const float* __restrict__ fw2, const float* __restrict__ fb2,
        float* __restrict__ out) {
    extern __shared__ unsigned char sm[];
    float4* g4   = (float4*)sm;
    float4* cwq  = (float4*)(sm + 4096);
    float2* cb2  = (float2*)(sm + 8192);
    float4* cs_a = (float4*)(sm + 8320);
    float4* cs_b = (float4*)(sm + 16768);
    float*  xrowf = (float*)(sm + 25216);     // [c][260]; aliased by vrow
    float*  vrow  = (float*)(sm + 25216);     // [c][260]
    float*  w1s  = (float*)(sm + 58496);
    float2* w2p  = (float2*)(sm + 74880);
    float*  b1s  = (float*)(sm + 77952);
    float*  b2s  = (float*)(sm + 78464);

    int b = blockIdx.x >> 8, h = blockIdx.x & 255, tid = threadIdx.x;

    gen_cs(cs_a, cs_b, tid);
    stage_layer(g4, cwq, cb2, xrowf, xin, a0.G, a0.cw, a0.cb, b, h, tid);
    for (int k = tid; k < 4096; k += 256) w1s[k] = fw1[k];
    if (tid < 128) {
        b1s[tid] = fb1[tid];
        w2p[tid*3 + 0] = make_float2(fw2[tid*5 + 0], fw2[tid*5 + 1]);
        w2p[tid*3 + 1] = make_float2(fw2[tid*5 + 2], fw2[tid*5 + 3]);
        w2p[tid*3 + 2] = make_float2(fw2[tid*5 + 4], 0.0f);
    }
    if (tid < 5) b2s[tid] = fb2[tid];
    __syncthreads();

    int u5 = tid & 31, pg = tid >> 5;
    float2 acc[16];
    compute_vals(g4, cwq, cb2, cs_a, cs_b, xrowf, u5, pg, acc);

    // gelu + skip (always present)
#pragma unroll
    for (int k = 0; k < 16; k++) {
        acc[k].x = gelu_f(acc[k].x);
        acc[k].y = gelu_f(acc[k].y);
    }
#pragma unroll
    for (int j = 0; j < 2; j++) {
#pragma unroll
        for (int k = 0; k < 2; k++) {
            int ch = 4*pg + 2*j + k;
            int base = ((b*NC + ch)*NH + h)*NW;
            float4 slo = *(const float4*)(a0.skip + base + 4*u5);
            float4 shi = *(const float4*)(a0.skip + base + 128 + 4*u5);
            if (k == 0) {
                acc[j*8+0].x += slo.x; acc[j*8+1].x += slo.y; acc[j*8+2].x += slo.z; acc[j*8+3].x += slo.w;
                acc[j*8+4].x += shi.x; acc[j*8+5].x += shi.y; acc[j*8+6].x += shi.z; acc[j*8+7].x += shi.w;
            } else {
                acc[j*8+0].y += slo.x; acc[j*8+1].y += slo.y; acc[j*8+2].y += slo.z; acc[j*8+3].y += slo.w;
                acc[j*8+4].y += shi.x; acc[j*8+5].y += shi.y; acc[j*8+6].y += shi.z; acc[j*8+7].y += shi.w;
            }
        }
    }

    __syncthreads();   // conv reads done -> safe to overwrite xrow with vrow
#pragma unroll
    for (int j = 0; j < 2; j++) {
#pragma unroll
        for (int k = 0; k < 2; k++) {
            int ch = 4*pg + 2*j + k;
            float4 lo, hi;
            if (k == 0) {
                lo = make_float4(acc[j*8+0].x, acc[j*8+1].x, acc[j*8+2].x, acc[j*8+3].x);
                hi = make_float4(acc[j*8+4].x, acc[j*8+5].x, acc[j*8+6].x, acc[j*8+7].x);
            } else {
                lo = make_float4(acc[j*8+0].y, acc[j*8+1].y, acc[j*8+2].y, acc[j*8+3].y);
                hi = make_float4(acc[j*8+4].y, acc[j*8+5].y, acc[j*8+6].y, acc[j*8+7].y);
            }
            *(float4*)(vrow + ch*260 + 4*u5)       = lo;
            *(float4*)(vrow + ch*260 + 128 + 4*u5) = hi;
        }
    }
    __syncthreads();

    // head: fc1 + GELU + fc2 for w = tid
    int w = tid;
    float2 o01 = make_float2(b2s[0], b2s[1]);
    float2 o23 = make_float2(b2s[2], b2s[3]);
    float2 o4z = make_float2(b2s[4], 0.0f);
    const float4* w1q = (const float4*)w1s;
    const float2* b1p = (const float2*)b1s;

#pragma unroll 1
    for (int q = 0; q < 4; q++) {
        float2 hacc[16];
#pragma unroll
        for (int jj = 0; jj < 16; jj++) hacc[jj] = b1p[q*16 + jj];
#pragma unroll 4
        for (int c = 0; c < NC; c++) {
            float xv = vrow[c*260 + w];
            float2 xv2 = make_float2(xv, xv);
#pragma unroll
            for (int j8 = 0; j8 < 8; j8++) {
                float4 w4 = w1q[c*32 + q*8 + j8];
                hacc[2*j8    ] = ffma2(xv2, make_float2(w4.x, w4.y), hacc[2*j8    ]);
                hacc[2*j8 + 1] = ffma2(xv2, make_float2(w4.z, w4.w), hacc[2*j8 + 1]);
            }
        }
#pragma unroll
        for (int jj = 0; jj < 16; jj++) {
            int j = 32*q + 2*jj;
            float h0 = gelu_f(hacc[jj].x);
            float h1 = gelu_f(hacc[jj].y);
            float2 h02 = make_float2(h0, h0), h12 = make_float2(h1, h1);
            o01 = ffma2(h02, w2p[j*3 + 0], o01);
            o23 = ffma2(h02, w2p[j*3 + 1], o23);
            o4z = ffma2(h02, w2p[j*3 + 2], o4z);
            o01 = ffma2(h12, w2p[(j+1)*3 + 0], o01);
            o23 = ffma2(h12, w2p[(j+1)*3 + 1], o23);
            o4z = ffma2(h12, w2p[(j+1)*3 + 2], o4z);
        }
    }
    float* op = out + (((b*NH) + h)*NW + w) * 5;
    op[0] = o01.x; op[1] = o01.y; op[2] = o23.x; op[3] = o23.y; op[4] = o4z.x;
}

// ---------------- host launcher ----------------
extern "C" void kernel_launch(void* const* d_in, const int* in_sizes, int n_in,
                              void* d_out, int out_size) {
    const float* x     = (const float*)d_in[0];
    const float* fc0w  = (const float*)d_in[1];
    const float* fc0b  = (const float*)d_in[2];
    const float* w1    = (const float*)d_in[3];
    const float* w2    = (const float*)d_in[4];
    const float* convw = (const float*)d_in[5];
    const float* convb = (const float*)d_in[6];
    const float* fc1w  = (const float*)d_in[7];
    const float* fc1b  = (const float*)d_in[8];
    const float* fc2w  = (const float*)d_in[9];
    const float* fc2b  = (const float*)d_in[10];
    float* out = (float*)d_out;

    float  *bufA, *bufB, *bufC;
    float2 *Y, *Z, *G0, *G1;
    cudaGetSymbolAddress((void**)&bufA, g_bufA);
    cudaGetSymbolAddress((void**)&bufB, g_bufB);
    cudaGetSymbolAddress((void**)&bufC, g_bufC);
    cudaGetSymbolAddress((void**)&Y, g_Y);
    cudaGetSymbolAddress((void**)&Z, g_Zb);
    cudaGetSymbolAddress((void**)&G0, g_G);
    cudaGetSymbolAddress((void**)&G1, g_G2);

    cudaFuncSetAttribute(lift_kernel,       cudaFuncAttributeMaxDynamicSharedMemorySize, LIFT_SM);
    cudaFuncSetAttribute(k2a_kernel,        cudaFuncAttributeMaxDynamicSharedMemorySize, K2A_SM);
    cudaFuncSetAttribute(layer_kernel,      cudaFuncAttributeMaxDynamicSharedMemorySize, ROW_SM);
    cudaFuncSetAttribute(layer5_head_kernel,cudaFuncAttributeMaxDynamicSharedMemorySize, HEAD5_SM);

    const float* w1p[6]; const float* w2p_[6]; const float* cwp[6]; const float* cbp[6];
    for (int l = 0; l < 6; l++) {
        w1p[l]  = w1 + (size_t)l * WSZ;
        w2p_[l] = w2 + (size_t)l * WSZ;
        cwp[l]  = convw + l * 32 * 32;
        cbp[l]  = convb + l * 32;
    }

    // DAG:  h0 = L0(lift); t1 = L1(lift); t2 = L2(t1) + h0;
    //       h1 = L3(t2);   t4 = L4(t2);   out = head(L5(t4) + h1);
    lift_kernel<<<NB*NH, 256, LIFT_SM>>>(x, fc0w, fc0b, bufA, Y);   // A = lift, Y_lift

    // L0 + L1 (share Z of Y_lift)
    k2a_kernel<<<NB*NC, 512, K2A_SM>>>(Y, Z);
    k2bc_kernel<<<2*NB*NC, 512>>>(Z, w1p[0], w2p_[0], G0, w1p[1], w2p_[1], G1);
    {
        LArg a0 = { G0, cwp[0], cbp[0], nullptr, bufB, 0 };   // h0
        LArg a1 = { G1, cwp[1], cbp[1], nullptr, bufC, 1 };   // t1 (+Y_t1)
        layer_kernel<<<2*NB*NH, 256, ROW_SM>>>(bufA, bufA, Y, a0, a1);
    }

    // L2
    k2a_kernel<<<NB*NC, 512, K2A_SM>>>(Y, Z);
    k2bc_kernel<<<NB*NC, 512>>>(Z, w1p[2], w2p_[2], G0, w1p[2], w2p_[2], G0);
    {
        LArg a = { G0, cwp[2], cbp[2], bufB, bufA, 1 };       // t2 (+Y_t2)
        layer_kernel<<<NB*NH, 256, ROW_SM>>>(bufC, bufC, Y, a, a);
    }

    // L3 + L4 (share Z of Y_t2)
    k2a_kernel<<<NB*NC, 512, K2A_SM>>>(Y, Z);
    k2bc_kernel<<<2*NB*NC, 512>>>(Z, w1p[3], w2p_[3], G0, w1p[4], w2p_[4], G1);
    {
        LArg a0 = { G0, cwp[3], cbp[3], nullptr, bufB, 0 };   // h1
        LArg a1 = { G1, cwp[4], cbp[4], nullptr, bufC, 1 };   // t4 (+Y_t4)
        layer_kernel<<<2*NB*NH, 256, ROW_SM>>>(bufA, bufA, Y, a0, a1);
    }

    // L5 + head fused
    k2a_kernel<<<NB*NC, 512, K2A_SM>>>(Y, Z);
    k2bc_kernel<<<NB*NC, 512>>>(Z, w1p[5], w2p_[5], G0, w1p[5], w2p_[5], G0);
    {
        LArg a = { G0, cwp[5], cbp[5], bufB, nullptr, 0 };    // final (consumed in-kernel)
        layer5_head_kernel<<<NB*NH, 256, HEAD5_SM>>>(bufC, a, fc1w, fc1b, fc2w, fc2b, out);
    }
}